// round 9
// baseline (speedup 1.0000x reference)
#include <cuda_runtime.h>

#define BB 4
#define CC 256
#define HH 56
#define NN 3136
#define NHD 8
#define HD 32
#define NK 784
#define PEW 111

__device__ __forceinline__ unsigned tf32c(float f) {
    unsigned u; asm("cvt.rna.tf32.f32 %0, %1;" : "=r"(u) : "f"(f)); return u;
}
__device__ __forceinline__ void mma8(float c[4], const unsigned a[4], unsigned b0, unsigned b1) {
    asm("mma.sync.aligned.m16n8k8.row.col.f32.tf32.tf32.f32 "
        "{%0,%1,%2,%3},{%4,%5,%6,%7},{%8,%9},{%0,%1,%2,%3};"
        : "+f"(c[0]), "+f"(c[1]), "+f"(c[2]), "+f"(c[3])
        : "r"(a[0]), "r"(a[1]), "r"(a[2]), "r"(a[3]), "r"(b0), "r"(b1));
}

// ---------------- scratch ----------------
__device__ float    g_q   [BB*NHD*NN*HD];   // (b, head, n, d)
__device__ float    g_k   [BB*NHD*NK*HD];   // (b, head, m, d)
__device__ float    g_v   [BB*NHD*NK*HD];
__device__ float    g_xkvp[4*BB*NK*CC];     // conv partial sums (K-split)
__device__ float    g_xkv [BB*NK*CC];       // LN output
__device__ float    g_ao  [BB*NN*CC];       // (b, n, head*32+d)
__device__ unsigned g_wt  [1024*CC];        // conv weight transposed tf32

// ---------------- prep ----------------
__global__ void wt_kernel(const float* __restrict__ sr_w) {
    g_wt[blockIdx.x*CC + threadIdx.x] = tf32c(sr_w[threadIdx.x*1024 + blockIdx.x]);
}

// ---- shared mma core: block 128(M)x64(N), ktile 16; As[16][132], Bs[16][68] ----
__device__ __forceinline__ void mma_ktile(const unsigned* As, const unsigned* Bs,
                                          int wm, int wn, int lane, float acc[2][4][4]) {
    int gr = lane >> 2, gc = lane & 3;
#pragma unroll
    for (int ks = 0; ks < 2; ks++) {
        unsigned a[2][4];
        const unsigned* ak0 = As + (ks*8 + gc)*132 + wm*32;
        const unsigned* ak4 = ak0 + 4*132;
#pragma unroll
        for (int mi = 0; mi < 2; mi++) {
            int r = mi*16 + gr;
            a[mi][0] = ak0[r]; a[mi][1] = ak0[r+8];
            a[mi][2] = ak4[r]; a[mi][3] = ak4[r+8];
        }
        const unsigned* bk0 = Bs + (ks*8 + gc)*68 + wn*32 + gr;
        const unsigned* bk4 = bk0 + 4*68;
#pragma unroll
        for (int nj = 0; nj < 4; nj++) {
            unsigned b0 = bk0[nj*8], b1 = bk4[nj*8];
            mma8(acc[0][nj], a[0], b0, b1);
            mma8(acc[1][nj], a[1], b0, b1);
        }
    }
}

#define GEMM_PRE                                                         \
    __shared__ unsigned As[16*132];                                      \
    __shared__ unsigned Bs[16*68];                                       \
    int tid = threadIdx.x, lane = tid & 31, w = tid >> 5;                \
    int wm = w >> 1, wn = w & 1;                                         \
    int gr = lane >> 2, tg = lane & 3;                                   \
    float acc[2][4][4];                                                  \
    _Pragma("unroll") for (int zi = 0; zi < 2; zi++)                     \
    _Pragma("unroll") for (int zj = 0; zj < 4; zj++)                     \
    _Pragma("unroll") for (int zk = 0; zk < 4; zk++) acc[zi][zj][zk] = 0.f;

// ---------------- 1: Q projection (prefetch double-buffered) ----------------
__global__ __launch_bounds__(256) void gemm_q_kernel(const float* __restrict__ x,
                                                     const float* __restrict__ Wq) {
    GEMM_PRE
    int b = blockIdx.z, n0 = blockIdx.x*128, c0 = blockIdx.y*64;
    int kk = tid >> 4, m8 = (tid & 15)*8, c4 = (tid & 15)*4;
    bool fok = (n0 + m8) < NN;
    const float* xb = x + b*CC*NN;

    float4 v0 = make_float4(0,0,0,0), v1 = v0, wv;
    {   // prefetch tile 0
        if (fok) { const float* s = xb + kk*NN + n0 + m8;
                   v0 = *(const float4*)s; v1 = *(const float4*)(s+4); }
        wv = *(const float4*)(Wq + kk*CC + c0 + c4);
    }
    for (int kt = 0; kt < 16; kt++) {
        {
            unsigned* d = As + kk*132 + m8;
            d[0]=tf32c(v0.x); d[1]=tf32c(v0.y); d[2]=tf32c(v0.z); d[3]=tf32c(v0.w);
            d[4]=tf32c(v1.x); d[5]=tf32c(v1.y); d[6]=tf32c(v1.z); d[7]=tf32c(v1.w);
            unsigned* e = Bs + kk*68 + c4;
            e[0]=tf32c(wv.x); e[1]=tf32c(wv.y); e[2]=tf32c(wv.z); e[3]=tf32c(wv.w);
        }
        __syncthreads();
        if (kt < 15) {
            int kg = (kt+1)*16 + kk;
            if (fok) { const float* s = xb + kg*NN + n0 + m8;
                       v0 = *(const float4*)s; v1 = *(const float4*)(s+4); }
            wv = *(const float4*)(Wq + kg*CC + c0 + c4);
        }
        mma_ktile(As, Bs, wm, wn, lane, acc);
        __syncthreads();
    }
#pragma unroll
    for (int nj = 0; nj < 4; nj++) {
        int c = c0 + wn*32 + nj*8 + 2*tg;
        int head = c >> 5, d = c & 31;
        float* qb = g_q + (b*NHD + head)*NN*HD + d;
#pragma unroll
        for (int mi = 0; mi < 2; mi++) {
            int n1 = n0 + wm*32 + mi*16 + gr;
            if (n1 < NN)   *(float2*)(qb + n1*HD)     = make_float2(acc[mi][nj][0], acc[mi][nj][1]);
            if (n1+8 < NN) *(float2*)(qb + (n1+8)*HD) = make_float2(acc[mi][nj][2], acc[mi][nj][3]);
        }
    }
}

// ---------------- 2: SR conv as GEMM, K-split x4 (K=256 each) ----------------
__global__ __launch_bounds__(256) void gemm_conv_kernel(const float* __restrict__ x) {
    GEMM_PRE
    int b = blockIdx.z;
    int part = blockIdx.y >> 2;
    int o0 = (blockIdx.y & 3) * 64;
    int m0 = blockIdx.x * 128;
    int kk = tid >> 4, m8 = (tid & 15)*8, c4 = (tid & 15)*4;
    bool fok = (m0 + m8) < NK;
    const float* xb = x + b*CC*NN;
    int sb[8];
#pragma unroll
    for (int c = 0; c < 8; c++) {
        int m = fok ? (m0 + m8 + c) : 0;
        int r = m / 28;
        sb[c] = (2*r)*HH + 2*(m - r*28);
    }
    int kbase = part*256;

    float va[8]; uint4 vb4;
    {
        int kg = kbase + kk;
        int ic = kg >> 2, kh = (kg >> 1) & 1, kw = kg & 1;
        const float* s = xb + ic*NN + kh*HH + kw;
#pragma unroll
        for (int c = 0; c < 8; c++) va[c] = fok ? s[sb[c]] : 0.f;
        vb4 = *(const uint4*)(g_wt + kg*CC + o0 + c4);
    }
    for (int kt = 0; kt < 16; kt++) {
        unsigned* d = As + kk*132 + m8;
#pragma unroll
        for (int c = 0; c < 8; c++) d[c] = tf32c(va[c]);
        *(uint4*)(Bs + kk*68 + c4) = vb4;
        __syncthreads();
        if (kt < 15) {
            int kg = kbase + (kt+1)*16 + kk;
            int ic = kg >> 2, kh = (kg >> 1) & 1, kw = kg & 1;
            const float* s = xb + ic*NN + kh*HH + kw;
#pragma unroll
            for (int c = 0; c < 8; c++) va[c] = fok ? s[sb[c]] : 0.f;
            vb4 = *(const uint4*)(g_wt + kg*CC + o0 + c4);
        }
        mma_ktile(As, Bs, wm, wn, lane, acc);
        __syncthreads();
    }
    float* dstp = g_xkvp + part*(BB*NK*CC) + (b*NK)*CC;
#pragma unroll
    for (int nj = 0; nj < 4; nj++) {
        int c = o0 + wn*32 + nj*8 + 2*tg;
#pragma unroll
        for (int mi = 0; mi < 2; mi++) {
            int m1 = m0 + wm*32 + mi*16 + gr;
            if (m1 < NK)   *(float2*)(&dstp[m1*CC + c]) =
                make_float2(acc[mi][nj][0], acc[mi][nj][1]);
            if (m1+8 < NK) *(float2*)(&dstp[(m1+8)*CC + c]) =
                make_float2(acc[mi][nj][2], acc[mi][nj][3]);
        }
    }
}

// ---------------- 3: LayerNorm (sums 4 conv partials + bias) ----------------
__global__ void ln_kernel(const float* __restrict__ gamma, const float* __restrict__ beta,
                          const float* __restrict__ sr_b) {
    int row = blockIdx.x, t = threadIdx.x;
    int idx = row*CC + t;
    const int stride = BB*NK*CC;
    float v = ((g_xkvp[idx] + g_xkvp[idx + stride]) +
               (g_xkvp[idx + 2*stride] + g_xkvp[idx + 3*stride])) + sr_b[t];
    float s = v, q = v*v;
#pragma unroll
    for (int m = 16; m >= 1; m >>= 1) {
        s += __shfl_xor_sync(0xffffffffu, s, m);
        q += __shfl_xor_sync(0xffffffffu, q, m);
    }
    __shared__ float r1[8], r2[8];
    if ((t & 31) == 0) { r1[t>>5] = s; r2[t>>5] = q; }
    __syncthreads();
    float tot = 0.f, tq = 0.f;
#pragma unroll
    for (int wv = 0; wv < 8; wv++) { tot += r1[wv]; tq += r2[wv]; }
    float mean = tot * (1.f/256.f);
    float var  = tq * (1.f/256.f) - mean*mean;
    float inv  = rsqrtf(var + 1e-5f);
    g_xkv[row*CC + t] = (v - mean)*inv*gamma[t] + beta[t];
}

// ---------------- 4: KV projection (prefetch double-buffered) ----------------
__global__ __launch_bounds__(256) void gemm_kv_kernel(const float* __restrict__ Wkv) {
    GEMM_PRE
    int b = blockIdx.z, m0 = blockIdx.x*128, c0 = blockIdx.y*64;
    int kk = tid >> 4, c4 = (tid & 15)*4;
    int am = tid >> 1, akc = (tid & 1)*8;
    int arow = m0 + am; if (arow > NK-1) arow = NK-1;
    const float* ap = g_xkv + (b*NK + arow)*CC;

    float4 v0, v1, wv;
    {
        v0 = *(const float4*)(ap + akc);
        v1 = *(const float4*)(ap + akc + 4);
        wv = *(const float4*)(Wkv + kk*512 + c0 + c4);
    }
    for (int kt = 0; kt < 16; kt++) {
        {
            As[(akc+0)*132+am]=tf32c(v0.x); As[(akc+1)*132+am]=tf32c(v0.y);
            As[(akc+2)*132+am]=tf32c(v0.z); As[(akc+3)*132+am]=tf32c(v0.w);
            As[(akc+4)*132+am]=tf32c(v1.x); As[(akc+5)*132+am]=tf32c(v1.y);
            As[(akc+6)*132+am]=tf32c(v1.z); As[(akc+7)*132+am]=tf32c(v1.w);
            unsigned* e = Bs + kk*68 + c4;
            e[0]=tf32c(wv.x); e[1]=tf32c(wv.y); e[2]=tf32c(wv.z); e[3]=tf32c(wv.w);
        }
        __syncthreads();
        if (kt < 15) {
            int k0 = (kt+1)*16;
            v0 = *(const float4*)(ap + k0 + akc);
            v1 = *(const float4*)(ap + k0 + akc + 4);
            wv = *(const float4*)(Wkv + (k0+kk)*512 + c0 + c4);
        }
        mma_ktile(As, Bs, wm, wn, lane, acc);
        __syncthreads();
    }
#pragma unroll
    for (int nj = 0; nj < 4; nj++) {
        int c = c0 + wn*32 + nj*8 + 2*tg;
        int d = c >> 4, head = (c >> 1) & 7;
        float* kb = g_k + (b*NHD + head)*NK*HD + d;
        float* vb = g_v + (b*NHD + head)*NK*HD + d;
#pragma unroll
        for (int mi = 0; mi < 2; mi++) {
            int m1 = m0 + wm*32 + mi*16 + gr;
            if (m1 < NK)   { kb[m1*HD]     = acc[mi][nj][0]; vb[m1*HD]     = acc[mi][nj][1]; }
            if (m1+8 < NK) { kb[(m1+8)*HD] = acc[mi][nj][2]; vb[(m1+8)*HD] = acc[mi][nj][3]; }
        }
    }
}

// ---------------- 5: fused flash attention (prefetch K/V tiles) ------
__global__ __launch_bounds__(256, 2) void attn_kernel(const float* __restrict__ pos_emb) {
    extern __shared__ unsigned smu[];
    unsigned* qs = smu;          // [32][132]
    unsigned* ks = smu + 4224;   // [32][68]
    unsigned* vs = smu + 6400;   // [64][36]
    unsigned* ps = smu + 8704;   // 8 warps x [16][68]
    int b = blockIdx.z, head = blockIdx.y, n0 = blockIdx.x*128;
    int tid = threadIdx.x, lane = tid & 31, w = tid >> 5;
    int gr = lane >> 2, tg = lane & 3;
    const float scale = 0.17677669529663687f;
    int bh = b*NHD + head;
    const float* qg = g_q + bh*NN*HD;
    const float* kg = g_k + bh*NK*HD;
    const float* vg = g_v + bh*NK*HD;

    {   // qs fill: [d][row], scaled + tf32
        int r = tid >> 1, dc = (tid & 1)*16;
        int n = n0 + r; if (n > NN-1) n = NN-1;
        const float* p = qg + n*HD + dc;
#pragma unroll
        for (int c4 = 0; c4 < 4; c4++) {
            float4 v = *(const float4*)(p + c4*4);
            qs[(dc+c4*4+0)*132 + r] = tf32c(v.x*scale);
            qs[(dc+c4*4+1)*132 + r] = tf32c(v.y*scale);
            qs[(dc+c4*4+2)*132 + r] = tf32c(v.z*scale);
            qs[(dc+c4*4+3)*132 + r] = tf32c(v.w*scale);
        }
    }

    int rown0 = n0 + w*16 + gr, rown1 = rown0 + 8;
    int nq0 = rown0 > NN-1 ? NN-1 : rown0;
    int nq1 = rown1 > NN-1 ? NN-1 : rown1;
    int qi0 = nq0/HH, qj0 = nq0 - qi0*HH;
    int qi1 = nq1/HH, qj1 = nq1 - qi1*HH;

    float m_i[2] = {-1e30f, -1e30f}, l_i[2] = {0.f, 0.f};
    float co[4][4];
#pragma unroll
    for (int i = 0; i < 4; i++) { co[i][0]=0.f; co[i][1]=0.f; co[i][2]=0.f; co[i][3]=0.f; }
    unsigned* psw = ps + w*16*68;

    int kr = tid >> 2, dc = (tid & 3)*8;
    float4 ka0, ka1, vw0, vw1;
    {   // prefetch K/V tile 0
        bool ok = kr < NK;
        int mr = ok ? kr : 0;
        const float* kp = kg + mr*HD + dc;
        ka0 = *(const float4*)kp; ka1 = *(const float4*)(kp+4);
        const float* vp = vg + mr*HD + dc;
        vw0 = *(const float4*)vp; vw1 = *(const float4*)(vp+4);
        if (!ok) { ka0 = make_float4(0,0,0,0); ka1 = ka0; vw0 = ka0; vw1 = ka0; }
    }

    for (int t = 0; t < 13; t++) {
        int mb = t*64;
        __syncthreads();
        {   // store prefetched K/V tile to smem
            ks[(dc+0)*68+kr]=tf32c(ka0.x); ks[(dc+1)*68+kr]=tf32c(ka0.y);
            ks[(dc+2)*68+kr]=tf32c(ka0.z); ks[(dc+3)*68+kr]=tf32c(ka0.w);
            ks[(dc+4)*68+kr]=tf32c(ka1.x); ks[(dc+5)*68+kr]=tf32c(ka1.y);
            ks[(dc+6)*68+kr]=tf32c(ka1.z); ks[(dc+7)*68+kr]=tf32c(ka1.w);
            uint4 u0 = make_uint4(tf32c(vw0.x), tf32c(vw0.y), tf32c(vw0.z), tf32c(vw0.w));
            uint4 u1 = make_uint4(tf32c(vw1.x), tf32c(vw1.y), tf32c(vw1.z), tf32c(vw1.w));
            *(uint4*)(vs + kr*36 + dc)     = u0;
            *(uint4*)(vs + kr*36 + dc + 4) = u1;
        }
        __syncthreads();
        if (t < 12) {   // prefetch next tile (overlaps entire compute phase)
            int mk = mb + 64 + kr;
            bool ok = mk < NK;
            int mr = ok ? mk : 0;
            const float* kp = kg + mr*HD + dc;
            ka0 = *(const float4*)kp; ka1 = *(const float4*)(kp+4);
            const float* vp = vg + mr*HD + dc;
            vw0 = *(const float4*)vp; vw1 = *(const float4*)(vp+4);
            if (!ok) { ka0 = make_float4(0,0,0,0); ka1 = ka0; vw0 = ka0; vw1 = ka0; }
        }

        // ---- QK^T: S = 16x64 per warp ----
        float cs[8][4];
#pragma unroll
        for (int i = 0; i < 8; i++) { cs[i][0]=0.f; cs[i][1]=0.f; cs[i][2]=0.f; cs[i][3]=0.f; }
#pragma unroll
        for (int ks8 = 0; ks8 < 4; ks8++) {
            unsigned a[4];
            const unsigned* ak0 = qs + (ks8*8 + tg)*132 + w*16;
            const unsigned* ak4 = ak0 + 4*132;
            a[0] = ak0[gr]; a[1] = ak0[gr+8]; a[2] = ak4[gr]; a[3] = ak4[gr+8];
            const unsigned* bk0 = ks + (ks8*8 + tg)*68 + gr;
            const unsigned* bk4 = bk0 + 4*68;
#pragma unroll
            for (int nj = 0; nj < 8; nj++)
                mma8(cs[nj], a, bk0[nj*8], bk4[nj*8]);
        }

        // ---- bias + mask (inline from L2-resident pos_emb) ----
#pragma unroll
        for (int nj = 0; nj < 8; nj++) {
            int mk = mb + nj*8 + 2*tg;
            if (mk < NK) {
                int ki = mk/HH, kj = mk - (mk/HH)*HH;
                int ki2 = (kj == HH-1) ? ki+1 : ki;
                int kj2 = (kj == HH-1) ? 0 : kj+1;
                cs[nj][0] += __ldg(&pos_emb[(ki -qi0+55)*PEW + (kj -qj0+55)]);
                cs[nj][1] += __ldg(&pos_emb[(ki2-qi0+55)*PEW + (kj2-qj0+55)]);
                cs[nj][2] += __ldg(&pos_emb[(ki -qi1+55)*PEW + (kj -qj1+55)]);
                cs[nj][3] += __ldg(&pos_emb[(ki2-qi1+55)*PEW + (kj2-qj1+55)]);
            } else {
                cs[nj][0] = -1e30f; cs[nj][1] = -1e30f;
                cs[nj][2] = -1e30f; cs[nj][3] = -1e30f;
            }
        }

        // ---- online softmax (rows gr, gr+8; quad reduction) ----
#pragma unroll
        for (int h = 0; h < 2; h++) {
            float tm = -1e30f;
#pragma unroll
            for (int nj = 0; nj < 8; nj++) tm = fmaxf(tm, fmaxf(cs[nj][2*h], cs[nj][2*h+1]));
            tm = fmaxf(tm, __shfl_xor_sync(0xffffffffu, tm, 1));
            tm = fmaxf(tm, __shfl_xor_sync(0xffffffffu, tm, 2));
            float mnew = fmaxf(m_i[h], tm);
            float f = __expf(m_i[h] - mnew);
            m_i[h] = mnew;
            float sum = 0.f;
            unsigned* prow = psw + (gr + 8*h)*68 + 2*tg;
#pragma unroll
            for (int nj = 0; nj < 8; nj++) {
                float p0 = __expf(cs[nj][2*h]   - mnew);
                float p1 = __expf(cs[nj][2*h+1] - mnew);
                sum += p0 + p1;
                *(uint2*)(prow + nj*8) = make_uint2(tf32c(p0), tf32c(p1));
            }
            sum += __shfl_xor_sync(0xffffffffu, sum, 1);
            sum += __shfl_xor_sync(0xffffffffu, sum, 2);
            l_i[h] = l_i[h]*f + sum;
#pragma unroll
            for (int nj = 0; nj < 4; nj++) { co[nj][2*h] *= f; co[nj][2*h+1] *= f; }
        }
        __syncwarp();

        // ---- O += P @ V ----
#pragma unroll
        for (int kk8 = 0; kk8 < 8; kk8++) {
            unsigned a[4];
            const unsigned* p0 = psw + gr*68 + kk8*8 + tg;
            const unsigned* p1 = psw + (gr+8)*68 + kk8*8 + tg;
            a[0] = p0[0]; a[1] = p1[0]; a[2] = p0[4]; a[3] = p1[4];
            const unsigned* b0p = vs + (kk8*8 + tg)*36 + gr;
            const unsigned* b1p = b0p + 4*36;
#pragma unroll
            for (int nj = 0; nj < 4; nj++)
                mma8(co[nj], a, b0p[nj*8], b1p[nj*8]);
        }
        __syncwarp();
    }

    float inv0 = 1.f/l_i[0], inv1 = 1.f/l_i[1];
#pragma unroll
    for (int nj = 0; nj < 4; nj++) {
        int d = nj*8 + 2*tg;
        if (rown0 < NN)
            *(float2*)&g_ao[(b*NN + rown0)*CC + head*HD + d] =
                make_float2(co[nj][0]*inv0, co[nj][1]*inv0);
        if (rown1 < NN)
            *(float2*)&g_ao[(b*NN + rown1)*CC + head*HD + d] =
                make_float2(co[nj][2]*inv1, co[nj][3]*inv1);
    }
}

// ---------------- 6: output projection + NCHW transpose (prefetch) ---------
__global__ __launch_bounds__(256) void gemm_proj_kernel(const float* __restrict__ pw,
                                                        const float* __restrict__ pb,
                                                        float* __restrict__ out) {
    GEMM_PRE
    int b = blockIdx.z, n0 = blockIdx.x*128, c0 = blockIdx.y*64;
    int kk = tid >> 4, c4 = (tid & 15)*4;
    int am = tid >> 1, akc = (tid & 1)*8;
    int arow = n0 + am; if (arow > NN-1) arow = NN-1;
    const float* ap = g_ao + (b*NN + arow)*CC;

    float4 v0, v1, wv;
    {
        v0 = *(const float4*)(ap + akc);
        v1 = *(const float4*)(ap + akc + 4);
        wv = *(const float4*)(pw + kk*CC + c0 + c4);
    }
    for (int kt = 0; kt < 16; kt++) {
        {
            As[(akc+0)*132+am]=tf32c(v0.x); As[(akc+1)*132+am]=tf32c(v0.y);
            As[(akc+2)*132+am]=tf32c(v0.z); As[(akc+3)*132+am]=tf32c(v0.w);
            As[(akc+4)*132+am]=tf32c(v1.x); As[(akc+5)*132+am]=tf32c(v1.y);
            As[(akc+6)*132+am]=tf32c(v1.z); As[(akc+7)*132+am]=tf32c(v1.w);
            unsigned* e = Bs + kk*68 + c4;
            e[0]=tf32c(wv.x); e[1]=tf32c(wv.y); e[2]=tf32c(wv.z); e[3]=tf32c(wv.w);
        }
        __syncthreads();
        if (kt < 15) {
            int k0 = (kt+1)*16;
            v0 = *(const float4*)(ap + k0 + akc);
            v1 = *(const float4*)(ap + k0 + akc + 4);
            wv = *(const float4*)(pw + (k0+kk)*CC + c0 + c4);
        }
        mma_ktile(As, Bs, wm, wn, lane, acc);
        __syncthreads();
    }
#pragma unroll
    for (int nj = 0; nj < 4; nj++) {
        int c = c0 + wn*32 + nj*8 + 2*tg;
        float2 pbv = *(const float2*)(pb + c);
        float* o0 = out + (b*CC + c)*NN;
        float* o1 = o0 + NN;
#pragma unroll
        for (int mi = 0; mi < 2; mi++) {
            int n1 = n0 + wm*32 + mi*16 + gr;
            if (n1 < NN)   { o0[n1]   = acc[mi][nj][0] + pbv.x; o1[n1]   = acc[mi][nj][1] + pbv.y; }
            if (n1+8 < NN) { o0[n1+8] = acc[mi][nj][2] + pbv.x; o1[n1+8] = acc[mi][nj][3] + pbv.y; }
        }
    }
}

// ---------------- launch ----------------
extern "C" void kernel_launch(void* const* d_in, const int* in_sizes, int n_in,
                              void* d_out, int out_size) {
    const float* x    = (const float*)d_in[0];
    const float* Wq   = (const float*)d_in[1];
    const float* Wkv  = (const float*)d_in[2];
    const float* sr_w = (const float*)d_in[3];
    const float* sr_b = (const float*)d_in[4];
    const float* ln_g = (const float*)d_in[5];
    const float* ln_b = (const float*)d_in[6];
    const float* pos  = (const float*)d_in[7];
    const float* pw   = (const float*)d_in[8];
    const float* pb   = (const float*)d_in[9];
    float* out = (float*)d_out;

    static int smem_set = 0;
    if (!smem_set) {
        cudaFuncSetAttribute(attn_kernel, cudaFuncAttributeMaxDynamicSharedMemorySize, 69632);
        smem_set = 1;
    }

    wt_kernel       <<<1024, 256>>>(sr_w);
    gemm_q_kernel   <<<dim3(25, 4, BB), 256>>>(x, Wq);
    gemm_conv_kernel<<<dim3(7, 16, BB), 256>>>(x);
    ln_kernel       <<<BB*NK, 256>>>(ln_g, ln_b, sr_b);
    gemm_kv_kernel  <<<dim3(7, 8, BB), 256>>>(Wkv);
    attn_kernel     <<<dim3(25, 8, BB), 256, 69632>>>(pos);
    gemm_proj_kernel<<<dim3(25, 4, BB), 256>>>(pw, pb, out);
}

// round 10
// speedup vs baseline: 1.5111x; 1.5111x over previous
#include <cuda_runtime.h>

#define BB 4
#define CC 256
#define HH 56
#define NN 3136
#define NHD 8
#define HD 32
#define NK 784
#define PEW 111

__device__ __forceinline__ unsigned tf32c(float f) {
    unsigned u; asm("cvt.rna.tf32.f32 %0, %1;" : "=r"(u) : "f"(f)); return u;
}
__device__ __forceinline__ void mma8(float c[4], const unsigned a[4], unsigned b0, unsigned b1) {
    asm("mma.sync.aligned.m16n8k8.row.col.f32.tf32.tf32.f32 "
        "{%0,%1,%2,%3},{%4,%5,%6,%7},{%8,%9},{%0,%1,%2,%3};"
        : "+f"(c[0]), "+f"(c[1]), "+f"(c[2]), "+f"(c[3])
        : "r"(a[0]), "r"(a[1]), "r"(a[2]), "r"(a[3]), "r"(b0), "r"(b1));
}

// ---------------- scratch ----------------
__device__ float    g_q   [BB*NHD*NN*HD];   // (b, head, n, d)
__device__ float    g_k   [BB*NHD*NK*HD];   // (b, head, m, d)
__device__ float    g_v   [BB*NHD*NK*HD];
__device__ float    g_xkvp[4*BB*NK*CC];     // conv partial sums (K-split)
__device__ float    g_xkv [BB*NK*CC];       // LN output
__device__ float    g_ao  [BB*NN*CC];       // (b, n, head*32+d)
__device__ unsigned g_wt  [1024*CC];        // conv weight transposed tf32

// ---------------- prep ----------------
__global__ void wt_kernel(const float* __restrict__ sr_w) {
    g_wt[blockIdx.x*CC + threadIdx.x] = tf32c(sr_w[threadIdx.x*1024 + blockIdx.x]);
}

// ---- shared mma core: block 128(M)x64(N), ktile 16; As[16][132], Bs[16][68] ----
__device__ __forceinline__ void mma_ktile(const unsigned* As, const unsigned* Bs,
                                          int wm, int wn, int lane, float acc[2][4][4]) {
    int gr = lane >> 2, gc = lane & 3;
#pragma unroll
    for (int ks = 0; ks < 2; ks++) {
        unsigned a[2][4];
        const unsigned* ak0 = As + (ks*8 + gc)*132 + wm*32;
        const unsigned* ak4 = ak0 + 4*132;
#pragma unroll
        for (int mi = 0; mi < 2; mi++) {
            int r = mi*16 + gr;
            a[mi][0] = ak0[r]; a[mi][1] = ak0[r+8];
            a[mi][2] = ak4[r]; a[mi][3] = ak4[r+8];
        }
        const unsigned* bk0 = Bs + (ks*8 + gc)*68 + wn*32 + gr;
        const unsigned* bk4 = bk0 + 4*68;
#pragma unroll
        for (int nj = 0; nj < 4; nj++) {
            unsigned b0 = bk0[nj*8], b1 = bk4[nj*8];
            mma8(acc[0][nj], a[0], b0, b1);
            mma8(acc[1][nj], a[1], b0, b1);
        }
    }
}

#define ACC_INIT                                                         \
    float acc[2][4][4];                                                  \
    _Pragma("unroll") for (int zi = 0; zi < 2; zi++)                     \
    _Pragma("unroll") for (int zj = 0; zj < 4; zj++)                     \
    _Pragma("unroll") for (int zk = 0; zk < 4; zk++) acc[zi][zj][zk] = 0.f;

// ---------------- 1+2 fused: Q projection || SR conv (K-split x4) ----------
// blockIdx.y < 4  -> Q projection block (x in [0,25))
// blockIdx.y >= 4 -> conv block (x in [0,7); others exit)
__global__ __launch_bounds__(256) void gemm_qconv_kernel(const float* __restrict__ x,
                                                         const float* __restrict__ Wq) {
    __shared__ unsigned As[16*132];
    __shared__ unsigned Bs[16*68];
    int tid = threadIdx.x, lane = tid & 31, w = tid >> 5;
    int wm = w >> 1, wn = w & 1;
    int gr = lane >> 2, tg = lane & 3;
    int b = blockIdx.z;

    if (blockIdx.y < 4) {
        // ---------- Q projection (R8 body, verbatim) ----------
        ACC_INIT
        int n0 = blockIdx.x*128, c0 = blockIdx.y*64;
        int kk = tid >> 4, m8 = (tid & 15)*8, c4 = (tid & 15)*4;
        bool fok = (n0 + m8) < NN;
        const float* xb = x + b*CC*NN;
        for (int kt = 0; kt < 16; kt++) {
            int k0 = kt*16;
            __syncthreads();
            {
                float4 v0 = make_float4(0,0,0,0), v1 = v0;
                if (fok) { const float* s = xb + (k0+kk)*NN + n0 + m8;
                           v0 = *(const float4*)s; v1 = *(const float4*)(s+4); }
                unsigned* d = As + kk*132 + m8;
                d[0]=tf32c(v0.x); d[1]=tf32c(v0.y); d[2]=tf32c(v0.z); d[3]=tf32c(v0.w);
                d[4]=tf32c(v1.x); d[5]=tf32c(v1.y); d[6]=tf32c(v1.z); d[7]=tf32c(v1.w);
                float4 wv = *(const float4*)(Wq + (k0+kk)*CC + c0 + c4);
                unsigned* e = Bs + kk*68 + c4;
                e[0]=tf32c(wv.x); e[1]=tf32c(wv.y); e[2]=tf32c(wv.z); e[3]=tf32c(wv.w);
            }
            __syncthreads();
            mma_ktile(As, Bs, wm, wn, lane, acc);
        }
#pragma unroll
        for (int nj = 0; nj < 4; nj++) {
            int c = c0 + wn*32 + nj*8 + 2*tg;
            int head = c >> 5, d = c & 31;
            float* qb = g_q + (b*NHD + head)*NN*HD + d;
#pragma unroll
            for (int mi = 0; mi < 2; mi++) {
                int n1 = n0 + wm*32 + mi*16 + gr;
                if (n1 < NN)   *(float2*)(qb + n1*HD)     = make_float2(acc[mi][nj][0], acc[mi][nj][1]);
                if (n1+8 < NN) *(float2*)(qb + (n1+8)*HD) = make_float2(acc[mi][nj][2], acc[mi][nj][3]);
            }
        }
    } else {
        // ---------- SR conv, K-split (R8 body, verbatim) ----------
        if (blockIdx.x >= 7) return;
        ACC_INIT
        int yy = blockIdx.y - 4;
        int part = yy >> 2;
        int o0 = (yy & 3) * 64;
        int m0 = blockIdx.x * 128;
        int kk = tid >> 4, m8 = (tid & 15)*8, c4 = (tid & 15)*4;
        bool fok = (m0 + m8) < NK;
        const float* xb = x + b*CC*NN;
        int sb[8];
#pragma unroll
        for (int c = 0; c < 8; c++) {
            int m = fok ? (m0 + m8 + c) : 0;
            int r = m / 28;
            sb[c] = (2*r)*HH + 2*(m - r*28);
        }
        int kbase = part*256;

        float va[8]; uint4 vb4;
        {
            int kg = kbase + kk;
            int ic = kg >> 2, kh = (kg >> 1) & 1, kw = kg & 1;
            const float* s = xb + ic*NN + kh*HH + kw;
#pragma unroll
            for (int c = 0; c < 8; c++) va[c] = fok ? s[sb[c]] : 0.f;
            vb4 = *(const uint4*)(g_wt + kg*CC + o0 + c4);
        }
        for (int kt = 0; kt < 16; kt++) {
            unsigned* d = As + kk*132 + m8;
#pragma unroll
            for (int c = 0; c < 8; c++) d[c] = tf32c(va[c]);
            *(uint4*)(Bs + kk*68 + c4) = vb4;
            __syncthreads();
            if (kt < 15) {
                int kg = kbase + (kt+1)*16 + kk;
                int ic = kg >> 2, kh = (kg >> 1) & 1, kw = kg & 1;
                const float* s = xb + ic*NN + kh*HH + kw;
#pragma unroll
                for (int c = 0; c < 8; c++) va[c] = fok ? s[sb[c]] : 0.f;
                vb4 = *(const uint4*)(g_wt + kg*CC + o0 + c4);
            }
            mma_ktile(As, Bs, wm, wn, lane, acc);
            __syncthreads();
        }
        float* dstp = g_xkvp + part*(BB*NK*CC) + (b*NK)*CC;
#pragma unroll
        for (int nj = 0; nj < 4; nj++) {
            int c = o0 + wn*32 + nj*8 + 2*tg;
#pragma unroll
            for (int mi = 0; mi < 2; mi++) {
                int m1 = m0 + wm*32 + mi*16 + gr;
                if (m1 < NK)   *(float2*)(&dstp[m1*CC + c]) =
                    make_float2(acc[mi][nj][0], acc[mi][nj][1]);
                if (m1+8 < NK) *(float2*)(&dstp[(m1+8)*CC + c]) =
                    make_float2(acc[mi][nj][2], acc[mi][nj][3]);
            }
        }
    }
}

// ---------------- 3: LayerNorm (sums 4 conv partials + bias) ----------------
__global__ void ln_kernel(const float* __restrict__ gamma, const float* __restrict__ beta,
                          const float* __restrict__ sr_b) {
    int row = blockIdx.x, t = threadIdx.x;
    int idx = row*CC + t;
    const int stride = BB*NK*CC;
    float v = ((g_xkvp[idx] + g_xkvp[idx + stride]) +
               (g_xkvp[idx + 2*stride] + g_xkvp[idx + 3*stride])) + sr_b[t];
    float s = v, q = v*v;
#pragma unroll
    for (int m = 16; m >= 1; m >>= 1) {
        s += __shfl_xor_sync(0xffffffffu, s, m);
        q += __shfl_xor_sync(0xffffffffu, q, m);
    }
    __shared__ float r1[8], r2[8];
    if ((t & 31) == 0) { r1[t>>5] = s; r2[t>>5] = q; }
    __syncthreads();
    float tot = 0.f, tq = 0.f;
#pragma unroll
    for (int wv = 0; wv < 8; wv++) { tot += r1[wv]; tq += r2[wv]; }
    float mean = tot * (1.f/256.f);
    float var  = tq * (1.f/256.f) - mean*mean;
    float inv  = rsqrtf(var + 1e-5f);
    g_xkv[row*CC + t] = (v - mean)*inv*gamma[t] + beta[t];
}

// ---------------- 4: KV projection (N=512, scatter) ----------------
__global__ __launch_bounds__(256) void gemm_kv_kernel(const float* __restrict__ Wkv) {
    __shared__ unsigned As[16*132];
    __shared__ unsigned Bs[16*68];
    int tid = threadIdx.x, lane = tid & 31, w = tid >> 5;
    int wm = w >> 1, wn = w & 1;
    int gr = lane >> 2, tg = lane & 3;
    ACC_INIT
    int b = blockIdx.z, m0 = blockIdx.x*128, c0 = blockIdx.y*64;
    int kk = tid >> 4, c4 = (tid & 15)*4;
    int am = tid >> 1, akc = (tid & 1)*8;
    int arow = m0 + am; if (arow > NK-1) arow = NK-1;
    const float* ap = g_xkv + (b*NK + arow)*CC;
    for (int kt = 0; kt < 16; kt++) {
        int k0 = kt*16;
        __syncthreads();
        {
            float4 v0 = *(const float4*)(ap + k0 + akc);
            float4 v1 = *(const float4*)(ap + k0 + akc + 4);
            As[(akc+0)*132+am]=tf32c(v0.x); As[(akc+1)*132+am]=tf32c(v0.y);
            As[(akc+2)*132+am]=tf32c(v0.z); As[(akc+3)*132+am]=tf32c(v0.w);
            As[(akc+4)*132+am]=tf32c(v1.x); As[(akc+5)*132+am]=tf32c(v1.y);
            As[(akc+6)*132+am]=tf32c(v1.z); As[(akc+7)*132+am]=tf32c(v1.w);
            float4 wv = *(const float4*)(Wkv + (k0+kk)*512 + c0 + c4);
            unsigned* e = Bs + kk*68 + c4;
            e[0]=tf32c(wv.x); e[1]=tf32c(wv.y); e[2]=tf32c(wv.z); e[3]=tf32c(wv.w);
        }
        __syncthreads();
        mma_ktile(As, Bs, wm, wn, lane, acc);
    }
#pragma unroll
    for (int nj = 0; nj < 4; nj++) {
        int c = c0 + wn*32 + nj*8 + 2*tg;
        int d = c >> 4, head = (c >> 1) & 7;
        float* kb = g_k + (b*NHD + head)*NK*HD + d;
        float* vb = g_v + (b*NHD + head)*NK*HD + d;
#pragma unroll
        for (int mi = 0; mi < 2; mi++) {
            int m1 = m0 + wm*32 + mi*16 + gr;
            if (m1 < NK)   { kb[m1*HD]     = acc[mi][nj][0]; vb[m1*HD]     = acc[mi][nj][1]; }
            if (m1+8 < NK) { kb[(m1+8)*HD] = acc[mi][nj][2]; vb[(m1+8)*HD] = acc[mi][nj][3]; }
        }
    }
}

// ---------------- 5: fused flash attention, tf32 mma (Br=128, Bc=64) ------
__global__ __launch_bounds__(256, 2) void attn_kernel(const float* __restrict__ pos_emb) {
    extern __shared__ unsigned smu[];
    unsigned* qs = smu;          // [32][132]
    unsigned* ks = smu + 4224;   // [32][68]
    unsigned* vs = smu + 6400;   // [64][36]
    unsigned* ps = smu + 8704;   // 8 warps x [16][68]
    int b = blockIdx.z, head = blockIdx.y, n0 = blockIdx.x*128;
    int tid = threadIdx.x, lane = tid & 31, w = tid >> 5;
    int gr = lane >> 2, tg = lane & 3;
    const float scale = 0.17677669529663687f;
    int bh = b*NHD + head;
    const float* qg = g_q + bh*NN*HD;
    const float* kg = g_k + bh*NK*HD;
    const float* vg = g_v + bh*NK*HD;

    {   // qs fill: [d][row], scaled + tf32
        int r = tid >> 1, dc = (tid & 1)*16;
        int n = n0 + r; if (n > NN-1) n = NN-1;
        const float* p = qg + n*HD + dc;
#pragma unroll
        for (int c4 = 0; c4 < 4; c4++) {
            float4 v = *(const float4*)(p + c4*4);
            qs[(dc+c4*4+0)*132 + r] = tf32c(v.x*scale);
            qs[(dc+c4*4+1)*132 + r] = tf32c(v.y*scale);
            qs[(dc+c4*4+2)*132 + r] = tf32c(v.z*scale);
            qs[(dc+c4*4+3)*132 + r] = tf32c(v.w*scale);
        }
    }

    int rown0 = n0 + w*16 + gr, rown1 = rown0 + 8;
    int nq0 = rown0 > NN-1 ? NN-1 : rown0;
    int nq1 = rown1 > NN-1 ? NN-1 : rown1;
    int qi0 = nq0/HH, qj0 = nq0 - qi0*HH;
    int qi1 = nq1/HH, qj1 = nq1 - qi1*HH;

    float m_i[2] = {-1e30f, -1e30f}, l_i[2] = {0.f, 0.f};
    float co[4][4];
#pragma unroll
    for (int i = 0; i < 4; i++) { co[i][0]=0.f; co[i][1]=0.f; co[i][2]=0.f; co[i][3]=0.f; }
    unsigned* psw = ps + w*16*68;

    for (int t = 0; t < 13; t++) {
        int mb = t*64;
        __syncthreads();
        {   // ks [d][key] + vs [key][d] fill (zero out-of-range keys)
            int kr = tid >> 2, dc = (tid & 3)*8;
            bool ok = (mb + kr) < NK;
            int mr = ok ? (mb + kr) : 0;
            const float* kp = kg + mr*HD + dc;
            float4 a0 = *(const float4*)kp, a1 = *(const float4*)(kp+4);
            if (!ok) { a0 = make_float4(0,0,0,0); a1 = a0; }
            ks[(dc+0)*68+kr]=tf32c(a0.x); ks[(dc+1)*68+kr]=tf32c(a0.y);
            ks[(dc+2)*68+kr]=tf32c(a0.z); ks[(dc+3)*68+kr]=tf32c(a0.w);
            ks[(dc+4)*68+kr]=tf32c(a1.x); ks[(dc+5)*68+kr]=tf32c(a1.y);
            ks[(dc+6)*68+kr]=tf32c(a1.z); ks[(dc+7)*68+kr]=tf32c(a1.w);
            const float* vp = vg + mr*HD + dc;
            float4 w0 = *(const float4*)vp, w1 = *(const float4*)(vp+4);
            if (!ok) { w0 = make_float4(0,0,0,0); w1 = w0; }
            uint4 u0 = make_uint4(tf32c(w0.x), tf32c(w0.y), tf32c(w0.z), tf32c(w0.w));
            uint4 u1 = make_uint4(tf32c(w1.x), tf32c(w1.y), tf32c(w1.z), tf32c(w1.w));
            *(uint4*)(vs + kr*36 + dc)     = u0;
            *(uint4*)(vs + kr*36 + dc + 4) = u1;
        }
        __syncthreads();

        // ---- QK^T: S = 16x64 per warp ----
        float cs[8][4];
#pragma unroll
        for (int i = 0; i < 8; i++) { cs[i][0]=0.f; cs[i][1]=0.f; cs[i][2]=0.f; cs[i][3]=0.f; }
#pragma unroll
        for (int ks8 = 0; ks8 < 4; ks8++) {
            unsigned a[4];
            const unsigned* ak0 = qs + (ks8*8 + tg)*132 + w*16;
            const unsigned* ak4 = ak0 + 4*132;
            a[0] = ak0[gr]; a[1] = ak0[gr+8]; a[2] = ak4[gr]; a[3] = ak4[gr+8];
            const unsigned* bk0 = ks + (ks8*8 + tg)*68 + gr;
            const unsigned* bk4 = bk0 + 4*68;
#pragma unroll
            for (int nj = 0; nj < 8; nj++)
                mma8(cs[nj], a, bk0[nj*8], bk4[nj*8]);
        }

        // ---- bias + mask (inline from L2-resident pos_emb) ----
#pragma unroll
        for (int nj = 0; nj < 8; nj++) {
            int mk = mb + nj*8 + 2*tg;
            if (mk < NK) {
                int ki = mk/HH, kj = mk - (mk/HH)*HH;
                int ki2 = (kj == HH-1) ? ki+1 : ki;
                int kj2 = (kj == HH-1) ? 0 : kj+1;
                cs[nj][0] += __ldg(&pos_emb[(ki -qi0+55)*PEW + (kj -qj0+55)]);
                cs[nj][1] += __ldg(&pos_emb[(ki2-qi0+55)*PEW + (kj2-qj0+55)]);
                cs[nj][2] += __ldg(&pos_emb[(ki -qi1+55)*PEW + (kj -qj1+55)]);
                cs[nj][3] += __ldg(&pos_emb[(ki2-qi1+55)*PEW + (kj2-qj1+55)]);
            } else {
                cs[nj][0] = -1e30f; cs[nj][1] = -1e30f;
                cs[nj][2] = -1e30f; cs[nj][3] = -1e30f;
            }
        }

        // ---- online softmax (rows gr, gr+8; quad reduction) ----
#pragma unroll
        for (int h = 0; h < 2; h++) {
            float tm = -1e30f;
#pragma unroll
            for (int nj = 0; nj < 8; nj++) tm = fmaxf(tm, fmaxf(cs[nj][2*h], cs[nj][2*h+1]));
            tm = fmaxf(tm, __shfl_xor_sync(0xffffffffu, tm, 1));
            tm = fmaxf(tm, __shfl_xor_sync(0xffffffffu, tm, 2));
            float mnew = fmaxf(m_i[h], tm);
            float f = __expf(m_i[h] - mnew);
            m_i[h] = mnew;
            float sum = 0.f;
            unsigned* prow = psw + (gr + 8*h)*68 + 2*tg;
#pragma unroll
            for (int nj = 0; nj < 8; nj++) {
                float p0 = __expf(cs[nj][2*h]   - mnew);
                float p1 = __expf(cs[nj][2*h+1] - mnew);
                sum += p0 + p1;
                *(uint2*)(prow + nj*8) = make_uint2(tf32c(p0), tf32c(p1));
            }
            sum += __shfl_xor_sync(0xffffffffu, sum, 1);
            sum += __shfl_xor_sync(0xffffffffu, sum, 2);
            l_i[h] = l_i[h]*f + sum;
#pragma unroll
            for (int nj = 0; nj < 4; nj++) { co[nj][2*h] *= f; co[nj][2*h+1] *= f; }
        }
        __syncwarp();

        // ---- O += P @ V ----
#pragma unroll
        for (int kk8 = 0; kk8 < 8; kk8++) {
            unsigned a[4];
            const unsigned* p0 = psw + gr*68 + kk8*8 + tg;
            const unsigned* p1 = psw + (gr+8)*68 + kk8*8 + tg;
            a[0] = p0[0]; a[1] = p1[0]; a[2] = p0[4]; a[3] = p1[4];
            const unsigned* b0p = vs + (kk8*8 + tg)*36 + gr;
            const unsigned* b1p = b0p + 4*36;
#pragma unroll
            for (int nj = 0; nj < 4; nj++)
                mma8(co[nj], a, b0p[nj*8], b1p[nj*8]);
        }
        __syncwarp();
    }

    float inv0 = 1.f/l_i[0], inv1 = 1.f/l_i[1];
#pragma unroll
    for (int nj = 0; nj < 4; nj++) {
        int d = nj*8 + 2*tg;
        if (rown0 < NN)
            *(float2*)&g_ao[(b*NN + rown0)*CC + head*HD + d] =
                make_float2(co[nj][0]*inv0, co[nj][1]*inv0);
        if (rown1 < NN)
            *(float2*)&g_ao[(b*NN + rown1)*CC + head*HD + d] =
                make_float2(co[nj][2]*inv1, co[nj][3]*inv1);
    }
}

// ---------------- 6: output projection + NCHW transpose ----------------
__global__ __launch_bounds__(256) void gemm_proj_kernel(const float* __restrict__ pw,
                                                        const float* __restrict__ pb,
                                                        float* __restrict__ out) {
    __shared__ unsigned As[16*132];
    __shared__ unsigned Bs[16*68];
    int tid = threadIdx.x, lane = tid & 31, w = tid >> 5;
    int wm = w >> 1, wn = w & 1;
    int gr = lane >> 2, tg = lane & 3;
    ACC_INIT
    int b = blockIdx.z, n0 = blockIdx.x*128, c0 = blockIdx.y*64;
    int kk = tid >> 4, c4 = (tid & 15)*4;
    int am = tid >> 1, akc = (tid & 1)*8;
    int arow = n0 + am; if (arow > NN-1) arow = NN-1;
    const float* ap = g_ao + (b*NN + arow)*CC;
    for (int kt = 0; kt < 16; kt++) {
        int k0 = kt*16;
        __syncthreads();
        {
            float4 v0 = *(const float4*)(ap + k0 + akc);
            float4 v1 = *(const float4*)(ap + k0 + akc + 4);
            As[(akc+0)*132+am]=tf32c(v0.x); As[(akc+1)*132+am]=tf32c(v0.y);
            As[(akc+2)*132+am]=tf32c(v0.z); As[(akc+3)*132+am]=tf32c(v0.w);
            As[(akc+4)*132+am]=tf32c(v1.x); As[(akc+5)*132+am]=tf32c(v1.y);
            As[(akc+6)*132+am]=tf32c(v1.z); As[(akc+7)*132+am]=tf32c(v1.w);
            float4 wv = *(const float4*)(pw + (k0+kk)*CC + c0 + c4);
            unsigned* e = Bs + kk*68 + c4;
            e[0]=tf32c(wv.x); e[1]=tf32c(wv.y); e[2]=tf32c(wv.z); e[3]=tf32c(wv.w);
        }
        __syncthreads();
        mma_ktile(As, Bs, wm, wn, lane, acc);
    }
#pragma unroll
    for (int nj = 0; nj < 4; nj++) {
        int c = c0 + wn*32 + nj*8 + 2*tg;
        float2 pbv = *(const float2*)(pb + c);
        float* o0 = out + (b*CC + c)*NN;
        float* o1 = o0 + NN;
#pragma unroll
        for (int mi = 0; mi < 2; mi++) {
            int n1 = n0 + wm*32 + mi*16 + gr;
            if (n1 < NN)   { o0[n1]   = acc[mi][nj][0] + pbv.x; o1[n1]   = acc[mi][nj][1] + pbv.y; }
            if (n1+8 < NN) { o0[n1+8] = acc[mi][nj][2] + pbv.x; o1[n1+8] = acc[mi][nj][3] + pbv.y; }
        }
    }
}

// ---------------- launch ----------------
extern "C" void kernel_launch(void* const* d_in, const int* in_sizes, int n_in,
                              void* d_out, int out_size) {
    const float* x    = (const float*)d_in[0];
    const float* Wq   = (const float*)d_in[1];
    const float* Wkv  = (const float*)d_in[2];
    const float* sr_w = (const float*)d_in[3];
    const float* sr_b = (const float*)d_in[4];
    const float* ln_g = (const float*)d_in[5];
    const float* ln_b = (const float*)d_in[6];
    const float* pos  = (const float*)d_in[7];
    const float* pw   = (const float*)d_in[8];
    const float* pb   = (const float*)d_in[9];
    float* out = (float*)d_out;

    static int smem_set = 0;
    if (!smem_set) {
        cudaFuncSetAttribute(attn_kernel, cudaFuncAttributeMaxDynamicSharedMemorySize, 69632);
        smem_set = 1;
    }

    wt_kernel        <<<1024, 256>>>(sr_w);
    gemm_qconv_kernel<<<dim3(25, 20, BB), 256>>>(x, Wq);
    ln_kernel        <<<BB*NK, 256>>>(ln_g, ln_b, sr_b);
    gemm_kv_kernel   <<<dim3(7, 8, BB), 256>>>(Wkv);
    attn_kernel      <<<dim3(25, 8, BB), 256, 69632>>>(pos);
    gemm_proj_kernel <<<dim3(25, 4, BB), 256>>>(pw, pb, out);
}

// round 11
// speedup vs baseline: 1.5198x; 1.0057x over previous
#include <cuda_runtime.h>

#define BB 4
#define CC 256
#define HH 56
#define NN 3136
#define NHD 8
#define HD 32
#define NK 784
#define PEW 111

__device__ __forceinline__ unsigned tf32c(float f) {
    unsigned u; asm("cvt.rna.tf32.f32 %0, %1;" : "=r"(u) : "f"(f)); return u;
}
__device__ __forceinline__ void mma8(float c[4], const unsigned a[4], unsigned b0, unsigned b1) {
    asm("mma.sync.aligned.m16n8k8.row.col.f32.tf32.tf32.f32 "
        "{%0,%1,%2,%3},{%4,%5,%6,%7},{%8,%9},{%0,%1,%2,%3};"
        : "+f"(c[0]), "+f"(c[1]), "+f"(c[2]), "+f"(c[3])
        : "r"(a[0]), "r"(a[1]), "r"(a[2]), "r"(a[3]), "r"(b0), "r"(b1));
}

// ---------------- scratch ----------------
__device__ float    g_q   [BB*NHD*NN*HD];   // (b, head, n, d)
__device__ float    g_k   [BB*NHD*NK*HD];   // (b, head, m, d)
__device__ float    g_v   [BB*NHD*NK*HD];
__device__ float    g_xkvp[4*BB*NK*CC];     // conv partial sums (K-split)
__device__ float    g_xkv [BB*NK*CC];       // LN output
__device__ float    g_ao  [BB*NN*CC];       // (b, n, head*32+d)
__device__ unsigned g_wt  [1024*CC];        // conv weight transposed tf32

// ---------------- prep ----------------
__global__ void wt_kernel(const float* __restrict__ sr_w) {
    g_wt[blockIdx.x*CC + threadIdx.x] = tf32c(sr_w[threadIdx.x*1024 + blockIdx.x]);
}

// ---- shared mma core: block 128(M)x64(N), ktile 16; As[16][132], Bs[16][68] ----
__device__ __forceinline__ void mma_ktile(const unsigned* As, const unsigned* Bs,
                                          int wm, int wn, int lane, float acc[2][4][4]) {
    int gr = lane >> 2, gc = lane & 3;
#pragma unroll
    for (int ks = 0; ks < 2; ks++) {
        unsigned a[2][4];
        const unsigned* ak0 = As + (ks*8 + gc)*132 + wm*32;
        const unsigned* ak4 = ak0 + 4*132;
#pragma unroll
        for (int mi = 0; mi < 2; mi++) {
            int r = mi*16 + gr;
            a[mi][0] = ak0[r]; a[mi][1] = ak0[r+8];
            a[mi][2] = ak4[r]; a[mi][3] = ak4[r+8];
        }
        const unsigned* bk0 = Bs + (ks*8 + gc)*68 + wn*32 + gr;
        const unsigned* bk4 = bk0 + 4*68;
#pragma unroll
        for (int nj = 0; nj < 4; nj++) {
            unsigned b0 = bk0[nj*8], b1 = bk4[nj*8];
            mma8(acc[0][nj], a[0], b0, b1);
            mma8(acc[1][nj], a[1], b0, b1);
        }
    }
}

#define ACC_INIT                                                         \
    float acc[2][4][4];                                                  \
    _Pragma("unroll") for (int zi = 0; zi < 2; zi++)                     \
    _Pragma("unroll") for (int zj = 0; zj < 4; zj++)                     \
    _Pragma("unroll") for (int zk = 0; zk < 4; zk++) acc[zi][zj][zk] = 0.f;

// ---------------- 1+2 fused: Q projection || SR conv (K-split x4) ----------
__global__ __launch_bounds__(256) void gemm_qconv_kernel(const float* __restrict__ x,
                                                         const float* __restrict__ Wq) {
    __shared__ unsigned As[16*132];
    __shared__ unsigned Bs[16*68];
    int tid = threadIdx.x, lane = tid & 31, w = tid >> 5;
    int wm = w >> 1, wn = w & 1;
    int gr = lane >> 2, tg = lane & 3;
    int b = blockIdx.z;

    if (blockIdx.y < 4) {
        // ---------- Q projection (register-prefetch double-buffered) ----------
        ACC_INIT
        int n0 = blockIdx.x*128, c0 = blockIdx.y*64;
        int kk = tid >> 4, m8 = (tid & 15)*8, c4 = (tid & 15)*4;
        bool fok = (n0 + m8) < NN;
        const float* xb = x + b*CC*NN;

        float4 v0 = make_float4(0,0,0,0), v1 = v0, wv;
        if (fok) { const float* s = xb + kk*NN + n0 + m8;
                   v0 = *(const float4*)s; v1 = *(const float4*)(s+4); }
        wv = *(const float4*)(Wq + kk*CC + c0 + c4);

        for (int kt = 0; kt < 16; kt++) {
            {
                unsigned* d = As + kk*132 + m8;
                d[0]=tf32c(v0.x); d[1]=tf32c(v0.y); d[2]=tf32c(v0.z); d[3]=tf32c(v0.w);
                d[4]=tf32c(v1.x); d[5]=tf32c(v1.y); d[6]=tf32c(v1.z); d[7]=tf32c(v1.w);
                unsigned* e = Bs + kk*68 + c4;
                e[0]=tf32c(wv.x); e[1]=tf32c(wv.y); e[2]=tf32c(wv.z); e[3]=tf32c(wv.w);
            }
            __syncthreads();
            if (kt < 15) {
                int kg = (kt+1)*16 + kk;
                if (fok) { const float* s = xb + kg*NN + n0 + m8;
                           v0 = *(const float4*)s; v1 = *(const float4*)(s+4); }
                wv = *(const float4*)(Wq + kg*CC + c0 + c4);
            }
            mma_ktile(As, Bs, wm, wn, lane, acc);
            __syncthreads();
        }
#pragma unroll
        for (int nj = 0; nj < 4; nj++) {
            int c = c0 + wn*32 + nj*8 + 2*tg;
            int head = c >> 5, d = c & 31;
            float* qb = g_q + (b*NHD + head)*NN*HD + d;
#pragma unroll
            for (int mi = 0; mi < 2; mi++) {
                int n1 = n0 + wm*32 + mi*16 + gr;
                if (n1 < NN)   *(float2*)(qb + n1*HD)     = make_float2(acc[mi][nj][0], acc[mi][nj][1]);
                if (n1+8 < NN) *(float2*)(qb + (n1+8)*HD) = make_float2(acc[mi][nj][2], acc[mi][nj][3]);
            }
        }
    } else {
        // ---------- SR conv, K-split (R8 body, verbatim) ----------
        if (blockIdx.x >= 7) return;
        ACC_INIT
        int yy = blockIdx.y - 4;
        int part = yy >> 2;
        int o0 = (yy & 3) * 64;
        int m0 = blockIdx.x * 128;
        int kk = tid >> 4, m8 = (tid & 15)*8, c4 = (tid & 15)*4;
        bool fok = (m0 + m8) < NK;
        const float* xb = x + b*CC*NN;
        int sb[8];
#pragma unroll
        for (int c = 0; c < 8; c++) {
            int m = fok ? (m0 + m8 + c) : 0;
            int r = m / 28;
            sb[c] = (2*r)*HH + 2*(m - r*28);
        }
        int kbase = part*256;

        float va[8]; uint4 vb4;
        {
            int kg = kbase + kk;
            int ic = kg >> 2, kh = (kg >> 1) & 1, kw = kg & 1;
            const float* s = xb + ic*NN + kh*HH + kw;
#pragma unroll
            for (int c = 0; c < 8; c++) va[c] = fok ? s[sb[c]] : 0.f;
            vb4 = *(const uint4*)(g_wt + kg*CC + o0 + c4);
        }
        for (int kt = 0; kt < 16; kt++) {
            unsigned* d = As + kk*132 + m8;
#pragma unroll
            for (int c = 0; c < 8; c++) d[c] = tf32c(va[c]);
            *(uint4*)(Bs + kk*68 + c4) = vb4;
            __syncthreads();
            if (kt < 15) {
                int kg = kbase + (kt+1)*16 + kk;
                int ic = kg >> 2, kh = (kg >> 1) & 1, kw = kg & 1;
                const float* s = xb + ic*NN + kh*HH + kw;
#pragma unroll
                for (int c = 0; c < 8; c++) va[c] = fok ? s[sb[c]] : 0.f;
                vb4 = *(const uint4*)(g_wt + kg*CC + o0 + c4);
            }
            mma_ktile(As, Bs, wm, wn, lane, acc);
            __syncthreads();
        }
        float* dstp = g_xkvp + part*(BB*NK*CC) + (b*NK)*CC;
#pragma unroll
        for (int nj = 0; nj < 4; nj++) {
            int c = o0 + wn*32 + nj*8 + 2*tg;
#pragma unroll
            for (int mi = 0; mi < 2; mi++) {
                int m1 = m0 + wm*32 + mi*16 + gr;
                if (m1 < NK)   *(float2*)(&dstp[m1*CC + c]) =
                    make_float2(acc[mi][nj][0], acc[mi][nj][1]);
                if (m1+8 < NK) *(float2*)(&dstp[(m1+8)*CC + c]) =
                    make_float2(acc[mi][nj][2], acc[mi][nj][3]);
            }
        }
    }
}

// ---------------- 3: LayerNorm (sums 4 conv partials + bias) ----------------
__global__ void ln_kernel(const float* __restrict__ gamma, const float* __restrict__ beta,
                          const float* __restrict__ sr_b) {
    int row = blockIdx.x, t = threadIdx.x;
    int idx = row*CC + t;
    const int stride = BB*NK*CC;
    float v = ((g_xkvp[idx] + g_xkvp[idx + stride]) +
               (g_xkvp[idx + 2*stride] + g_xkvp[idx + 3*stride])) + sr_b[t];
    float s = v, q = v*v;
#pragma unroll
    for (int m = 16; m >= 1; m >>= 1) {
        s += __shfl_xor_sync(0xffffffffu, s, m);
        q += __shfl_xor_sync(0xffffffffu, q, m);
    }
    __shared__ float r1[8], r2[8];
    if ((t & 31) == 0) { r1[t>>5] = s; r2[t>>5] = q; }
    __syncthreads();
    float tot = 0.f, tq = 0.f;
#pragma unroll
    for (int wv = 0; wv < 8; wv++) { tot += r1[wv]; tq += r2[wv]; }
    float mean = tot * (1.f/256.f);
    float var  = tq * (1.f/256.f) - mean*mean;
    float inv  = rsqrtf(var + 1e-5f);
    g_xkv[row*CC + t] = (v - mean)*inv*gamma[t] + beta[t];
}

// ---------------- 4: KV projection (register-prefetch double-buffered) -----
__global__ __launch_bounds__(256) void gemm_kv_kernel(const float* __restrict__ Wkv) {
    __shared__ unsigned As[16*132];
    __shared__ unsigned Bs[16*68];
    int tid = threadIdx.x, lane = tid & 31, w = tid >> 5;
    int wm = w >> 1, wn = w & 1;
    int gr = lane >> 2, tg = lane & 3;
    ACC_INIT
    int b = blockIdx.z, m0 = blockIdx.x*128, c0 = blockIdx.y*64;
    int kk = tid >> 4, c4 = (tid & 15)*4;
    int am = tid >> 1, akc = (tid & 1)*8;
    int arow = m0 + am; if (arow > NK-1) arow = NK-1;
    const float* ap = g_xkv + (b*NK + arow)*CC;

    float4 v0, v1, wv;
    v0 = *(const float4*)(ap + akc);
    v1 = *(const float4*)(ap + akc + 4);
    wv = *(const float4*)(Wkv + kk*512 + c0 + c4);

    for (int kt = 0; kt < 16; kt++) {
        {
            As[(akc+0)*132+am]=tf32c(v0.x); As[(akc+1)*132+am]=tf32c(v0.y);
            As[(akc+2)*132+am]=tf32c(v0.z); As[(akc+3)*132+am]=tf32c(v0.w);
            As[(akc+4)*132+am]=tf32c(v1.x); As[(akc+5)*132+am]=tf32c(v1.y);
            As[(akc+6)*132+am]=tf32c(v1.z); As[(akc+7)*132+am]=tf32c(v1.w);
            unsigned* e = Bs + kk*68 + c4;
            e[0]=tf32c(wv.x); e[1]=tf32c(wv.y); e[2]=tf32c(wv.z); e[3]=tf32c(wv.w);
        }
        __syncthreads();
        if (kt < 15) {
            int k0 = (kt+1)*16;
            v0 = *(const float4*)(ap + k0 + akc);
            v1 = *(const float4*)(ap + k0 + akc + 4);
            wv = *(const float4*)(Wkv + (k0+kk)*512 + c0 + c4);
        }
        mma_ktile(As, Bs, wm, wn, lane, acc);
        __syncthreads();
    }
#pragma unroll
    for (int nj = 0; nj < 4; nj++) {
        int c = c0 + wn*32 + nj*8 + 2*tg;
        int d = c >> 4, head = (c >> 1) & 7;
        float* kb = g_k + (b*NHD + head)*NK*HD + d;
        float* vb = g_v + (b*NHD + head)*NK*HD + d;
#pragma unroll
        for (int mi = 0; mi < 2; mi++) {
            int m1 = m0 + wm*32 + mi*16 + gr;
            if (m1 < NK)   { kb[m1*HD]     = acc[mi][nj][0]; vb[m1*HD]     = acc[mi][nj][1]; }
            if (m1+8 < NK) { kb[(m1+8)*HD] = acc[mi][nj][2]; vb[(m1+8)*HD] = acc[mi][nj][3]; }
        }
    }
}

// ---------------- 5: fused flash attention (R10 body, untouched) ------
__global__ __launch_bounds__(256, 2) void attn_kernel(const float* __restrict__ pos_emb) {
    extern __shared__ unsigned smu[];
    unsigned* qs = smu;          // [32][132]
    unsigned* ks = smu + 4224;   // [32][68]
    unsigned* vs = smu + 6400;   // [64][36]
    unsigned* ps = smu + 8704;   // 8 warps x [16][68]
    int b = blockIdx.z, head = blockIdx.y, n0 = blockIdx.x*128;
    int tid = threadIdx.x, lane = tid & 31, w = tid >> 5;
    int gr = lane >> 2, tg = lane & 3;
    const float scale = 0.17677669529663687f;
    int bh = b*NHD + head;
    const float* qg = g_q + bh*NN*HD;
    const float* kg = g_k + bh*NK*HD;
    const float* vg = g_v + bh*NK*HD;

    {   // qs fill: [d][row], scaled + tf32
        int r = tid >> 1, dc = (tid & 1)*16;
        int n = n0 + r; if (n > NN-1) n = NN-1;
        const float* p = qg + n*HD + dc;
#pragma unroll
        for (int c4 = 0; c4 < 4; c4++) {
            float4 v = *(const float4*)(p + c4*4);
            qs[(dc+c4*4+0)*132 + r] = tf32c(v.x*scale);
            qs[(dc+c4*4+1)*132 + r] = tf32c(v.y*scale);
            qs[(dc+c4*4+2)*132 + r] = tf32c(v.z*scale);
            qs[(dc+c4*4+3)*132 + r] = tf32c(v.w*scale);
        }
    }

    int rown0 = n0 + w*16 + gr, rown1 = rown0 + 8;
    int nq0 = rown0 > NN-1 ? NN-1 : rown0;
    int nq1 = rown1 > NN-1 ? NN-1 : rown1;
    int qi0 = nq0/HH, qj0 = nq0 - qi0*HH;
    int qi1 = nq1/HH, qj1 = nq1 - qi1*HH;

    float m_i[2] = {-1e30f, -1e30f}, l_i[2] = {0.f, 0.f};
    float co[4][4];
#pragma unroll
    for (int i = 0; i < 4; i++) { co[i][0]=0.f; co[i][1]=0.f; co[i][2]=0.f; co[i][3]=0.f; }
    unsigned* psw = ps + w*16*68;

    for (int t = 0; t < 13; t++) {
        int mb = t*64;
        __syncthreads();
        {   // ks [d][key] + vs [key][d] fill (zero out-of-range keys)
            int kr = tid >> 2, dc = (tid & 3)*8;
            bool ok = (mb + kr) < NK;
            int mr = ok ? (mb + kr) : 0;
            const float* kp = kg + mr*HD + dc;
            float4 a0 = *(const float4*)kp, a1 = *(const float4*)(kp+4);
            if (!ok) { a0 = make_float4(0,0,0,0); a1 = a0; }
            ks[(dc+0)*68+kr]=tf32c(a0.x); ks[(dc+1)*68+kr]=tf32c(a0.y);
            ks[(dc+2)*68+kr]=tf32c(a0.z); ks[(dc+3)*68+kr]=tf32c(a0.w);
            ks[(dc+4)*68+kr]=tf32c(a1.x); ks[(dc+5)*68+kr]=tf32c(a1.y);
            ks[(dc+6)*68+kr]=tf32c(a1.z); ks[(dc+7)*68+kr]=tf32c(a1.w);
            const float* vp = vg + mr*HD + dc;
            float4 w0 = *(const float4*)vp, w1 = *(const float4*)(vp+4);
            if (!ok) { w0 = make_float4(0,0,0,0); w1 = w0; }
            uint4 u0 = make_uint4(tf32c(w0.x), tf32c(w0.y), tf32c(w0.z), tf32c(w0.w));
            uint4 u1 = make_uint4(tf32c(w1.x), tf32c(w1.y), tf32c(w1.z), tf32c(w1.w));
            *(uint4*)(vs + kr*36 + dc)     = u0;
            *(uint4*)(vs + kr*36 + dc + 4) = u1;
        }
        __syncthreads();

        // ---- QK^T: S = 16x64 per warp ----
        float cs[8][4];
#pragma unroll
        for (int i = 0; i < 8; i++) { cs[i][0]=0.f; cs[i][1]=0.f; cs[i][2]=0.f; cs[i][3]=0.f; }
#pragma unroll
        for (int ks8 = 0; ks8 < 4; ks8++) {
            unsigned a[4];
            const unsigned* ak0 = qs + (ks8*8 + tg)*132 + w*16;
            const unsigned* ak4 = ak0 + 4*132;
            a[0] = ak0[gr]; a[1] = ak0[gr+8]; a[2] = ak4[gr]; a[3] = ak4[gr+8];
            const unsigned* bk0 = ks + (ks8*8 + tg)*68 + gr;
            const unsigned* bk4 = bk0 + 4*68;
#pragma unroll
            for (int nj = 0; nj < 8; nj++)
                mma8(cs[nj], a, bk0[nj*8], bk4[nj*8]);
        }

        // ---- bias + mask (inline from L2-resident pos_emb) ----
#pragma unroll
        for (int nj = 0; nj < 8; nj++) {
            int mk = mb + nj*8 + 2*tg;
            if (mk < NK) {
                int ki = mk/HH, kj = mk - (mk/HH)*HH;
                int ki2 = (kj == HH-1) ? ki+1 : ki;
                int kj2 = (kj == HH-1) ? 0 : kj+1;
                cs[nj][0] += __ldg(&pos_emb[(ki -qi0+55)*PEW + (kj -qj0+55)]);
                cs[nj][1] += __ldg(&pos_emb[(ki2-qi0+55)*PEW + (kj2-qj0+55)]);
                cs[nj][2] += __ldg(&pos_emb[(ki -qi1+55)*PEW + (kj -qj1+55)]);
                cs[nj][3] += __ldg(&pos_emb[(ki2-qi1+55)*PEW + (kj2-qj1+55)]);
            } else {
                cs[nj][0] = -1e30f; cs[nj][1] = -1e30f;
                cs[nj][2] = -1e30f; cs[nj][3] = -1e30f;
            }
        }

        // ---- online softmax (rows gr, gr+8; quad reduction) ----
#pragma unroll
        for (int h = 0; h < 2; h++) {
            float tm = -1e30f;
#pragma unroll
            for (int nj = 0; nj < 8; nj++) tm = fmaxf(tm, fmaxf(cs[nj][2*h], cs[nj][2*h+1]));
            tm = fmaxf(tm, __shfl_xor_sync(0xffffffffu, tm, 1));
            tm = fmaxf(tm, __shfl_xor_sync(0xffffffffu, tm, 2));
            float mnew = fmaxf(m_i[h], tm);
            float f = __expf(m_i[h] - mnew);
            m_i[h] = mnew;
            float sum = 0.f;
            unsigned* prow = psw + (gr + 8*h)*68 + 2*tg;
#pragma unroll
            for (int nj = 0; nj < 8; nj++) {
                float p0 = __expf(cs[nj][2*h]   - mnew);
                float p1 = __expf(cs[nj][2*h+1] - mnew);
                sum += p0 + p1;
                *(uint2*)(prow + nj*8) = make_uint2(tf32c(p0), tf32c(p1));
            }
            sum += __shfl_xor_sync(0xffffffffu, sum, 1);
            sum += __shfl_xor_sync(0xffffffffu, sum, 2);
            l_i[h] = l_i[h]*f + sum;
#pragma unroll
            for (int nj = 0; nj < 4; nj++) { co[nj][2*h] *= f; co[nj][2*h+1] *= f; }
        }
        __syncwarp();

        // ---- O += P @ V ----
#pragma unroll
        for (int kk8 = 0; kk8 < 8; kk8++) {
            unsigned a[4];
            const unsigned* p0 = psw + gr*68 + kk8*8 + tg;
            const unsigned* p1 = psw + (gr+8)*68 + kk8*8 + tg;
            a[0] = p0[0]; a[1] = p1[0]; a[2] = p0[4]; a[3] = p1[4];
            const unsigned* b0p = vs + (kk8*8 + tg)*36 + gr;
            const unsigned* b1p = b0p + 4*36;
#pragma unroll
            for (int nj = 0; nj < 4; nj++)
                mma8(co[nj], a, b0p[nj*8], b1p[nj*8]);
        }
        __syncwarp();
    }

    float inv0 = 1.f/l_i[0], inv1 = 1.f/l_i[1];
#pragma unroll
    for (int nj = 0; nj < 4; nj++) {
        int d = nj*8 + 2*tg;
        if (rown0 < NN)
            *(float2*)&g_ao[(b*NN + rown0)*CC + head*HD + d] =
                make_float2(co[nj][0]*inv0, co[nj][1]*inv0);
        if (rown1 < NN)
            *(float2*)&g_ao[(b*NN + rown1)*CC + head*HD + d] =
                make_float2(co[nj][2]*inv1, co[nj][3]*inv1);
    }
}

// ---------------- 6: output projection (register-prefetch double-buffered) -
__global__ __launch_bounds__(256) void gemm_proj_kernel(const float* __restrict__ pw,
                                                        const float* __restrict__ pb,
                                                        float* __restrict__ out) {
    __shared__ unsigned As[16*132];
    __shared__ unsigned Bs[16*68];
    int tid = threadIdx.x, lane = tid & 31, w = tid >> 5;
    int wm = w >> 1, wn = w & 1;
    int gr = lane >> 2, tg = lane & 3;
    ACC_INIT
    int b = blockIdx.z, n0 = blockIdx.x*128, c0 = blockIdx.y*64;
    int kk = tid >> 4, c4 = (tid & 15)*4;
    int am = tid >> 1, akc = (tid & 1)*8;
    int arow = n0 + am; if (arow > NN-1) arow = NN-1;
    const float* ap = g_ao + (b*NN + arow)*CC;

    float4 v0, v1, wv;
    v0 = *(const float4*)(ap + akc);
    v1 = *(const float4*)(ap + akc + 4);
    wv = *(const float4*)(pw + kk*CC + c0 + c4);

    for (int kt = 0; kt < 16; kt++) {
        {
            As[(akc+0)*132+am]=tf32c(v0.x); As[(akc+1)*132+am]=tf32c(v0.y);
            As[(akc+2)*132+am]=tf32c(v0.z); As[(akc+3)*132+am]=tf32c(v0.w);
            As[(akc+4)*132+am]=tf32c(v1.x); As[(akc+5)*132+am]=tf32c(v1.y);
            As[(akc+6)*132+am]=tf32c(v1.z); As[(akc+7)*132+am]=tf32c(v1.w);
            unsigned* e = Bs + kk*68 + c4;
            e[0]=tf32c(wv.x); e[1]=tf32c(wv.y); e[2]=tf32c(wv.z); e[3]=tf32c(wv.w);
        }
        __syncthreads();
        if (kt < 15) {
            int k0 = (kt+1)*16;
            v0 = *(const float4*)(ap + k0 + akc);
            v1 = *(const float4*)(ap + k0 + akc + 4);
            wv = *(const float4*)(pw + (k0+kk)*CC + c0 + c4);
        }
        mma_ktile(As, Bs, wm, wn, lane, acc);
        __syncthreads();
    }
#pragma unroll
    for (int nj = 0; nj < 4; nj++) {
        int c = c0 + wn*32 + nj*8 + 2*tg;
        float2 pbv = *(const float2*)(pb + c);
        float* o0 = out + (b*CC + c)*NN;
        float* o1 = o0 + NN;
#pragma unroll
        for (int mi = 0; mi < 2; mi++) {
            int n1 = n0 + wm*32 + mi*16 + gr;
            if (n1 < NN)   { o0[n1]   = acc[mi][nj][0] + pbv.x; o1[n1]   = acc[mi][nj][1] + pbv.y; }
            if (n1+8 < NN) { o0[n1+8] = acc[mi][nj][2] + pbv.x; o1[n1+8] = acc[mi][nj][3] + pbv.y; }
        }
    }
}

// ---------------- launch ----------------
extern "C" void kernel_launch(void* const* d_in, const int* in_sizes, int n_in,
                              void* d_out, int out_size) {
    const float* x    = (const float*)d_in[0];
    const float* Wq   = (const float*)d_in[1];
    const float* Wkv  = (const float*)d_in[2];
    const float* sr_w = (const float*)d_in[3];
    const float* sr_b = (const float*)d_in[4];
    const float* ln_g = (const float*)d_in[5];
    const float* ln_b = (const float*)d_in[6];
    const float* pos  = (const float*)d_in[7];
    const float* pw   = (const float*)d_in[8];
    const float* pb   = (const float*)d_in[9];
    float* out = (float*)d_out;

    static int smem_set = 0;
    if (!smem_set) {
        cudaFuncSetAttribute(attn_kernel, cudaFuncAttributeMaxDynamicSharedMemorySize, 69632);
        smem_set = 1;
    }

    wt_kernel        <<<1024, 256>>>(sr_w);
    gemm_qconv_kernel<<<dim3(25, 20, BB), 256>>>(x, Wq);
    ln_kernel        <<<BB*NK, 256>>>(ln_g, ln_b, sr_b);
    gemm_kv_kernel   <<<dim3(7, 8, BB), 256>>>(Wkv);
    attn_kernel      <<<dim3(25, 8, BB), 256, 69632>>>(pos);
    gemm_proj_kernel <<<dim3(25, 4, BB), 256>>>(pw, pb, out);
}

// round 12
// speedup vs baseline: 1.5585x; 1.0255x over previous
#include <cuda_runtime.h>

#define BB 4
#define CC 256
#define HH 56
#define NN 3136
#define NHD 8
#define HD 32
#define NK 784
#define PEW 111

__device__ __forceinline__ unsigned tf32c(float f) {
    unsigned u; asm("cvt.rna.tf32.f32 %0, %1;" : "=r"(u) : "f"(f)); return u;
}
__device__ __forceinline__ void mma8(float c[4], const unsigned a[4], unsigned b0, unsigned b1) {
    asm("mma.sync.aligned.m16n8k8.row.col.f32.tf32.tf32.f32 "
        "{%0,%1,%2,%3},{%4,%5,%6,%7},{%8,%9},{%0,%1,%2,%3};"
        : "+f"(c[0]), "+f"(c[1]), "+f"(c[2]), "+f"(c[3])
        : "r"(a[0]), "r"(a[1]), "r"(a[2]), "r"(a[3]), "r"(b0), "r"(b1));
}

// ---------------- scratch ----------------
__device__ float    g_q   [BB*NHD*NN*HD];   // (b, head, n, d)
__device__ float    g_k   [BB*NHD*NK*HD];   // (b, head, m, d)
__device__ float    g_v   [BB*NHD*NK*HD];
__device__ float    g_xkvp[4*BB*NK*CC];     // conv partial sums (K-split)
__device__ float    g_xkv [BB*NK*CC];       // LN output
__device__ float    g_kvp [2*BB*NK*512];    // kv partial sums (K-split x2)
__device__ float    g_ao  [BB*NN*CC];       // (b, n, head*32+d)
__device__ unsigned g_wt  [1024*CC];        // conv weight transposed tf32

// ---------------- prep ----------------
__global__ void wt_kernel(const float* __restrict__ sr_w) {
    g_wt[blockIdx.x*CC + threadIdx.x] = tf32c(sr_w[threadIdx.x*1024 + blockIdx.x]);
}

// ---- shared mma core: block 128(M)x64(N), ktile 16; As[16][132], Bs[16][68] ----
__device__ __forceinline__ void mma_ktile(const unsigned* As, const unsigned* Bs,
                                          int wm, int wn, int lane, float acc[2][4][4]) {
    int gr = lane >> 2, gc = lane & 3;
#pragma unroll
    for (int ks = 0; ks < 2; ks++) {
        unsigned a[2][4];
        const unsigned* ak0 = As + (ks*8 + gc)*132 + wm*32;
        const unsigned* ak4 = ak0 + 4*132;
#pragma unroll
        for (int mi = 0; mi < 2; mi++) {
            int r = mi*16 + gr;
            a[mi][0] = ak0[r]; a[mi][1] = ak0[r+8];
            a[mi][2] = ak4[r]; a[mi][3] = ak4[r+8];
        }
        const unsigned* bk0 = Bs + (ks*8 + gc)*68 + wn*32 + gr;
        const unsigned* bk4 = bk0 + 4*68;
#pragma unroll
        for (int nj = 0; nj < 4; nj++) {
            unsigned b0 = bk0[nj*8], b1 = bk4[nj*8];
            mma8(acc[0][nj], a[0], b0, b1);
            mma8(acc[1][nj], a[1], b0, b1);
        }
    }
}

#define ACC_INIT                                                         \
    float acc[2][4][4];                                                  \
    _Pragma("unroll") for (int zi = 0; zi < 2; zi++)                     \
    _Pragma("unroll") for (int zj = 0; zj < 4; zj++)                     \
    _Pragma("unroll") for (int zk = 0; zk < 4; zk++) acc[zi][zj][zk] = 0.f;

// ---------------- 1+2 fused: Q projection || SR conv (K-split x4) ----------
__global__ __launch_bounds__(256) void gemm_qconv_kernel(const float* __restrict__ x,
                                                         const float* __restrict__ Wq) {
    __shared__ unsigned As[16*132];
    __shared__ unsigned Bs[16*68];
    int tid = threadIdx.x, lane = tid & 31, w = tid >> 5;
    int wm = w >> 1, wn = w & 1;
    int gr = lane >> 2, tg = lane & 3;
    int b = blockIdx.z;

    if (blockIdx.y < 4) {
        // ---------- Q projection (register-prefetch double-buffered) ----------
        ACC_INIT
        int n0 = blockIdx.x*128, c0 = blockIdx.y*64;
        int kk = tid >> 4, m8 = (tid & 15)*8, c4 = (tid & 15)*4;
        bool fok = (n0 + m8) < NN;
        const float* xb = x + b*CC*NN;

        float4 v0 = make_float4(0,0,0,0), v1 = v0, wv;
        if (fok) { const float* s = xb + kk*NN + n0 + m8;
                   v0 = *(const float4*)s; v1 = *(const float4*)(s+4); }
        wv = *(const float4*)(Wq + kk*CC + c0 + c4);

        for (int kt = 0; kt < 16; kt++) {
            {
                unsigned* d = As + kk*132 + m8;
                d[0]=tf32c(v0.x); d[1]=tf32c(v0.y); d[2]=tf32c(v0.z); d[3]=tf32c(v0.w);
                d[4]=tf32c(v1.x); d[5]=tf32c(v1.y); d[6]=tf32c(v1.z); d[7]=tf32c(v1.w);
                unsigned* e = Bs + kk*68 + c4;
                e[0]=tf32c(wv.x); e[1]=tf32c(wv.y); e[2]=tf32c(wv.z); e[3]=tf32c(wv.w);
            }
            __syncthreads();
            if (kt < 15) {
                int kg = (kt+1)*16 + kk;
                if (fok) { const float* s = xb + kg*NN + n0 + m8;
                           v0 = *(const float4*)s; v1 = *(const float4*)(s+4); }
                wv = *(const float4*)(Wq + kg*CC + c0 + c4);
            }
            mma_ktile(As, Bs, wm, wn, lane, acc);
            __syncthreads();
        }
#pragma unroll
        for (int nj = 0; nj < 4; nj++) {
            int c = c0 + wn*32 + nj*8 + 2*tg;
            int head = c >> 5, d = c & 31;
            float* qb = g_q + (b*NHD + head)*NN*HD + d;
#pragma unroll
            for (int mi = 0; mi < 2; mi++) {
                int n1 = n0 + wm*32 + mi*16 + gr;
                if (n1 < NN)   *(float2*)(qb + n1*HD)     = make_float2(acc[mi][nj][0], acc[mi][nj][1]);
                if (n1+8 < NN) *(float2*)(qb + (n1+8)*HD) = make_float2(acc[mi][nj][2], acc[mi][nj][3]);
            }
        }
    } else {
        // ---------- SR conv, K-split (R8 body, verbatim) ----------
        if (blockIdx.x >= 7) return;
        ACC_INIT
        int yy = blockIdx.y - 4;
        int part = yy >> 2;
        int o0 = (yy & 3) * 64;
        int m0 = blockIdx.x * 128;
        int kk = tid >> 4, m8 = (tid & 15)*8, c4 = (tid & 15)*4;
        bool fok = (m0 + m8) < NK;
        const float* xb = x + b*CC*NN;
        int sb[8];
#pragma unroll
        for (int c = 0; c < 8; c++) {
            int m = fok ? (m0 + m8 + c) : 0;
            int r = m / 28;
            sb[c] = (2*r)*HH + 2*(m - r*28);
        }
        int kbase = part*256;

        float va[8]; uint4 vb4;
        {
            int kg = kbase + kk;
            int ic = kg >> 2, kh = (kg >> 1) & 1, kw = kg & 1;
            const float* s = xb + ic*NN + kh*HH + kw;
#pragma unroll
            for (int c = 0; c < 8; c++) va[c] = fok ? s[sb[c]] : 0.f;
            vb4 = *(const uint4*)(g_wt + kg*CC + o0 + c4);
        }
        for (int kt = 0; kt < 16; kt++) {
            unsigned* d = As + kk*132 + m8;
#pragma unroll
            for (int c = 0; c < 8; c++) d[c] = tf32c(va[c]);
            *(uint4*)(Bs + kk*68 + c4) = vb4;
            __syncthreads();
            if (kt < 15) {
                int kg = kbase + (kt+1)*16 + kk;
                int ic = kg >> 2, kh = (kg >> 1) & 1, kw = kg & 1;
                const float* s = xb + ic*NN + kh*HH + kw;
#pragma unroll
                for (int c = 0; c < 8; c++) va[c] = fok ? s[sb[c]] : 0.f;
                vb4 = *(const uint4*)(g_wt + kg*CC + o0 + c4);
            }
            mma_ktile(As, Bs, wm, wn, lane, acc);
            __syncthreads();
        }
        float* dstp = g_xkvp + part*(BB*NK*CC) + (b*NK)*CC;
#pragma unroll
        for (int nj = 0; nj < 4; nj++) {
            int c = o0 + wn*32 + nj*8 + 2*tg;
#pragma unroll
            for (int mi = 0; mi < 2; mi++) {
                int m1 = m0 + wm*32 + mi*16 + gr;
                if (m1 < NK)   *(float2*)(&dstp[m1*CC + c]) =
                    make_float2(acc[mi][nj][0], acc[mi][nj][1]);
                if (m1+8 < NK) *(float2*)(&dstp[(m1+8)*CC + c]) =
                    make_float2(acc[mi][nj][2], acc[mi][nj][3]);
            }
        }
    }
}

// ---------------- 3: LayerNorm (sums 4 conv partials + bias) ----------------
__global__ void ln_kernel(const float* __restrict__ gamma, const float* __restrict__ beta,
                          const float* __restrict__ sr_b) {
    int row = blockIdx.x, t = threadIdx.x;
    int idx = row*CC + t;
    const int stride = BB*NK*CC;
    float v = ((g_xkvp[idx] + g_xkvp[idx + stride]) +
               (g_xkvp[idx + 2*stride] + g_xkvp[idx + 3*stride])) + sr_b[t];
    float s = v, q = v*v;
#pragma unroll
    for (int m = 16; m >= 1; m >>= 1) {
        s += __shfl_xor_sync(0xffffffffu, s, m);
        q += __shfl_xor_sync(0xffffffffu, q, m);
    }
    __shared__ float r1[8], r2[8];
    if ((t & 31) == 0) { r1[t>>5] = s; r2[t>>5] = q; }
    __syncthreads();
    float tot = 0.f, tq = 0.f;
#pragma unroll
    for (int wv = 0; wv < 8; wv++) { tot += r1[wv]; tq += r2[wv]; }
    float mean = tot * (1.f/256.f);
    float var  = tq * (1.f/256.f) - mean*mean;
    float inv  = rsqrtf(var + 1e-5f);
    g_xkv[row*CC + t] = (v - mean)*inv*gamma[t] + beta[t];
}

// ---------------- 4: KV projection, K-split x2 -> partial buffers -----------
__global__ __launch_bounds__(256) void gemm_kv_kernel(const float* __restrict__ Wkv) {
    __shared__ unsigned As[16*132];
    __shared__ unsigned Bs[16*68];
    int tid = threadIdx.x, lane = tid & 31, w = tid >> 5;
    int wm = w >> 1, wn = w & 1;
    int gr = lane >> 2, tg = lane & 3;
    ACC_INIT
    int b = blockIdx.z, m0 = blockIdx.x*128;
    int part = blockIdx.y >> 3;
    int c0 = (blockIdx.y & 7)*64;
    int kk = tid >> 4, c4 = (tid & 15)*4;
    int am = tid >> 1, akc = (tid & 1)*8;
    int arow = m0 + am; if (arow > NK-1) arow = NK-1;
    const float* ap = g_xkv + (b*NK + arow)*CC + part*128;
    const float* wp = Wkv + part*128*512;

    float4 v0, v1, wv;
    v0 = *(const float4*)(ap + akc);
    v1 = *(const float4*)(ap + akc + 4);
    wv = *(const float4*)(wp + kk*512 + c0 + c4);

    for (int kt = 0; kt < 8; kt++) {
        {
            As[(akc+0)*132+am]=tf32c(v0.x); As[(akc+1)*132+am]=tf32c(v0.y);
            As[(akc+2)*132+am]=tf32c(v0.z); As[(akc+3)*132+am]=tf32c(v0.w);
            As[(akc+4)*132+am]=tf32c(v1.x); As[(akc+5)*132+am]=tf32c(v1.y);
            As[(akc+6)*132+am]=tf32c(v1.z); As[(akc+7)*132+am]=tf32c(v1.w);
            unsigned* e = Bs + kk*68 + c4;
            e[0]=tf32c(wv.x); e[1]=tf32c(wv.y); e[2]=tf32c(wv.z); e[3]=tf32c(wv.w);
        }
        __syncthreads();
        if (kt < 7) {
            int k0 = (kt+1)*16;
            v0 = *(const float4*)(ap + k0 + akc);
            v1 = *(const float4*)(ap + k0 + akc + 4);
            wv = *(const float4*)(wp + (k0+kk)*512 + c0 + c4);
        }
        mma_ktile(As, Bs, wm, wn, lane, acc);
        __syncthreads();
    }
    float* dstp = g_kvp + ((part*BB + b)*NK)*512;
#pragma unroll
    for (int nj = 0; nj < 4; nj++) {
        int c = c0 + wn*32 + nj*8 + 2*tg;
#pragma unroll
        for (int mi = 0; mi < 2; mi++) {
            int m1 = m0 + wm*32 + mi*16 + gr;
            if (m1 < NK)   *(float2*)(&dstp[m1*512 + c]) =
                make_float2(acc[mi][nj][0], acc[mi][nj][1]);
            if (m1+8 < NK) *(float2*)(&dstp[(m1+8)*512 + c]) =
                make_float2(acc[mi][nj][2], acc[mi][nj][3]);
        }
    }
}

// ---------------- 4b: combine kv partials + scatter to g_k/g_v --------------
__global__ void kvcomb_kernel() {
    int m = blockIdx.x, b = blockIdx.y, c = threadIdx.x;   // 512 threads
    int idx = (b*NK + m)*512 + c;
    float val = g_kvp[idx] + g_kvp[BB*NK*512 + idx];
    int d = c >> 4, head = (c >> 1) & 7, sel = c & 1;
    float* dst = sel ? g_v : g_k;
    dst[((b*NHD + head)*NK + m)*HD + d] = val;
}

// ---------------- 5: fused flash attention (occupancy 3) ------
__global__ __launch_bounds__(256, 3) void attn_kernel(const float* __restrict__ pos_emb) {
    extern __shared__ unsigned smu[];
    unsigned* qs = smu;          // [32][132]
    unsigned* ks = smu + 4224;   // [32][68]
    unsigned* vs = smu + 6400;   // [64][36]
    unsigned* ps = smu + 8704;   // 8 warps x [16][68]
    int b = blockIdx.z, head = blockIdx.y, n0 = blockIdx.x*128;
    int tid = threadIdx.x, lane = tid & 31, w = tid >> 5;
    int gr = lane >> 2, tg = lane & 3;
    const float scale = 0.17677669529663687f;
    int bh = b*NHD + head;
    const float* qg = g_q + bh*NN*HD;
    const float* kg = g_k + bh*NK*HD;
    const float* vg = g_v + bh*NK*HD;

    {   // qs fill: [d][row], scaled + tf32
        int r = tid >> 1, dc = (tid & 1)*16;
        int n = n0 + r; if (n > NN-1) n = NN-1;
        const float* p = qg + n*HD + dc;
#pragma unroll
        for (int c4 = 0; c4 < 4; c4++) {
            float4 v = *(const float4*)(p + c4*4);
            qs[(dc+c4*4+0)*132 + r] = tf32c(v.x*scale);
            qs[(dc+c4*4+1)*132 + r] = tf32c(v.y*scale);
            qs[(dc+c4*4+2)*132 + r] = tf32c(v.z*scale);
            qs[(dc+c4*4+3)*132 + r] = tf32c(v.w*scale);
        }
    }

    int rown0 = n0 + w*16 + gr, rown1 = rown0 + 8;
    int nq0 = rown0 > NN-1 ? NN-1 : rown0;
    int nq1 = rown1 > NN-1 ? NN-1 : rown1;
    int qi0 = nq0/HH, qj0 = nq0 - qi0*HH;
    int qi1 = nq1/HH, qj1 = nq1 - qi1*HH;

    float m_i[2] = {-1e30f, -1e30f}, l_i[2] = {0.f, 0.f};
    float co[4][4];
#pragma unroll
    for (int i = 0; i < 4; i++) { co[i][0]=0.f; co[i][1]=0.f; co[i][2]=0.f; co[i][3]=0.f; }
    unsigned* psw = ps + w*16*68;

    for (int t = 0; t < 13; t++) {
        int mb = t*64;
        __syncthreads();
        {   // ks [d][key] + vs [key][d] fill (zero out-of-range keys)
            int kr = tid >> 2, dc = (tid & 3)*8;
            bool ok = (mb + kr) < NK;
            int mr = ok ? (mb + kr) : 0;
            const float* kp = kg + mr*HD + dc;
            float4 a0 = *(const float4*)kp, a1 = *(const float4*)(kp+4);
            if (!ok) { a0 = make_float4(0,0,0,0); a1 = a0; }
            ks[(dc+0)*68+kr]=tf32c(a0.x); ks[(dc+1)*68+kr]=tf32c(a0.y);
            ks[(dc+2)*68+kr]=tf32c(a0.z); ks[(dc+3)*68+kr]=tf32c(a0.w);
            ks[(dc+4)*68+kr]=tf32c(a1.x); ks[(dc+5)*68+kr]=tf32c(a1.y);
            ks[(dc+6)*68+kr]=tf32c(a1.z); ks[(dc+7)*68+kr]=tf32c(a1.w);
            const float* vp = vg + mr*HD + dc;
            float4 w0 = *(const float4*)vp, w1 = *(const float4*)(vp+4);
            if (!ok) { w0 = make_float4(0,0,0,0); w1 = w0; }
            uint4 u0 = make_uint4(tf32c(w0.x), tf32c(w0.y), tf32c(w0.z), tf32c(w0.w));
            uint4 u1 = make_uint4(tf32c(w1.x), tf32c(w1.y), tf32c(w1.z), tf32c(w1.w));
            *(uint4*)(vs + kr*36 + dc)     = u0;
            *(uint4*)(vs + kr*36 + dc + 4) = u1;
        }
        __syncthreads();

        // ---- QK^T: S = 16x64 per warp ----
        float cs[8][4];
#pragma unroll
        for (int i = 0; i < 8; i++) { cs[i][0]=0.f; cs[i][1]=0.f; cs[i][2]=0.f; cs[i][3]=0.f; }
#pragma unroll
        for (int ks8 = 0; ks8 < 4; ks8++) {
            unsigned a[4];
            const unsigned* ak0 = qs + (ks8*8 + tg)*132 + w*16;
            const unsigned* ak4 = ak0 + 4*132;
            a[0] = ak0[gr]; a[1] = ak0[gr+8]; a[2] = ak4[gr]; a[3] = ak4[gr+8];
            const unsigned* bk0 = ks + (ks8*8 + tg)*68 + gr;
            const unsigned* bk4 = bk0 + 4*68;
#pragma unroll
            for (int nj = 0; nj < 8; nj++)
                mma8(cs[nj], a, bk0[nj*8], bk4[nj*8]);
        }

        // ---- bias + mask (inline from L2-resident pos_emb) ----
#pragma unroll
        for (int nj = 0; nj < 8; nj++) {
            int mk = mb + nj*8 + 2*tg;
            if (mk < NK) {
                int ki = mk/HH, kj = mk - (mk/HH)*HH;
                int ki2 = (kj == HH-1) ? ki+1 : ki;
                int kj2 = (kj == HH-1) ? 0 : kj+1;
                cs[nj][0] += __ldg(&pos_emb[(ki -qi0+55)*PEW + (kj -qj0+55)]);
                cs[nj][1] += __ldg(&pos_emb[(ki2-qi0+55)*PEW + (kj2-qj0+55)]);
                cs[nj][2] += __ldg(&pos_emb[(ki -qi1+55)*PEW + (kj -qj1+55)]);
                cs[nj][3] += __ldg(&pos_emb[(ki2-qi1+55)*PEW + (kj2-qj1+55)]);
            } else {
                cs[nj][0] = -1e30f; cs[nj][1] = -1e30f;
                cs[nj][2] = -1e30f; cs[nj][3] = -1e30f;
            }
        }

        // ---- online softmax (rows gr, gr+8; quad reduction) ----
#pragma unroll
        for (int h = 0; h < 2; h++) {
            float tm = -1e30f;
#pragma unroll
            for (int nj = 0; nj < 8; nj++) tm = fmaxf(tm, fmaxf(cs[nj][2*h], cs[nj][2*h+1]));
            tm = fmaxf(tm, __shfl_xor_sync(0xffffffffu, tm, 1));
            tm = fmaxf(tm, __shfl_xor_sync(0xffffffffu, tm, 2));
            float mnew = fmaxf(m_i[h], tm);
            float f = __expf(m_i[h] - mnew);
            m_i[h] = mnew;
            float sum = 0.f;
            unsigned* prow = psw + (gr + 8*h)*68 + 2*tg;
#pragma unroll
            for (int nj = 0; nj < 8; nj++) {
                float p0 = __expf(cs[nj][2*h]   - mnew);
                float p1 = __expf(cs[nj][2*h+1] - mnew);
                sum += p0 + p1;
                *(uint2*)(prow + nj*8) = make_uint2(tf32c(p0), tf32c(p1));
            }
            sum += __shfl_xor_sync(0xffffffffu, sum, 1);
            sum += __shfl_xor_sync(0xffffffffu, sum, 2);
            l_i[h] = l_i[h]*f + sum;
#pragma unroll
            for (int nj = 0; nj < 4; nj++) { co[nj][2*h] *= f; co[nj][2*h+1] *= f; }
        }
        __syncwarp();

        // ---- O += P @ V ----
#pragma unroll
        for (int kk8 = 0; kk8 < 8; kk8++) {
            unsigned a[4];
            const unsigned* p0 = psw + gr*68 + kk8*8 + tg;
            const unsigned* p1 = psw + (gr+8)*68 + kk8*8 + tg;
            a[0] = p0[0]; a[1] = p1[0]; a[2] = p0[4]; a[3] = p1[4];
            const unsigned* b0p = vs + (kk8*8 + tg)*36 + gr;
            const unsigned* b1p = b0p + 4*36;
#pragma unroll
            for (int nj = 0; nj < 4; nj++)
                mma8(co[nj], a, b0p[nj*8], b1p[nj*8]);
        }
        __syncwarp();
    }

    float inv0 = 1.f/l_i[0], inv1 = 1.f/l_i[1];
#pragma unroll
    for (int nj = 0; nj < 4; nj++) {
        int d = nj*8 + 2*tg;
        if (rown0 < NN)
            *(float2*)&g_ao[(b*NN + rown0)*CC + head*HD + d] =
                make_float2(co[nj][0]*inv0, co[nj][1]*inv0);
        if (rown1 < NN)
            *(float2*)&g_ao[(b*NN + rown1)*CC + head*HD + d] =
                make_float2(co[nj][2]*inv1, co[nj][3]*inv1);
    }
}

// ---------------- 6: output projection (register-prefetch double-buffered) -
__global__ __launch_bounds__(256) void gemm_proj_kernel(const float* __restrict__ pw,
                                                        const float* __restrict__ pb,
                                                        float* __restrict__ out) {
    __shared__ unsigned As[16*132];
    __shared__ unsigned Bs[16*68];
    int tid = threadIdx.x, lane = tid & 31, w = tid >> 5;
    int wm = w >> 1, wn = w & 1;
    int gr = lane >> 2, tg = lane & 3;
    ACC_INIT
    int b = blockIdx.z, n0 = blockIdx.x*128, c0 = blockIdx.y*64;
    int kk = tid >> 4, c4 = (tid & 15)*4;
    int am = tid >> 1, akc = (tid & 1)*8;
    int arow = n0 + am; if (arow > NN-1) arow = NN-1;
    const float* ap = g_ao + (b*NN + arow)*CC;

    float4 v0, v1, wv;
    v0 = *(const float4*)(ap + akc);
    v1 = *(const float4*)(ap + akc + 4);
    wv = *(const float4*)(pw + kk*CC + c0 + c4);

    for (int kt = 0; kt < 16; kt++) {
        {
            As[(akc+0)*132+am]=tf32c(v0.x); As[(akc+1)*132+am]=tf32c(v0.y);
            As[(akc+2)*132+am]=tf32c(v0.z); As[(akc+3)*132+am]=tf32c(v0.w);
            As[(akc+4)*132+am]=tf32c(v1.x); As[(akc+5)*132+am]=tf32c(v1.y);
            As[(akc+6)*132+am]=tf32c(v1.z); As[(akc+7)*132+am]=tf32c(v1.w);
            unsigned* e = Bs + kk*68 + c4;
            e[0]=tf32c(wv.x); e[1]=tf32c(wv.y); e[2]=tf32c(wv.z); e[3]=tf32c(wv.w);
        }
        __syncthreads();
        if (kt < 15) {
            int k0 = (kt+1)*16;
            v0 = *(const float4*)(ap + k0 + akc);
            v1 = *(const float4*)(ap + k0 + akc + 4);
            wv = *(const float4*)(pw + (k0+kk)*CC + c0 + c4);
        }
        mma_ktile(As, Bs, wm, wn, lane, acc);
        __syncthreads();
    }
#pragma unroll
    for (int nj = 0; nj < 4; nj++) {
        int c = c0 + wn*32 + nj*8 + 2*tg;
        float2 pbv = *(const float2*)(pb + c);
        float* o0 = out + (b*CC + c)*NN;
        float* o1 = o0 + NN;
#pragma unroll
        for (int mi = 0; mi < 2; mi++) {
            int n1 = n0 + wm*32 + mi*16 + gr;
            if (n1 < NN)   { o0[n1]   = acc[mi][nj][0] + pbv.x; o1[n1]   = acc[mi][nj][1] + pbv.y; }
            if (n1+8 < NN) { o0[n1+8] = acc[mi][nj][2] + pbv.x; o1[n1+8] = acc[mi][nj][3] + pbv.y; }
        }
    }
}

// ---------------- launch ----------------
extern "C" void kernel_launch(void* const* d_in, const int* in_sizes, int n_in,
                              void* d_out, int out_size) {
    const float* x    = (const float*)d_in[0];
    const float* Wq   = (const float*)d_in[1];
    const float* Wkv  = (const float*)d_in[2];
    const float* sr_w = (const float*)d_in[3];
    const float* sr_b = (const float*)d_in[4];
    const float* ln_g = (const float*)d_in[5];
    const float* ln_b = (const float*)d_in[6];
    const float* pos  = (const float*)d_in[7];
    const float* pw   = (const float*)d_in[8];
    const float* pb   = (const float*)d_in[9];
    float* out = (float*)d_out;

    static int smem_set = 0;
    if (!smem_set) {
        cudaFuncSetAttribute(attn_kernel, cudaFuncAttributeMaxDynamicSharedMemorySize, 69632);
        smem_set = 1;
    }

    wt_kernel        <<<1024, 256>>>(sr_w);
    gemm_qconv_kernel<<<dim3(25, 20, BB), 256>>>(x, Wq);
    ln_kernel        <<<BB*NK, 256>>>(ln_g, ln_b, sr_b);
    gemm_kv_kernel   <<<dim3(7, 16, BB), 256>>>(Wkv);
    kvcomb_kernel    <<<dim3(NK, BB), 512>>>();
    attn_kernel      <<<dim3(25, 8, BB), 256, 69632>>>(pos);
    gemm_proj_kernel <<<dim3(25, 4, BB), 256>>>(pw, pb, out);
}

// round 13
// speedup vs baseline: 1.9712x; 1.2648x over previous
#include <cuda_runtime.h>
#include <cuda_fp16.h>

#define BB 4
#define CC 256
#define HH 56
#define NN 3136
#define NHD 8
#define HD 32
#define NK 784
#define PEW 111

__device__ __forceinline__ unsigned tf32c(float f) {
    unsigned u; asm("cvt.rna.tf32.f32 %0, %1;" : "=r"(u) : "f"(f)); return u;
}
__device__ __forceinline__ void mma8(float c[4], const unsigned a[4], unsigned b0, unsigned b1) {
    asm("mma.sync.aligned.m16n8k8.row.col.f32.tf32.tf32.f32 "
        "{%0,%1,%2,%3},{%4,%5,%6,%7},{%8,%9},{%0,%1,%2,%3};"
        : "+f"(c[0]), "+f"(c[1]), "+f"(c[2]), "+f"(c[3])
        : "r"(a[0]), "r"(a[1]), "r"(a[2]), "r"(a[3]), "r"(b0), "r"(b1));
}
__device__ __forceinline__ void mma16h(float c[4], const unsigned a[4], unsigned b0, unsigned b1) {
    asm("mma.sync.aligned.m16n8k16.row.col.f32.f16.f16.f32 "
        "{%0,%1,%2,%3},{%4,%5,%6,%7},{%8,%9},{%0,%1,%2,%3};"
        : "+f"(c[0]), "+f"(c[1]), "+f"(c[2]), "+f"(c[3])
        : "r"(a[0]), "r"(a[1]), "r"(a[2]), "r"(a[3]), "r"(b0), "r"(b1));
}
__device__ __forceinline__ unsigned f2h2(float a, float b) {
    __half2 h = __floats2half2_rn(a, b);
    return *(unsigned*)&h;
}
__device__ __forceinline__ unsigned cvta_sh(const void* p) {
    return (unsigned)__cvta_generic_to_shared(p);
}

// ---------------- scratch ----------------
__device__ float    g_q   [BB*NHD*NN*HD];   // (b, head, n, d)
__device__ float    g_k   [BB*NHD*NK*HD];   // (b, head, m, d)
__device__ float    g_v   [BB*NHD*NK*HD];
__device__ float    g_xkvp[4*BB*NK*CC];     // conv partial sums (K-split)
__device__ float    g_xkv [BB*NK*CC];       // LN output
__device__ float    g_kvp [2*BB*NK*512];    // kv partial sums (K-split x2)
__device__ float    g_ao  [BB*NN*CC];       // (b, n, head*32+d)
__device__ unsigned g_wt  [1024*CC];        // conv weight transposed tf32

// ---------------- prep ----------------
__global__ void wt_kernel(const float* __restrict__ sr_w) {
    g_wt[blockIdx.x*CC + threadIdx.x] = tf32c(sr_w[threadIdx.x*1024 + blockIdx.x]);
}

// ---- shared mma core: block 128(M)x64(N), ktile 16; As[16][132], Bs[16][68] ----
__device__ __forceinline__ void mma_ktile(const unsigned* As, const unsigned* Bs,
                                          int wm, int wn, int lane, float acc[2][4][4]) {
    int gr = lane >> 2, gc = lane & 3;
#pragma unroll
    for (int ks = 0; ks < 2; ks++) {
        unsigned a[2][4];
        const unsigned* ak0 = As + (ks*8 + gc)*132 + wm*32;
        const unsigned* ak4 = ak0 + 4*132;
#pragma unroll
        for (int mi = 0; mi < 2; mi++) {
            int r = mi*16 + gr;
            a[mi][0] = ak0[r]; a[mi][1] = ak0[r+8];
            a[mi][2] = ak4[r]; a[mi][3] = ak4[r+8];
        }
        const unsigned* bk0 = Bs + (ks*8 + gc)*68 + wn*32 + gr;
        const unsigned* bk4 = bk0 + 4*68;
#pragma unroll
        for (int nj = 0; nj < 4; nj++) {
            unsigned b0 = bk0[nj*8], b1 = bk4[nj*8];
            mma8(acc[0][nj], a[0], b0, b1);
            mma8(acc[1][nj], a[1], b0, b1);
        }
    }
}

#define ACC_INIT                                                         \
    float acc[2][4][4];                                                  \
    _Pragma("unroll") for (int zi = 0; zi < 2; zi++)                     \
    _Pragma("unroll") for (int zj = 0; zj < 4; zj++)                     \
    _Pragma("unroll") for (int zk = 0; zk < 4; zk++) acc[zi][zj][zk] = 0.f;

// ---------------- 1+2 fused: Q projection || SR conv (K-split x4) ----------
__global__ __launch_bounds__(256) void gemm_qconv_kernel(const float* __restrict__ x,
                                                         const float* __restrict__ Wq) {
    __shared__ unsigned As[16*132];
    __shared__ unsigned Bs[16*68];
    int tid = threadIdx.x, lane = tid & 31, w = tid >> 5;
    int wm = w >> 1, wn = w & 1;
    int gr = lane >> 2, tg = lane & 3;
    int b = blockIdx.z;

    if (blockIdx.y < 4) {
        ACC_INIT
        int n0 = blockIdx.x*128, c0 = blockIdx.y*64;
        int kk = tid >> 4, m8 = (tid & 15)*8, c4 = (tid & 15)*4;
        bool fok = (n0 + m8) < NN;
        const float* xb = x + b*CC*NN;

        float4 v0 = make_float4(0,0,0,0), v1 = v0, wv;
        if (fok) { const float* s = xb + kk*NN + n0 + m8;
                   v0 = *(const float4*)s; v1 = *(const float4*)(s+4); }
        wv = *(const float4*)(Wq + kk*CC + c0 + c4);

        for (int kt = 0; kt < 16; kt++) {
            {
                unsigned* d = As + kk*132 + m8;
                d[0]=tf32c(v0.x); d[1]=tf32c(v0.y); d[2]=tf32c(v0.z); d[3]=tf32c(v0.w);
                d[4]=tf32c(v1.x); d[5]=tf32c(v1.y); d[6]=tf32c(v1.z); d[7]=tf32c(v1.w);
                unsigned* e = Bs + kk*68 + c4;
                e[0]=tf32c(wv.x); e[1]=tf32c(wv.y); e[2]=tf32c(wv.z); e[3]=tf32c(wv.w);
            }
            __syncthreads();
            if (kt < 15) {
                int kg = (kt+1)*16 + kk;
                if (fok) { const float* s = xb + kg*NN + n0 + m8;
                           v0 = *(const float4*)s; v1 = *(const float4*)(s+4); }
                wv = *(const float4*)(Wq + kg*CC + c0 + c4);
            }
            mma_ktile(As, Bs, wm, wn, lane, acc);
            __syncthreads();
        }
#pragma unroll
        for (int nj = 0; nj < 4; nj++) {
            int c = c0 + wn*32 + nj*8 + 2*tg;
            int head = c >> 5, d = c & 31;
            float* qb = g_q + (b*NHD + head)*NN*HD + d;
#pragma unroll
            for (int mi = 0; mi < 2; mi++) {
                int n1 = n0 + wm*32 + mi*16 + gr;
                if (n1 < NN)   *(float2*)(qb + n1*HD)     = make_float2(acc[mi][nj][0], acc[mi][nj][1]);
                if (n1+8 < NN) *(float2*)(qb + (n1+8)*HD) = make_float2(acc[mi][nj][2], acc[mi][nj][3]);
            }
        }
    } else {
        if (blockIdx.x >= 7) return;
        ACC_INIT
        int yy = blockIdx.y - 4;
        int part = yy >> 2;
        int o0 = (yy & 3) * 64;
        int m0 = blockIdx.x * 128;
        int kk = tid >> 4, m8 = (tid & 15)*8, c4 = (tid & 15)*4;
        bool fok = (m0 + m8) < NK;
        const float* xb = x + b*CC*NN;
        int sb[8];
#pragma unroll
        for (int c = 0; c < 8; c++) {
            int m = fok ? (m0 + m8 + c) : 0;
            int r = m / 28;
            sb[c] = (2*r)*HH + 2*(m - r*28);
        }
        int kbase = part*256;

        float va[8]; uint4 vb4;
        {
            int kg = kbase + kk;
            int ic = kg >> 2, kh = (kg >> 1) & 1, kw = kg & 1;
            const float* s = xb + ic*NN + kh*HH + kw;
#pragma unroll
            for (int c = 0; c < 8; c++) va[c] = fok ? s[sb[c]] : 0.f;
            vb4 = *(const uint4*)(g_wt + kg*CC + o0 + c4);
        }
        for (int kt = 0; kt < 16; kt++) {
            unsigned* d = As + kk*132 + m8;
#pragma unroll
            for (int c = 0; c < 8; c++) d[c] = tf32c(va[c]);
            *(uint4*)(Bs + kk*68 + c4) = vb4;
            __syncthreads();
            if (kt < 15) {
                int kg = kbase + (kt+1)*16 + kk;
                int ic = kg >> 2, kh = (kg >> 1) & 1, kw = kg & 1;
                const float* s = xb + ic*NN + kh*HH + kw;
#pragma unroll
                for (int c = 0; c < 8; c++) va[c] = fok ? s[sb[c]] : 0.f;
                vb4 = *(const uint4*)(g_wt + kg*CC + o0 + c4);
            }
            mma_ktile(As, Bs, wm, wn, lane, acc);
            __syncthreads();
        }
        float* dstp = g_xkvp + part*(BB*NK*CC) + (b*NK)*CC;
#pragma unroll
        for (int nj = 0; nj < 4; nj++) {
            int c = o0 + wn*32 + nj*8 + 2*tg;
#pragma unroll
            for (int mi = 0; mi < 2; mi++) {
                int m1 = m0 + wm*32 + mi*16 + gr;
                if (m1 < NK)   *(float2*)(&dstp[m1*CC + c]) =
                    make_float2(acc[mi][nj][0], acc[mi][nj][1]);
                if (m1+8 < NK) *(float2*)(&dstp[(m1+8)*CC + c]) =
                    make_float2(acc[mi][nj][2], acc[mi][nj][3]);
            }
        }
    }
}

// ---------------- 3: LayerNorm (sums 4 conv partials + bias) ----------------
__global__ void ln_kernel(const float* __restrict__ gamma, const float* __restrict__ beta,
                          const float* __restrict__ sr_b) {
    int row = blockIdx.x, t = threadIdx.x;
    int idx = row*CC + t;
    const int stride = BB*NK*CC;
    float v = ((g_xkvp[idx] + g_xkvp[idx + stride]) +
               (g_xkvp[idx + 2*stride] + g_xkvp[idx + 3*stride])) + sr_b[t];
    float s = v, q = v*v;
#pragma unroll
    for (int m = 16; m >= 1; m >>= 1) {
        s += __shfl_xor_sync(0xffffffffu, s, m);
        q += __shfl_xor_sync(0xffffffffu, q, m);
    }
    __shared__ float r1[8], r2[8];
    if ((t & 31) == 0) { r1[t>>5] = s; r2[t>>5] = q; }
    __syncthreads();
    float tot = 0.f, tq = 0.f;
#pragma unroll
    for (int wv = 0; wv < 8; wv++) { tot += r1[wv]; tq += r2[wv]; }
    float mean = tot * (1.f/256.f);
    float var  = tq * (1.f/256.f) - mean*mean;
    float inv  = rsqrtf(var + 1e-5f);
    g_xkv[row*CC + t] = (v - mean)*inv*gamma[t] + beta[t];
}

// ---------------- 4: KV projection, K-split x2 -> partial buffers -----------
__global__ __launch_bounds__(256) void gemm_kv_kernel(const float* __restrict__ Wkv) {
    __shared__ unsigned As[16*132];
    __shared__ unsigned Bs[16*68];
    int tid = threadIdx.x, lane = tid & 31, w = tid >> 5;
    int wm = w >> 1, wn = w & 1;
    int gr = lane >> 2, tg = lane & 3;
    ACC_INIT
    int b = blockIdx.z, m0 = blockIdx.x*128;
    int part = blockIdx.y >> 3;
    int c0 = (blockIdx.y & 7)*64;
    int kk = tid >> 4, c4 = (tid & 15)*4;
    int am = tid >> 1, akc = (tid & 1)*8;
    int arow = m0 + am; if (arow > NK-1) arow = NK-1;
    const float* ap = g_xkv + (b*NK + arow)*CC + part*128;
    const float* wp = Wkv + part*128*512;

    float4 v0, v1, wv;
    v0 = *(const float4*)(ap + akc);
    v1 = *(const float4*)(ap + akc + 4);
    wv = *(const float4*)(wp + kk*512 + c0 + c4);

    for (int kt = 0; kt < 8; kt++) {
        {
            As[(akc+0)*132+am]=tf32c(v0.x); As[(akc+1)*132+am]=tf32c(v0.y);
            As[(akc+2)*132+am]=tf32c(v0.z); As[(akc+3)*132+am]=tf32c(v0.w);
            As[(akc+4)*132+am]=tf32c(v1.x); As[(akc+5)*132+am]=tf32c(v1.y);
            As[(akc+6)*132+am]=tf32c(v1.z); As[(akc+7)*132+am]=tf32c(v1.w);
            unsigned* e = Bs + kk*68 + c4;
            e[0]=tf32c(wv.x); e[1]=tf32c(wv.y); e[2]=tf32c(wv.z); e[3]=tf32c(wv.w);
        }
        __syncthreads();
        if (kt < 7) {
            int k0 = (kt+1)*16;
            v0 = *(const float4*)(ap + k0 + akc);
            v1 = *(const float4*)(ap + k0 + akc + 4);
            wv = *(const float4*)(wp + (k0+kk)*512 + c0 + c4);
        }
        mma_ktile(As, Bs, wm, wn, lane, acc);
        __syncthreads();
    }
    float* dstp = g_kvp + ((part*BB + b)*NK)*512;
#pragma unroll
    for (int nj = 0; nj < 4; nj++) {
        int c = c0 + wn*32 + nj*8 + 2*tg;
#pragma unroll
        for (int mi = 0; mi < 2; mi++) {
            int m1 = m0 + wm*32 + mi*16 + gr;
            if (m1 < NK)   *(float2*)(&dstp[m1*512 + c]) =
                make_float2(acc[mi][nj][0], acc[mi][nj][1]);
            if (m1+8 < NK) *(float2*)(&dstp[(m1+8)*512 + c]) =
                make_float2(acc[mi][nj][2], acc[mi][nj][3]);
        }
    }
}

// ---------------- 4b: combine kv partials + scatter to g_k/g_v --------------
__global__ void kvcomb_kernel() {
    int m = blockIdx.x, b = blockIdx.y, c = threadIdx.x;   // 512 threads
    int idx = (b*NK + m)*512 + c;
    float val = g_kvp[idx] + g_kvp[BB*NK*512 + idx];
    int d = c >> 4, head = (c >> 1) & 7, sel = c & 1;
    float* dst = sel ? g_v : g_k;
    dst[((b*NHD + head)*NK + m)*HD + d] = val;
}

// ---------------- 5: fused flash attention, fp16 mma (Br=128, Bc=64) ------
// smem halves: qsh[128][40], ksh[64][40], vsh[64][40], psh 8w x [16][72]
__global__ __launch_bounds__(256, 2) void attn_kernel(const float* __restrict__ pos_emb) {
    extern __shared__ __half smh[];
    __half* qsh = smh;            // 5120 halves
    __half* ksh = smh + 5120;     // 2560
    __half* vsh = smh + 7680;     // 2560
    __half* psh = smh + 10240;    // 9216
    int b = blockIdx.z, head = blockIdx.y, n0 = blockIdx.x*128;
    int tid = threadIdx.x, lane = tid & 31, w = tid >> 5;
    int gr = lane >> 2, tg = lane & 3;
    const float scale = 0.17677669529663687f;
    int bh = b*NHD + head;
    const float* qg = g_q + bh*NN*HD;
    const float* kg = g_k + bh*NK*HD;
    const float* vg = g_v + bh*NK*HD;

    {   // q fill: [n][d] half, scaled
        int r = tid >> 1, dcq = (tid & 1)*16;
        int n = n0 + r; if (n > NN-1) n = NN-1;
        const float* p = qg + n*HD + dcq;
        float4 u0 = *(const float4*)(p);
        float4 u1 = *(const float4*)(p+4);
        float4 u2 = *(const float4*)(p+8);
        float4 u3 = *(const float4*)(p+12);
        uint4 w0 = make_uint4(f2h2(u0.x*scale,u0.y*scale), f2h2(u0.z*scale,u0.w*scale),
                              f2h2(u1.x*scale,u1.y*scale), f2h2(u1.z*scale,u1.w*scale));
        uint4 w1 = make_uint4(f2h2(u2.x*scale,u2.y*scale), f2h2(u2.z*scale,u2.w*scale),
                              f2h2(u3.x*scale,u3.y*scale), f2h2(u3.z*scale,u3.w*scale));
        *(uint4*)(qsh + r*40 + dcq)     = w0;
        *(uint4*)(qsh + r*40 + dcq + 8) = w1;
    }
    __syncthreads();

    // hoisted Q fragments (constant across key tiles)
    unsigned qa[2][4];
    {
        const unsigned* qsu = (const unsigned*)qsh;
        int rw = (w*16 + gr)*20;
#pragma unroll
        for (int ks = 0; ks < 2; ks++) {
            qa[ks][0] = qsu[rw + ks*8 + tg];
            qa[ks][1] = qsu[rw + 160 + ks*8 + tg];
            qa[ks][2] = qsu[rw + ks*8 + tg + 4];
            qa[ks][3] = qsu[rw + 160 + ks*8 + tg + 4];
        }
    }

    int rown0 = n0 + w*16 + gr, rown1 = rown0 + 8;
    int nq0 = rown0 > NN-1 ? NN-1 : rown0;
    int nq1 = rown1 > NN-1 ? NN-1 : rown1;
    int qi0 = nq0/HH, qj0 = nq0 - qi0*HH;
    int qi1 = nq1/HH, qj1 = nq1 - qi1*HH;

    float m_i[2] = {-1e30f, -1e30f}, l_i[2] = {0.f, 0.f};
    float co[4][4];
#pragma unroll
    for (int i = 0; i < 4; i++) { co[i][0]=0.f; co[i][1]=0.f; co[i][2]=0.f; co[i][3]=0.f; }
    __half* psw = psh + w*1152;           // [16][72]
    unsigned vlbase = cvta_sh(vsh) + (lane & 15)*80;   // row base for ldmatrix

    for (int t = 0; t < 13; t++) {
        int mb = t*64;
        __syncthreads();
        {   // K/V fill: [key][d] half (zero out-of-range keys)
            int kr = tid >> 2, dc = (tid & 3)*8;
            bool ok = (mb + kr) < NK;
            int mr = ok ? (mb + kr) : 0;
            const float* kp = kg + mr*HD + dc;
            float4 a0 = *(const float4*)kp, a1 = *(const float4*)(kp+4);
            const float* vp = vg + mr*HD + dc;
            float4 w0 = *(const float4*)vp, w1 = *(const float4*)(vp+4);
            uint4 kw = make_uint4(f2h2(a0.x,a0.y), f2h2(a0.z,a0.w),
                                  f2h2(a1.x,a1.y), f2h2(a1.z,a1.w));
            uint4 vw = make_uint4(f2h2(w0.x,w0.y), f2h2(w0.z,w0.w),
                                  f2h2(w1.x,w1.y), f2h2(w1.z,w1.w));
            if (!ok) { kw = make_uint4(0,0,0,0); vw = kw; }
            *(uint4*)(ksh + kr*40 + dc) = kw;
            *(uint4*)(vsh + kr*40 + dc) = vw;
        }
        __syncthreads();

        // ---- QK^T: S = 16x64 per warp (fp16, k16) ----
        float cs[8][4];
#pragma unroll
        for (int i = 0; i < 8; i++) { cs[i][0]=0.f; cs[i][1]=0.f; cs[i][2]=0.f; cs[i][3]=0.f; }
        {
            const unsigned* ksu = (const unsigned*)ksh;
#pragma unroll
            for (int nj = 0; nj < 8; nj++) {
                int bw = (nj*8 + gr)*20;
#pragma unroll
                for (int ks = 0; ks < 2; ks++) {
                    unsigned b0 = ksu[bw + ks*8 + tg];
                    unsigned b1 = ksu[bw + ks*8 + tg + 4];
                    mma16h(cs[nj], qa[ks], b0, b1);
                }
            }
        }

        // ---- bias + mask (fp32, inline from L2-resident pos_emb) ----
#pragma unroll
        for (int nj = 0; nj < 8; nj++) {
            int mk = mb + nj*8 + 2*tg;
            if (mk < NK) {
                int ki = mk/HH, kj = mk - (mk/HH)*HH;
                int ki2 = (kj == HH-1) ? ki+1 : ki;
                int kj2 = (kj == HH-1) ? 0 : kj+1;
                cs[nj][0] += __ldg(&pos_emb[(ki -qi0+55)*PEW + (kj -qj0+55)]);
                cs[nj][1] += __ldg(&pos_emb[(ki2-qi0+55)*PEW + (kj2-qj0+55)]);
                cs[nj][2] += __ldg(&pos_emb[(ki -qi1+55)*PEW + (kj -qj1+55)]);
                cs[nj][3] += __ldg(&pos_emb[(ki2-qi1+55)*PEW + (kj2-qj1+55)]);
            } else {
                cs[nj][0] = -1e30f; cs[nj][1] = -1e30f;
                cs[nj][2] = -1e30f; cs[nj][3] = -1e30f;
            }
        }

        // ---- online softmax (rows gr, gr+8; quad reduction) ----
#pragma unroll
        for (int h = 0; h < 2; h++) {
            float tm = -1e30f;
#pragma unroll
            for (int nj = 0; nj < 8; nj++) tm = fmaxf(tm, fmaxf(cs[nj][2*h], cs[nj][2*h+1]));
            tm = fmaxf(tm, __shfl_xor_sync(0xffffffffu, tm, 1));
            tm = fmaxf(tm, __shfl_xor_sync(0xffffffffu, tm, 2));
            float mnew = fmaxf(m_i[h], tm);
            float f = __expf(m_i[h] - mnew);
            m_i[h] = mnew;
            float sum = 0.f;
            __half* prow = psw + (gr + 8*h)*72 + 2*tg;
#pragma unroll
            for (int nj = 0; nj < 8; nj++) {
                float p0 = __expf(cs[nj][2*h]   - mnew);
                float p1 = __expf(cs[nj][2*h+1] - mnew);
                sum += p0 + p1;
                *(unsigned*)(prow + nj*8) = f2h2(p0, p1);
            }
            sum += __shfl_xor_sync(0xffffffffu, sum, 1);
            sum += __shfl_xor_sync(0xffffffffu, sum, 2);
            l_i[h] = l_i[h]*f + sum;
#pragma unroll
            for (int nj = 0; nj < 4; nj++) { co[nj][2*h] *= f; co[nj][2*h+1] *= f; }
        }
        __syncwarp();

        // ---- O += P @ V (fp16, ldmatrix.trans for V) ----
        {
            const unsigned* psu = (const unsigned*)psw;
#pragma unroll
            for (int ks8 = 0; ks8 < 4; ks8++) {
                unsigned pa[4];
                pa[0] = psu[gr*36 + ks8*8 + tg];
                pa[1] = psu[(gr+8)*36 + ks8*8 + tg];
                pa[2] = psu[gr*36 + ks8*8 + tg + 4];
                pa[3] = psu[(gr+8)*36 + ks8*8 + tg + 4];
#pragma unroll
                for (int nj = 0; nj < 4; nj++) {
                    unsigned vb0, vb1;
                    unsigned addr = vlbase + ks8*1280 + nj*16;
                    asm volatile("ldmatrix.sync.aligned.m8n8.x2.trans.shared.b16 {%0,%1}, [%2];"
                                 : "=r"(vb0), "=r"(vb1) : "r"(addr));
                    mma16h(co[nj], pa, vb0, vb1);
                }
            }
        }
        __syncwarp();
    }

    float inv0 = 1.f/l_i[0], inv1 = 1.f/l_i[1];
#pragma unroll
    for (int nj = 0; nj < 4; nj++) {
        int d = nj*8 + 2*tg;
        if (rown0 < NN)
            *(float2*)&g_ao[(b*NN + rown0)*CC + head*HD + d] =
                make_float2(co[nj][0]*inv0, co[nj][1]*inv0);
        if (rown1 < NN)
            *(float2*)&g_ao[(b*NN + rown1)*CC + head*HD + d] =
                make_float2(co[nj][2]*inv1, co[nj][3]*inv1);
    }
}

// ---------------- 6: output projection (register-prefetch double-buffered) -
__global__ __launch_bounds__(256) void gemm_proj_kernel(const float* __restrict__ pw,
                                                        const float* __restrict__ pb,
                                                        float* __restrict__ out) {
    __shared__ unsigned As[16*132];
    __shared__ unsigned Bs[16*68];
    int tid = threadIdx.x, lane = tid & 31, w = tid >> 5;
    int wm = w >> 1, wn = w & 1;
    int gr = lane >> 2, tg = lane & 3;
    ACC_INIT
    int b = blockIdx.z, n0 = blockIdx.x*128, c0 = blockIdx.y*64;
    int kk = tid >> 4, c4 = (tid & 15)*4;
    int am = tid >> 1, akc = (tid & 1)*8;
    int arow = n0 + am; if (arow > NN-1) arow = NN-1;
    const float* ap = g_ao + (b*NN + arow)*CC;

    float4 v0, v1, wv;
    v0 = *(const float4*)(ap + akc);
    v1 = *(const float4*)(ap + akc + 4);
    wv = *(const float4*)(pw + kk*CC + c0 + c4);

    for (int kt = 0; kt < 16; kt++) {
        {
            As[(akc+0)*132+am]=tf32c(v0.x); As[(akc+1)*132+am]=tf32c(v0.y);
            As[(akc+2)*132+am]=tf32c(v0.z); As[(akc+3)*132+am]=tf32c(v0.w);
            As[(akc+4)*132+am]=tf32c(v1.x); As[(akc+5)*132+am]=tf32c(v1.y);
            As[(akc+6)*132+am]=tf32c(v1.z); As[(akc+7)*132+am]=tf32c(v1.w);
            unsigned* e = Bs + kk*68 + c4;
            e[0]=tf32c(wv.x); e[1]=tf32c(wv.y); e[2]=tf32c(wv.z); e[3]=tf32c(wv.w);
        }
        __syncthreads();
        if (kt < 15) {
            int k0 = (kt+1)*16;
            v0 = *(const float4*)(ap + k0 + akc);
            v1 = *(const float4*)(ap + k0 + akc + 4);
            wv = *(const float4*)(pw + (k0+kk)*CC + c0 + c4);
        }
        mma_ktile(As, Bs, wm, wn, lane, acc);
        __syncthreads();
    }
#pragma unroll
    for (int nj = 0; nj < 4; nj++) {
        int c = c0 + wn*32 + nj*8 + 2*tg;
        float2 pbv = *(const float2*)(pb + c);
        float* o0 = out + (b*CC + c)*NN;
        float* o1 = o0 + NN;
#pragma unroll
        for (int mi = 0; mi < 2; mi++) {
            int n1 = n0 + wm*32 + mi*16 + gr;
            if (n1 < NN)   { o0[n1]   = acc[mi][nj][0] + pbv.x; o1[n1]   = acc[mi][nj][1] + pbv.y; }
            if (n1+8 < NN) { o0[n1+8] = acc[mi][nj][2] + pbv.x; o1[n1+8] = acc[mi][nj][3] + pbv.y; }
        }
    }
}

// ---------------- launch ----------------
extern "C" void kernel_launch(void* const* d_in, const int* in_sizes, int n_in,
                              void* d_out, int out_size) {
    const float* x    = (const float*)d_in[0];
    const float* Wq   = (const float*)d_in[1];
    const float* Wkv  = (const float*)d_in[2];
    const float* sr_w = (const float*)d_in[3];
    const float* sr_b = (const float*)d_in[4];
    const float* ln_g = (const float*)d_in[5];
    const float* ln_b = (const float*)d_in[6];
    const float* pos  = (const float*)d_in[7];
    const float* pw   = (const float*)d_in[8];
    const float* pb   = (const float*)d_in[9];
    float* out = (float*)d_out;

    wt_kernel        <<<1024, 256>>>(sr_w);
    gemm_qconv_kernel<<<dim3(25, 20, BB), 256>>>(x, Wq);
    ln_kernel        <<<BB*NK, 256>>>(ln_g, ln_b, sr_b);
    gemm_kv_kernel   <<<dim3(7, 16, BB), 256>>>(Wkv);
    kvcomb_kernel    <<<dim3(NK, BB), 512>>>();
    attn_kernel      <<<dim3(25, 8, BB), 256, 38912>>>(pos);
    gemm_proj_kernel <<<dim3(25, 4, BB), 256>>>(pw, pb, out);
}

// round 14
// speedup vs baseline: 2.4260x; 1.2307x over previous
#include <cuda_runtime.h>
#include <cuda_fp16.h>

#define BB 4
#define CC 256
#define HH 56
#define NN 3136
#define NHD 8
#define HD 32
#define NK 784
#define PEW 111

__device__ __forceinline__ void mma16h(float c[4], const unsigned a[4], unsigned b0, unsigned b1) {
    asm("mma.sync.aligned.m16n8k16.row.col.f32.f16.f16.f32 "
        "{%0,%1,%2,%3},{%4,%5,%6,%7},{%8,%9},{%0,%1,%2,%3};"
        : "+f"(c[0]), "+f"(c[1]), "+f"(c[2]), "+f"(c[3])
        : "r"(a[0]), "r"(a[1]), "r"(a[2]), "r"(a[3]), "r"(b0), "r"(b1));
}
__device__ __forceinline__ unsigned f2h2(float a, float b) {
    __half2 h = __floats2half2_rn(a, b);
    return *(unsigned*)&h;
}
__device__ __forceinline__ unsigned cvta_sh(const void* p) {
    return (unsigned)__cvta_generic_to_shared(p);
}

// ---------------- scratch ----------------
__device__ float    g_q   [BB*NHD*NN*HD];   // (b, head, n, d)
__device__ float    g_k   [BB*NHD*NK*HD];   // (b, head, m, d)
__device__ float    g_v   [BB*NHD*NK*HD];
__device__ float    g_xkvp[4*BB*NK*CC];     // conv partial sums (K-split)
__device__ float    g_xkv [BB*NK*CC];       // LN output
__device__ float    g_kvp [2*BB*NK*512];    // kv partial sums (K-split x2)
__device__ float    g_ao  [BB*NN*CC];       // (b, n, head*32+d)
__device__ __half   g_wth [1024*CC];        // conv weight transposed, half

// ---------------- prep ----------------
__global__ void wt_kernel(const float* __restrict__ sr_w) {
    g_wth[blockIdx.x*CC + threadIdx.x] = __float2half_rn(sr_w[threadIdx.x*1024 + blockIdx.x]);
}

// ---- fp16 mma core: block 128(M)x64(N), ktile 16 ----
// As: [128 m][24 halves pitch] (16 k used); Bs: [16 k][72 halves pitch] (64 c used)
#define AS_U32  (128*12)
#define BS_U32  (16*36)
__device__ __forceinline__ void mma_ktile_h(const unsigned* Asu, const unsigned bs_base,
                                            int wm, int wn, int lane, float acc[2][4][4]) {
    int gr = lane >> 2, tg = lane & 3;
    unsigned a[2][4];
#pragma unroll
    for (int mi = 0; mi < 2; mi++) {
        int r = wm*32 + mi*16 + gr;
        a[mi][0] = Asu[r*12 + tg];
        a[mi][1] = Asu[(r+8)*12 + tg];
        a[mi][2] = Asu[r*12 + tg + 4];
        a[mi][3] = Asu[(r+8)*12 + tg + 4];
    }
    unsigned bb = bs_base + (lane & 15)*144 + wn*64;
#pragma unroll
    for (int nj = 0; nj < 4; nj++) {
        unsigned b0, b1;
        asm volatile("ldmatrix.sync.aligned.m8n8.x2.trans.shared.b16 {%0,%1}, [%2];"
                     : "=r"(b0), "=r"(b1) : "r"(bb + nj*16));
        mma16h(acc[0][nj], a[0], b0, b1);
        mma16h(acc[1][nj], a[1], b0, b1);
    }
}

#define ACC_INIT                                                         \
    float acc[2][4][4];                                                  \
    _Pragma("unroll") for (int zi = 0; zi < 2; zi++)                     \
    _Pragma("unroll") for (int zj = 0; zj < 4; zj++)                     \
    _Pragma("unroll") for (int zk = 0; zk < 4; zk++) acc[zi][zj][zk] = 0.f;

// ---------------- 1+2 fused: Q projection || SR conv (K-split x4) ----------
__global__ __launch_bounds__(256) void gemm_qconv_kernel(const float* __restrict__ x,
                                                         const float* __restrict__ Wq) {
    __shared__ unsigned Asu[AS_U32];
    __shared__ unsigned Bsu[BS_U32];
    int tid = threadIdx.x, lane = tid & 31, w = tid >> 5;
    int wm = w >> 1, wn = w & 1;
    int gr = lane >> 2, tg = lane & 3;
    int b = blockIdx.z;
    unsigned bsb = cvta_sh(Bsu);
    int mrow = tid >> 1, kh = (tid & 1)*8;        // A fill mapping
    int kk = tid >> 4, c4 = (tid & 15)*4;         // B fill mapping

    if (blockIdx.y < 4) {
        // ---------- Q projection ----------
        ACC_INIT
        int n0 = blockIdx.x*128, c0 = blockIdx.y*64;
        int n = n0 + mrow; if (n > NN-1) n = NN-1;
        const float* xb = x + b*CC*NN + n;

        float va[8]; float4 wv;
        {
#pragma unroll
            for (int j = 0; j < 8; j++) va[j] = xb[(kh+j)*NN];
            wv = *(const float4*)(Wq + kk*CC + c0 + c4);
        }
        for (int kt = 0; kt < 16; kt++) {
            {
                uint4 aw = make_uint4(f2h2(va[0],va[1]), f2h2(va[2],va[3]),
                                      f2h2(va[4],va[5]), f2h2(va[6],va[7]));
                *(uint4*)(Asu + mrow*12 + (tid&1)*4) = aw;
                *(uint2*)(Bsu + kk*36 + c4/2) = make_uint2(f2h2(wv.x,wv.y), f2h2(wv.z,wv.w));
            }
            __syncthreads();
            if (kt < 15) {
                int k0 = (kt+1)*16;
#pragma unroll
                for (int j = 0; j < 8; j++) va[j] = xb[(k0+kh+j)*NN];
                wv = *(const float4*)(Wq + (k0+kk)*CC + c0 + c4);
            }
            mma_ktile_h(Asu, bsb, wm, wn, lane, acc);
            __syncthreads();
        }
#pragma unroll
        for (int nj = 0; nj < 4; nj++) {
            int c = c0 + wn*32 + nj*8 + 2*tg;
            int head = c >> 5, d = c & 31;
            float* qb = g_q + (b*NHD + head)*NN*HD + d;
#pragma unroll
            for (int mi = 0; mi < 2; mi++) {
                int n1 = n0 + wm*32 + mi*16 + gr;
                if (n1 < NN)   *(float2*)(qb + n1*HD)     = make_float2(acc[mi][nj][0], acc[mi][nj][1]);
                if (n1+8 < NN) *(float2*)(qb + (n1+8)*HD) = make_float2(acc[mi][nj][2], acc[mi][nj][3]);
            }
        }
    } else {
        // ---------- SR conv, K-split x4 ----------
        if (blockIdx.x >= 7) return;
        ACC_INIT
        int yy = blockIdx.y - 4;
        int part = yy >> 2;
        int o0 = (yy & 3) * 64;
        int m0 = blockIdx.x * 128;
        bool fok = (m0 + mrow) < NK;
        const float* xb = x + b*CC*NN;
        int sbase;
        {
            int m = fok ? (m0 + mrow) : 0;
            int r = m / 28;
            sbase = (2*r)*HH + 2*(m - r*28);
        }
        int kbase = part*256;

        float va[8]; uint2 vb2;
        {
#pragma unroll
            for (int j = 0; j < 8; j++) {
                int kg = kbase + kh + j;
                int ic = kg >> 2, khh = (kg >> 1) & 1, kw = kg & 1;
                va[j] = fok ? xb[ic*NN + sbase + khh*HH + kw] : 0.f;
            }
            vb2 = *(const uint2*)(g_wth + (kbase+kk)*CC + o0 + c4);
        }
        for (int kt = 0; kt < 16; kt++) {
            {
                uint4 aw = make_uint4(f2h2(va[0],va[1]), f2h2(va[2],va[3]),
                                      f2h2(va[4],va[5]), f2h2(va[6],va[7]));
                *(uint4*)(Asu + mrow*12 + (tid&1)*4) = aw;
                *(uint2*)(Bsu + kk*36 + c4/2) = vb2;
            }
            __syncthreads();
            if (kt < 15) {
                int k0 = kbase + (kt+1)*16;
#pragma unroll
                for (int j = 0; j < 8; j++) {
                    int kg = k0 + kh + j;
                    int ic = kg >> 2, khh = (kg >> 1) & 1, kw = kg & 1;
                    va[j] = fok ? xb[ic*NN + sbase + khh*HH + kw] : 0.f;
                }
                vb2 = *(const uint2*)(g_wth + (k0+kk)*CC + o0 + c4);
            }
            mma_ktile_h(Asu, bsb, wm, wn, lane, acc);
            __syncthreads();
        }
        float* dstp = g_xkvp + part*(BB*NK*CC) + (b*NK)*CC;
#pragma unroll
        for (int nj = 0; nj < 4; nj++) {
            int c = o0 + wn*32 + nj*8 + 2*tg;
#pragma unroll
            for (int mi = 0; mi < 2; mi++) {
                int m1 = m0 + wm*32 + mi*16 + gr;
                if (m1 < NK)   *(float2*)(&dstp[m1*CC + c]) =
                    make_float2(acc[mi][nj][0], acc[mi][nj][1]);
                if (m1+8 < NK) *(float2*)(&dstp[(m1+8)*CC + c]) =
                    make_float2(acc[mi][nj][2], acc[mi][nj][3]);
            }
        }
    }
}

// ---------------- 3: LayerNorm (sums 4 conv partials + bias) ----------------
__global__ void ln_kernel(const float* __restrict__ gamma, const float* __restrict__ beta,
                          const float* __restrict__ sr_b) {
    int row = blockIdx.x, t = threadIdx.x;
    int idx = row*CC + t;
    const int stride = BB*NK*CC;
    float v = ((g_xkvp[idx] + g_xkvp[idx + stride]) +
               (g_xkvp[idx + 2*stride] + g_xkvp[idx + 3*stride])) + sr_b[t];
    float s = v, q = v*v;
#pragma unroll
    for (int m = 16; m >= 1; m >>= 1) {
        s += __shfl_xor_sync(0xffffffffu, s, m);
        q += __shfl_xor_sync(0xffffffffu, q, m);
    }
    __shared__ float r1[8], r2[8];
    if ((t & 31) == 0) { r1[t>>5] = s; r2[t>>5] = q; }
    __syncthreads();
    float tot = 0.f, tq = 0.f;
#pragma unroll
    for (int wv = 0; wv < 8; wv++) { tot += r1[wv]; tq += r2[wv]; }
    float mean = tot * (1.f/256.f);
    float var  = tq * (1.f/256.f) - mean*mean;
    float inv  = rsqrtf(var + 1e-5f);
    g_xkv[row*CC + t] = (v - mean)*inv*gamma[t] + beta[t];
}

// ---------------- 4: KV projection, K-split x2 -> partial buffers -----------
__global__ __launch_bounds__(256) void gemm_kv_kernel(const float* __restrict__ Wkv) {
    __shared__ unsigned Asu[AS_U32];
    __shared__ unsigned Bsu[BS_U32];
    int tid = threadIdx.x, lane = tid & 31, w = tid >> 5;
    int wm = w >> 1, wn = w & 1;
    int gr = lane >> 2, tg = lane & 3;
    ACC_INIT
    unsigned bsb = cvta_sh(Bsu);
    int b = blockIdx.z, m0 = blockIdx.x*128;
    int part = blockIdx.y >> 3;
    int c0 = (blockIdx.y & 7)*64;
    int mrow = tid >> 1, kh = (tid & 1)*8;
    int kk = tid >> 4, c4 = (tid & 15)*4;
    int arow = m0 + mrow; if (arow > NK-1) arow = NK-1;
    const float* ap = g_xkv + (b*NK + arow)*CC + part*128 + kh;
    const float* wp = Wkv + part*128*512;

    float4 v0, v1, wv;
    v0 = *(const float4*)(ap);
    v1 = *(const float4*)(ap + 4);
    wv = *(const float4*)(wp + kk*512 + c0 + c4);

    for (int kt = 0; kt < 8; kt++) {
        {
            uint4 aw = make_uint4(f2h2(v0.x,v0.y), f2h2(v0.z,v0.w),
                                  f2h2(v1.x,v1.y), f2h2(v1.z,v1.w));
            *(uint4*)(Asu + mrow*12 + (tid&1)*4) = aw;
            *(uint2*)(Bsu + kk*36 + c4/2) = make_uint2(f2h2(wv.x,wv.y), f2h2(wv.z,wv.w));
        }
        __syncthreads();
        if (kt < 7) {
            int k0 = (kt+1)*16;
            v0 = *(const float4*)(ap + k0);
            v1 = *(const float4*)(ap + k0 + 4);
            wv = *(const float4*)(wp + (k0+kk)*512 + c0 + c4);
        }
        mma_ktile_h(Asu, bsb, wm, wn, lane, acc);
        __syncthreads();
    }
    float* dstp = g_kvp + ((part*BB + b)*NK)*512;
#pragma unroll
    for (int nj = 0; nj < 4; nj++) {
        int c = c0 + wn*32 + nj*8 + 2*tg;
#pragma unroll
        for (int mi = 0; mi < 2; mi++) {
            int m1 = m0 + wm*32 + mi*16 + gr;
            if (m1 < NK)   *(float2*)(&g_kvp[((part*BB + b)*NK + m1)*512 + c]) =
                make_float2(acc[mi][nj][0], acc[mi][nj][1]);
            if (m1+8 < NK) *(float2*)(&dstp[(m1+8)*512 + c]) =
                make_float2(acc[mi][nj][2], acc[mi][nj][3]);
        }
    }
}

// ---------------- 4b: combine kv partials + scatter to g_k/g_v --------------
__global__ void kvcomb_kernel() {
    int m = blockIdx.x, b = blockIdx.y, c = threadIdx.x;   // 512 threads
    int idx = (b*NK + m)*512 + c;
    float val = g_kvp[idx] + g_kvp[BB*NK*512 + idx];
    int d = c >> 4, head = (c >> 1) & 7, sel = c & 1;
    float* dst = sel ? g_v : g_k;
    dst[((b*NHD + head)*NK + m)*HD + d] = val;
}

// ---------------- 5: fused flash attention, fp16 mma (Br=128, Bc=64) ------
__global__ __launch_bounds__(256, 2) void attn_kernel(const float* __restrict__ pos_emb) {
    extern __shared__ __half smh[];
    __half* qsh = smh;            // 5120 halves
    __half* ksh = smh + 5120;     // 2560
    __half* vsh = smh + 7680;     // 2560
    __half* psh = smh + 10240;    // 9216
    int b = blockIdx.z, head = blockIdx.y, n0 = blockIdx.x*128;
    int tid = threadIdx.x, lane = tid & 31, w = tid >> 5;
    int gr = lane >> 2, tg = lane & 3;
    const float scale = 0.17677669529663687f;
    int bh = b*NHD + head;
    const float* qg = g_q + bh*NN*HD;
    const float* kg = g_k + bh*NK*HD;
    const float* vg = g_v + bh*NK*HD;

    {   // q fill: [n][d] half, scaled
        int r = tid >> 1, dcq = (tid & 1)*16;
        int n = n0 + r; if (n > NN-1) n = NN-1;
        const float* p = qg + n*HD + dcq;
        float4 u0 = *(const float4*)(p);
        float4 u1 = *(const float4*)(p+4);
        float4 u2 = *(const float4*)(p+8);
        float4 u3 = *(const float4*)(p+12);
        uint4 w0 = make_uint4(f2h2(u0.x*scale,u0.y*scale), f2h2(u0.z*scale,u0.w*scale),
                              f2h2(u1.x*scale,u1.y*scale), f2h2(u1.z*scale,u1.w*scale));
        uint4 w1 = make_uint4(f2h2(u2.x*scale,u2.y*scale), f2h2(u2.z*scale,u2.w*scale),
                              f2h2(u3.x*scale,u3.y*scale), f2h2(u3.z*scale,u3.w*scale));
        *(uint4*)(qsh + r*40 + dcq)     = w0;
        *(uint4*)(qsh + r*40 + dcq + 8) = w1;
    }
    __syncthreads();

    unsigned qa[2][4];
    {
        const unsigned* qsu = (const unsigned*)qsh;
        int rw = (w*16 + gr)*20;
#pragma unroll
        for (int ks = 0; ks < 2; ks++) {
            qa[ks][0] = qsu[rw + ks*8 + tg];
            qa[ks][1] = qsu[rw + 160 + ks*8 + tg];
            qa[ks][2] = qsu[rw + ks*8 + tg + 4];
            qa[ks][3] = qsu[rw + 160 + ks*8 + tg + 4];
        }
    }

    int rown0 = n0 + w*16 + gr, rown1 = rown0 + 8;
    int nq0 = rown0 > NN-1 ? NN-1 : rown0;
    int nq1 = rown1 > NN-1 ? NN-1 : rown1;
    int qi0 = nq0/HH, qj0 = nq0 - qi0*HH;
    int qi1 = nq1/HH, qj1 = nq1 - qi1*HH;

    float m_i[2] = {-1e30f, -1e30f}, l_i[2] = {0.f, 0.f};
    float co[4][4];
#pragma unroll
    for (int i = 0; i < 4; i++) { co[i][0]=0.f; co[i][1]=0.f; co[i][2]=0.f; co[i][3]=0.f; }
    __half* psw = psh + w*1152;
    unsigned vlbase = cvta_sh(vsh) + (lane & 15)*80;

    for (int t = 0; t < 13; t++) {
        int mb = t*64;
        __syncthreads();
        {
            int kr = tid >> 2, dc = (tid & 3)*8;
            bool ok = (mb + kr) < NK;
            int mr = ok ? (mb + kr) : 0;
            const float* kp = kg + mr*HD + dc;
            float4 a0 = *(const float4*)kp, a1 = *(const float4*)(kp+4);
            const float* vp = vg + mr*HD + dc;
            float4 w0 = *(const float4*)vp, w1 = *(const float4*)(vp+4);
            uint4 kw = make_uint4(f2h2(a0.x,a0.y), f2h2(a0.z,a0.w),
                                  f2h2(a1.x,a1.y), f2h2(a1.z,a1.w));
            uint4 vw = make_uint4(f2h2(w0.x,w0.y), f2h2(w0.z,w0.w),
                                  f2h2(w1.x,w1.y), f2h2(w1.z,w1.w));
            if (!ok) { kw = make_uint4(0,0,0,0); vw = kw; }
            *(uint4*)(ksh + kr*40 + dc) = kw;
            *(uint4*)(vsh + kr*40 + dc) = vw;
        }
        __syncthreads();

        float cs[8][4];
#pragma unroll
        for (int i = 0; i < 8; i++) { cs[i][0]=0.f; cs[i][1]=0.f; cs[i][2]=0.f; cs[i][3]=0.f; }
        {
            const unsigned* ksu = (const unsigned*)ksh;
#pragma unroll
            for (int nj = 0; nj < 8; nj++) {
                int bw = (nj*8 + gr)*20;
#pragma unroll
                for (int ks = 0; ks < 2; ks++) {
                    unsigned b0 = ksu[bw + ks*8 + tg];
                    unsigned b1 = ksu[bw + ks*8 + tg + 4];
                    mma16h(cs[nj], qa[ks], b0, b1);
                }
            }
        }

#pragma unroll
        for (int nj = 0; nj < 8; nj++) {
            int mk = mb + nj*8 + 2*tg;
            if (mk < NK) {
                int ki = mk/HH, kj = mk - (mk/HH)*HH;
                int ki2 = (kj == HH-1) ? ki+1 : ki;
                int kj2 = (kj == HH-1) ? 0 : kj+1;
                cs[nj][0] += __ldg(&pos_emb[(ki -qi0+55)*PEW + (kj -qj0+55)]);
                cs[nj][1] += __ldg(&pos_emb[(ki2-qi0+55)*PEW + (kj2-qj0+55)]);
                cs[nj][2] += __ldg(&pos_emb[(ki -qi1+55)*PEW + (kj -qj1+55)]);
                cs[nj][3] += __ldg(&pos_emb[(ki2-qi1+55)*PEW + (kj2-qj1+55)]);
            } else {
                cs[nj][0] = -1e30f; cs[nj][1] = -1e30f;
                cs[nj][2] = -1e30f; cs[nj][3] = -1e30f;
            }
        }

#pragma unroll
        for (int h = 0; h < 2; h++) {
            float tm = -1e30f;
#pragma unroll
            for (int nj = 0; nj < 8; nj++) tm = fmaxf(tm, fmaxf(cs[nj][2*h], cs[nj][2*h+1]));
            tm = fmaxf(tm, __shfl_xor_sync(0xffffffffu, tm, 1));
            tm = fmaxf(tm, __shfl_xor_sync(0xffffffffu, tm, 2));
            float mnew = fmaxf(m_i[h], tm);
            float f = __expf(m_i[h] - mnew);
            m_i[h] = mnew;
            float sum = 0.f;
            __half* prow = psw + (gr + 8*h)*72 + 2*tg;
#pragma unroll
            for (int nj = 0; nj < 8; nj++) {
                float p0 = __expf(cs[nj][2*h]   - mnew);
                float p1 = __expf(cs[nj][2*h+1] - mnew);
                sum += p0 + p1;
                *(unsigned*)(prow + nj*8) = f2h2(p0, p1);
            }
            sum += __shfl_xor_sync(0xffffffffu, sum, 1);
            sum += __shfl_xor_sync(0xffffffffu, sum, 2);
            l_i[h] = l_i[h]*f + sum;
#pragma unroll
            for (int nj = 0; nj < 4; nj++) { co[nj][2*h] *= f; co[nj][2*h+1] *= f; }
        }
        __syncwarp();

        {
            const unsigned* psu = (const unsigned*)psw;
#pragma unroll
            for (int ks8 = 0; ks8 < 4; ks8++) {
                unsigned pa[4];
                pa[0] = psu[gr*36 + ks8*8 + tg];
                pa[1] = psu[(gr+8)*36 + ks8*8 + tg];
                pa[2] = psu[gr*36 + ks8*8 + tg + 4];
                pa[3] = psu[(gr+8)*36 + ks8*8 + tg + 4];
#pragma unroll
                for (int nj = 0; nj < 4; nj++) {
                    unsigned vb0, vb1;
                    unsigned addr = vlbase + ks8*1280 + nj*16;
                    asm volatile("ldmatrix.sync.aligned.m8n8.x2.trans.shared.b16 {%0,%1}, [%2];"
                                 : "=r"(vb0), "=r"(vb1) : "r"(addr));
                    mma16h(co[nj], pa, vb0, vb1);
                }
            }
        }
        __syncwarp();
    }

    float inv0 = 1.f/l_i[0], inv1 = 1.f/l_i[1];
#pragma unroll
    for (int nj = 0; nj < 4; nj++) {
        int d = nj*8 + 2*tg;
        if (rown0 < NN)
            *(float2*)&g_ao[(b*NN + rown0)*CC + head*HD + d] =
                make_float2(co[nj][0]*inv0, co[nj][1]*inv0);
        if (rown1 < NN)
            *(float2*)&g_ao[(b*NN + rown1)*CC + head*HD + d] =
                make_float2(co[nj][2]*inv1, co[nj][3]*inv1);
    }
}

// ---------------- 6: output projection (fp16 core, prefetch) ---------------
__global__ __launch_bounds__(256) void gemm_proj_kernel(const float* __restrict__ pw,
                                                        const float* __restrict__ pb,
                                                        float* __restrict__ out) {
    __shared__ unsigned Asu[AS_U32];
    __shared__ unsigned Bsu[BS_U32];
    int tid = threadIdx.x, lane = tid & 31, w = tid >> 5;
    int wm = w >> 1, wn = w & 1;
    int gr = lane >> 2, tg = lane & 3;
    ACC_INIT
    unsigned bsb = cvta_sh(Bsu);
    int b = blockIdx.z, n0 = blockIdx.x*128, c0 = blockIdx.y*64;
    int mrow = tid >> 1, kh = (tid & 1)*8;
    int kk = tid >> 4, c4 = (tid & 15)*4;
    int arow = n0 + mrow; if (arow > NN-1) arow = NN-1;
    const float* ap = g_ao + (b*NN + arow)*CC + kh;

    float4 v0, v1, wv;
    v0 = *(const float4*)(ap);
    v1 = *(const float4*)(ap + 4);
    wv = *(const float4*)(pw + kk*CC + c0 + c4);

    for (int kt = 0; kt < 16; kt++) {
        {
            uint4 aw = make_uint4(f2h2(v0.x,v0.y), f2h2(v0.z,v0.w),
                                  f2h2(v1.x,v1.y), f2h2(v1.z,v1.w));
            *(uint4*)(Asu + mrow*12 + (tid&1)*4) = aw;
            *(uint2*)(Bsu + kk*36 + c4/2) = make_uint2(f2h2(wv.x,wv.y), f2h2(wv.z,wv.w));
        }
        __syncthreads();
        if (kt < 15) {
            int k0 = (kt+1)*16;
            v0 = *(const float4*)(ap + k0);
            v1 = *(const float4*)(ap + k0 + 4);
            wv = *(const float4*)(pw + (k0+kk)*CC + c0 + c4);
        }
        mma_ktile_h(Asu, bsb, wm, wn, lane, acc);
        __syncthreads();
    }
#pragma unroll
    for (int nj = 0; nj < 4; nj++) {
        int c = c0 + wn*32 + nj*8 + 2*tg;
        float2 pbv = *(const float2*)(pb + c);
        float* o0 = out + (b*CC + c)*NN;
        float* o1 = o0 + NN;
#pragma unroll
        for (int mi = 0; mi < 2; mi++) {
            int n1 = n0 + wm*32 + mi*16 + gr;
            if (n1 < NN)   { o0[n1]   = acc[mi][nj][0] + pbv.x; o1[n1]   = acc[mi][nj][1] + pbv.y; }
            if (n1+8 < NN) { o0[n1+8] = acc[mi][nj][2] + pbv.x; o1[n1+8] = acc[mi][nj][3] + pbv.y; }
        }
    }
}

// ---------------- launch ----------------
extern "C" void kernel_launch(void* const* d_in, const int* in_sizes, int n_in,
                              void* d_out, int out_size) {
    const float* x    = (const float*)d_in[0];
    const float* Wq   = (const float*)d_in[1];
    const float* Wkv  = (const float*)d_in[2];
    const float* sr_w = (const float*)d_in[3];
    const float* sr_b = (const float*)d_in[4];
    const float* ln_g = (const float*)d_in[5];
    const float* ln_b = (const float*)d_in[6];
    const float* pos  = (const float*)d_in[7];
    const float* pw   = (const float*)d_in[8];
    const float* pb   = (const float*)d_in[9];
    float* out = (float*)d_out;

    wt_kernel        <<<1024, 256>>>(sr_w);
    gemm_qconv_kernel<<<dim3(25, 20, BB), 256>>>(x, Wq);
    ln_kernel        <<<BB*NK, 256>>>(ln_g, ln_b, sr_b);
    gemm_kv_kernel   <<<dim3(7, 16, BB), 256>>>(Wkv);
    kvcomb_kernel    <<<dim3(NK, BB), 512>>>();
    attn_kernel      <<<dim3(25, 8, BB), 256, 38912>>>(pos);
    gemm_proj_kernel <<<dim3(25, 4, BB), 256>>>(pw, pb, out);
}

// round 15
// speedup vs baseline: 2.4690x; 1.0177x over previous
#include <cuda_runtime.h>
#include <cuda_fp16.h>

#define BB 4
#define CC 256
#define HH 56
#define NN 3136
#define NHD 8
#define HD 32
#define NK 784
#define PEW 111

__device__ __forceinline__ void mma16h(float c[4], const unsigned a[4], unsigned b0, unsigned b1) {
    asm("mma.sync.aligned.m16n8k16.row.col.f32.f16.f16.f32 "
        "{%0,%1,%2,%3},{%4,%5,%6,%7},{%8,%9},{%0,%1,%2,%3};"
        : "+f"(c[0]), "+f"(c[1]), "+f"(c[2]), "+f"(c[3])
        : "r"(a[0]), "r"(a[1]), "r"(a[2]), "r"(a[3]), "r"(b0), "r"(b1));
}
__device__ __forceinline__ unsigned f2h2(float a, float b) {
    __half2 h = __floats2half2_rn(a, b);
    return *(unsigned*)&h;
}
__device__ __forceinline__ unsigned cvta_sh(const void* p) {
    return (unsigned)__cvta_generic_to_shared(p);
}

// ---------------- scratch ----------------
__device__ float    g_q   [BB*NHD*NN*HD];   // (b, head, n, d)
__device__ float    g_k   [BB*NHD*NK*HD];   // (b, head, m, d)
__device__ float    g_v   [BB*NHD*NK*HD];
__device__ float    g_xkvp[4*BB*NK*CC];     // conv partial sums (K-split)
__device__ float    g_xkv [BB*NK*CC];       // LN output
__device__ float    g_kvp [2*BB*NK*512];    // kv partial sums (K-split x2)
__device__ float    g_ao  [BB*NN*CC];       // (b, n, head*32+d)
__device__ __half   g_wth [1024*CC];        // conv weight transposed, half

// ---------------- prep ----------------
__global__ void wt_kernel(const float* __restrict__ sr_w) {
    g_wth[blockIdx.x*CC + threadIdx.x] = __float2half_rn(sr_w[threadIdx.x*1024 + blockIdx.x]);
}

// ---- fp16 mma core: block 128(M)x64(N), ktile 16 ----
#define AS_U32  (128*12)
#define BS_U32  (16*36)
__device__ __forceinline__ void mma_ktile_h(const unsigned* Asu, const unsigned bs_base,
                                            int wm, int wn, int lane, float acc[2][4][4]) {
    int gr = lane >> 2, tg = lane & 3;
    unsigned a[2][4];
#pragma unroll
    for (int mi = 0; mi < 2; mi++) {
        int r = wm*32 + mi*16 + gr;
        a[mi][0] = Asu[r*12 + tg];
        a[mi][1] = Asu[(r+8)*12 + tg];
        a[mi][2] = Asu[r*12 + tg + 4];
        a[mi][3] = Asu[(r+8)*12 + tg + 4];
    }
    unsigned bb = bs_base + (lane & 15)*144 + wn*64;
#pragma unroll
    for (int nj = 0; nj < 4; nj++) {
        unsigned b0, b1;
        asm volatile("ldmatrix.sync.aligned.m8n8.x2.trans.shared.b16 {%0,%1}, [%2];"
                     : "=r"(b0), "=r"(b1) : "r"(bb + nj*16));
        mma16h(acc[0][nj], a[0], b0, b1);
        mma16h(acc[1][nj], a[1], b0, b1);
    }
}

#define ACC_INIT                                                         \
    float acc[2][4][4];                                                  \
    _Pragma("unroll") for (int zi = 0; zi < 2; zi++)                     \
    _Pragma("unroll") for (int zj = 0; zj < 4; zj++)                     \
    _Pragma("unroll") for (int zk = 0; zk < 4; zk++) acc[zi][zj][zk] = 0.f;

// ---------------- 1+2 fused: Q projection || SR conv (K-split x4) ----------
__global__ __launch_bounds__(256) void gemm_qconv_kernel(const float* __restrict__ x,
                                                         const float* __restrict__ Wq) {
    __shared__ unsigned Asu[AS_U32];
    __shared__ unsigned Bsu[BS_U32];
    int tid = threadIdx.x, lane = tid & 31, w = tid >> 5;
    int wm = w >> 1, wn = w & 1;
    int gr = lane >> 2, tg = lane & 3;
    int b = blockIdx.z;
    unsigned bsb = cvta_sh(Bsu);
    int mrow = tid >> 1, kh = (tid & 1)*8;
    int kk = tid >> 4, c4 = (tid & 15)*4;

    if (blockIdx.y < 4) {
        ACC_INIT
        int n0 = blockIdx.x*128, c0 = blockIdx.y*64;
        int n = n0 + mrow; if (n > NN-1) n = NN-1;
        const float* xb = x + b*CC*NN + n;

        float va[8]; float4 wv;
        {
#pragma unroll
            for (int j = 0; j < 8; j++) va[j] = xb[(kh+j)*NN];
            wv = *(const float4*)(Wq + kk*CC + c0 + c4);
        }
        for (int kt = 0; kt < 16; kt++) {
            {
                uint4 aw = make_uint4(f2h2(va[0],va[1]), f2h2(va[2],va[3]),
                                      f2h2(va[4],va[5]), f2h2(va[6],va[7]));
                *(uint4*)(Asu + mrow*12 + (tid&1)*4) = aw;
                *(uint2*)(Bsu + kk*36 + c4/2) = make_uint2(f2h2(wv.x,wv.y), f2h2(wv.z,wv.w));
            }
            __syncthreads();
            if (kt < 15) {
                int k0 = (kt+1)*16;
#pragma unroll
                for (int j = 0; j < 8; j++) va[j] = xb[(k0+kh+j)*NN];
                wv = *(const float4*)(Wq + (k0+kk)*CC + c0 + c4);
            }
            mma_ktile_h(Asu, bsb, wm, wn, lane, acc);
            __syncthreads();
        }
#pragma unroll
        for (int nj = 0; nj < 4; nj++) {
            int c = c0 + wn*32 + nj*8 + 2*tg;
            int head = c >> 5, d = c & 31;
            float* qb = g_q + (b*NHD + head)*NN*HD + d;
#pragma unroll
            for (int mi = 0; mi < 2; mi++) {
                int n1 = n0 + wm*32 + mi*16 + gr;
                if (n1 < NN)   *(float2*)(qb + n1*HD)     = make_float2(acc[mi][nj][0], acc[mi][nj][1]);
                if (n1+8 < NN) *(float2*)(qb + (n1+8)*HD) = make_float2(acc[mi][nj][2], acc[mi][nj][3]);
            }
        }
    } else {
        if (blockIdx.x >= 7) return;
        ACC_INIT
        int yy = blockIdx.y - 4;
        int part = yy >> 2;
        int o0 = (yy & 3) * 64;
        int m0 = blockIdx.x * 128;
        bool fok = (m0 + mrow) < NK;
        const float* xb = x + b*CC*NN;
        int sbase;
        {
            int m = fok ? (m0 + mrow) : 0;
            int r = m / 28;
            sbase = (2*r)*HH + 2*(m - r*28);
        }
        int kbase = part*256;

        float va[8]; uint2 vb2;
        {
#pragma unroll
            for (int j = 0; j < 8; j++) {
                int kg = kbase + kh + j;
                int ic = kg >> 2, khh = (kg >> 1) & 1, kw = kg & 1;
                va[j] = fok ? xb[ic*NN + sbase + khh*HH + kw] : 0.f;
            }
            vb2 = *(const uint2*)(g_wth + (kbase+kk)*CC + o0 + c4);
        }
        for (int kt = 0; kt < 16; kt++) {
            {
                uint4 aw = make_uint4(f2h2(va[0],va[1]), f2h2(va[2],va[3]),
                                      f2h2(va[4],va[5]), f2h2(va[6],va[7]));
                *(uint4*)(Asu + mrow*12 + (tid&1)*4) = aw;
                *(uint2*)(Bsu + kk*36 + c4/2) = vb2;
            }
            __syncthreads();
            if (kt < 15) {
                int k0 = kbase + (kt+1)*16;
#pragma unroll
                for (int j = 0; j < 8; j++) {
                    int kg = k0 + kh + j;
                    int ic = kg >> 2, khh = (kg >> 1) & 1, kw = kg & 1;
                    va[j] = fok ? xb[ic*NN + sbase + khh*HH + kw] : 0.f;
                }
                vb2 = *(const uint2*)(g_wth + (k0+kk)*CC + o0 + c4);
            }
            mma_ktile_h(Asu, bsb, wm, wn, lane, acc);
            __syncthreads();
        }
        float* dstp = g_xkvp + part*(BB*NK*CC) + (b*NK)*CC;
#pragma unroll
        for (int nj = 0; nj < 4; nj++) {
            int c = o0 + wn*32 + nj*8 + 2*tg;
#pragma unroll
            for (int mi = 0; mi < 2; mi++) {
                int m1 = m0 + wm*32 + mi*16 + gr;
                if (m1 < NK)   *(float2*)(&dstp[m1*CC + c]) =
                    make_float2(acc[mi][nj][0], acc[mi][nj][1]);
                if (m1+8 < NK) *(float2*)(&dstp[(m1+8)*CC + c]) =
                    make_float2(acc[mi][nj][2], acc[mi][nj][3]);
            }
        }
    }
}

// ---------------- 3: LayerNorm (sums 4 conv partials + bias) ----------------
__global__ void ln_kernel(const float* __restrict__ gamma, const float* __restrict__ beta,
                          const float* __restrict__ sr_b) {
    int row = blockIdx.x, t = threadIdx.x;
    int idx = row*CC + t;
    const int stride = BB*NK*CC;
    float v = ((g_xkvp[idx] + g_xkvp[idx + stride]) +
               (g_xkvp[idx + 2*stride] + g_xkvp[idx + 3*stride])) + sr_b[t];
    float s = v, q = v*v;
#pragma unroll
    for (int m = 16; m >= 1; m >>= 1) {
        s += __shfl_xor_sync(0xffffffffu, s, m);
        q += __shfl_xor_sync(0xffffffffu, q, m);
    }
    __shared__ float r1[8], r2[8];
    if ((t & 31) == 0) { r1[t>>5] = s; r2[t>>5] = q; }
    __syncthreads();
    float tot = 0.f, tq = 0.f;
#pragma unroll
    for (int wv = 0; wv < 8; wv++) { tot += r1[wv]; tq += r2[wv]; }
    float mean = tot * (1.f/256.f);
    float var  = tq * (1.f/256.f) - mean*mean;
    float inv  = rsqrtf(var + 1e-5f);
    g_xkv[row*CC + t] = (v - mean)*inv*gamma[t] + beta[t];
}

// ---------------- 4: KV projection, K-split x2 -> partial buffers -----------
__global__ __launch_bounds__(256) void gemm_kv_kernel(const float* __restrict__ Wkv) {
    __shared__ unsigned Asu[AS_U32];
    __shared__ unsigned Bsu[BS_U32];
    int tid = threadIdx.x, lane = tid & 31, w = tid >> 5;
    int wm = w >> 1, wn = w & 1;
    int gr = lane >> 2, tg = lane & 3;
    ACC_INIT
    unsigned bsb = cvta_sh(Bsu);
    int b = blockIdx.z, m0 = blockIdx.x*128;
    int part = blockIdx.y >> 3;
    int c0 = (blockIdx.y & 7)*64;
    int mrow = tid >> 1, kh = (tid & 1)*8;
    int kk = tid >> 4, c4 = (tid & 15)*4;
    int arow = m0 + mrow; if (arow > NK-1) arow = NK-1;
    const float* ap = g_xkv + (b*NK + arow)*CC + part*128 + kh;
    const float* wp = Wkv + part*128*512;

    float4 v0, v1, wv;
    v0 = *(const float4*)(ap);
    v1 = *(const float4*)(ap + 4);
    wv = *(const float4*)(wp + kk*512 + c0 + c4);

    for (int kt = 0; kt < 8; kt++) {
        {
            uint4 aw = make_uint4(f2h2(v0.x,v0.y), f2h2(v0.z,v0.w),
                                  f2h2(v1.x,v1.y), f2h2(v1.z,v1.w));
            *(uint4*)(Asu + mrow*12 + (tid&1)*4) = aw;
            *(uint2*)(Bsu + kk*36 + c4/2) = make_uint2(f2h2(wv.x,wv.y), f2h2(wv.z,wv.w));
        }
        __syncthreads();
        if (kt < 7) {
            int k0 = (kt+1)*16;
            v0 = *(const float4*)(ap + k0);
            v1 = *(const float4*)(ap + k0 + 4);
            wv = *(const float4*)(wp + (k0+kk)*512 + c0 + c4);
        }
        mma_ktile_h(Asu, bsb, wm, wn, lane, acc);
        __syncthreads();
    }
    float* dstp = g_kvp + ((part*BB + b)*NK)*512;
#pragma unroll
    for (int nj = 0; nj < 4; nj++) {
        int c = c0 + wn*32 + nj*8 + 2*tg;
#pragma unroll
        for (int mi = 0; mi < 2; mi++) {
            int m1 = m0 + wm*32 + mi*16 + gr;
            if (m1 < NK)   *(float2*)(&dstp[m1*512 + c]) =
                make_float2(acc[mi][nj][0], acc[mi][nj][1]);
            if (m1+8 < NK) *(float2*)(&dstp[(m1+8)*512 + c]) =
                make_float2(acc[mi][nj][2], acc[mi][nj][3]);
        }
    }
}

// ---------------- 4b: combine kv partials + scatter to g_k/g_v --------------
__global__ void kvcomb_kernel() {
    int m = blockIdx.x, b = blockIdx.y, c = threadIdx.x;   // 512 threads
    int idx = (b*NK + m)*512 + c;
    float val = g_kvp[idx] + g_kvp[BB*NK*512 + idx];
    int d = c >> 4, head = (c >> 1) & 7, sel = c & 1;
    float* dst = sel ? g_v : g_k;
    dst[((b*NHD + head)*NK + m)*HD + d] = val;
}

// ---------------- 5: fused flash attention, fp16 mma, ping-pong K/V --------
// smem halves: qsh[128][40]=5120, k0/v0/k1/v1 each [64][40]=2560, psh 9216
// total 24576 halves = 49152 bytes
__global__ __launch_bounds__(256, 3) void attn_kernel(const float* __restrict__ pos_emb) {
    extern __shared__ __half smh[];
    __half* qsh = smh;
    __half* kb0 = smh + 5120;
    __half* vb0 = smh + 7680;
    __half* kb1 = smh + 10240;
    __half* vb1 = smh + 12800;
    __half* psh = smh + 15360;
    int b = blockIdx.z, head = blockIdx.y, n0 = blockIdx.x*128;
    int tid = threadIdx.x, lane = tid & 31, w = tid >> 5;
    int gr = lane >> 2, tg = lane & 3;
    const float scale = 0.17677669529663687f;
    int bh = b*NHD + head;
    const float* qg = g_q + bh*NN*HD;
    const float* kg = g_k + bh*NK*HD;
    const float* vg = g_v + bh*NK*HD;

    {   // q fill: [n][d] half, scaled
        int r = tid >> 1, dcq = (tid & 1)*16;
        int n = n0 + r; if (n > NN-1) n = NN-1;
        const float* p = qg + n*HD + dcq;
        float4 u0 = *(const float4*)(p);
        float4 u1 = *(const float4*)(p+4);
        float4 u2 = *(const float4*)(p+8);
        float4 u3 = *(const float4*)(p+12);
        uint4 w0 = make_uint4(f2h2(u0.x*scale,u0.y*scale), f2h2(u0.z*scale,u0.w*scale),
                              f2h2(u1.x*scale,u1.y*scale), f2h2(u1.z*scale,u1.w*scale));
        uint4 w1 = make_uint4(f2h2(u2.x*scale,u2.y*scale), f2h2(u2.z*scale,u2.w*scale),
                              f2h2(u3.x*scale,u3.y*scale), f2h2(u3.z*scale,u3.w*scale));
        *(uint4*)(qsh + r*40 + dcq)     = w0;
        *(uint4*)(qsh + r*40 + dcq + 8) = w1;
    }

    int kr = tid >> 2, dck = (tid & 3)*8;
    auto fillKV = [&](int mbase, __half* kd, __half* vd) {
        bool ok = (mbase + kr) < NK;
        int mr = ok ? (mbase + kr) : 0;
        const float* kp = kg + mr*HD + dck;
        float4 a0 = *(const float4*)kp, a1 = *(const float4*)(kp+4);
        const float* vp = vg + mr*HD + dck;
        float4 w0 = *(const float4*)vp, w1 = *(const float4*)(vp+4);
        uint4 kw = make_uint4(f2h2(a0.x,a0.y), f2h2(a0.z,a0.w),
                              f2h2(a1.x,a1.y), f2h2(a1.z,a1.w));
        uint4 vw = make_uint4(f2h2(w0.x,w0.y), f2h2(w0.z,w0.w),
                              f2h2(w1.x,w1.y), f2h2(w1.z,w1.w));
        if (!ok) { kw = make_uint4(0,0,0,0); vw = kw; }
        *(uint4*)(kd + kr*40 + dck) = kw;
        *(uint4*)(vd + kr*40 + dck) = vw;
    };
    fillKV(0, kb0, vb0);
    __syncthreads();

    unsigned qa[2][4];
    {
        const unsigned* qsu = (const unsigned*)qsh;
        int rw = (w*16 + gr)*20;
#pragma unroll
        for (int ks = 0; ks < 2; ks++) {
            qa[ks][0] = qsu[rw + ks*8 + tg];
            qa[ks][1] = qsu[rw + 160 + ks*8 + tg];
            qa[ks][2] = qsu[rw + ks*8 + tg + 4];
            qa[ks][3] = qsu[rw + 160 + ks*8 + tg + 4];
        }
    }

    int rown0 = n0 + w*16 + gr, rown1 = rown0 + 8;
    int nq0 = rown0 > NN-1 ? NN-1 : rown0;
    int nq1 = rown1 > NN-1 ? NN-1 : rown1;
    int qi0 = nq0/HH, qj0 = nq0 - qi0*HH;
    int qi1 = nq1/HH, qj1 = nq1 - qi1*HH;

    float m_i[2] = {-1e30f, -1e30f}, l_i[2] = {0.f, 0.f};
    float co[4][4];
#pragma unroll
    for (int i = 0; i < 4; i++) { co[i][0]=0.f; co[i][1]=0.f; co[i][2]=0.f; co[i][3]=0.f; }
    __half* psw = psh + w*1152;

    for (int t = 0; t < 13; t++) {
        int mb = t*64;
        int cur = t & 1;
        __half* ksh = cur ? kb1 : kb0;
        __half* vsh = cur ? vb1 : vb0;
        if (t < 12) fillKV(mb + 64, cur ? kb0 : kb1, cur ? vb0 : vb1);

        // ---- QK^T ----
        float cs[8][4];
#pragma unroll
        for (int i = 0; i < 8; i++) { cs[i][0]=0.f; cs[i][1]=0.f; cs[i][2]=0.f; cs[i][3]=0.f; }
        {
            const unsigned* ksu = (const unsigned*)ksh;
#pragma unroll
            for (int nj = 0; nj < 8; nj++) {
                int bw = (nj*8 + gr)*20;
#pragma unroll
                for (int ks = 0; ks < 2; ks++) {
                    unsigned b0 = ksu[bw + ks*8 + tg];
                    unsigned b1 = ksu[bw + ks*8 + tg + 4];
                    mma16h(cs[nj], qa[ks], b0, b1);
                }
            }
        }

        // ---- bias + mask ----
#pragma unroll
        for (int nj = 0; nj < 8; nj++) {
            int mk = mb + nj*8 + 2*tg;
            if (mk < NK) {
                int ki = mk/HH, kj = mk - (mk/HH)*HH;
                int ki2 = (kj == HH-1) ? ki+1 : ki;
                int kj2 = (kj == HH-1) ? 0 : kj+1;
                cs[nj][0] += __ldg(&pos_emb[(ki -qi0+55)*PEW + (kj -qj0+55)]);
                cs[nj][1] += __ldg(&pos_emb[(ki2-qi0+55)*PEW + (kj2-qj0+55)]);
                cs[nj][2] += __ldg(&pos_emb[(ki -qi1+55)*PEW + (kj -qj1+55)]);
                cs[nj][3] += __ldg(&pos_emb[(ki2-qi1+55)*PEW + (kj2-qj1+55)]);
            } else {
                cs[nj][0] = -1e30f; cs[nj][1] = -1e30f;
                cs[nj][2] = -1e30f; cs[nj][3] = -1e30f;
            }
        }

        // ---- online softmax ----
#pragma unroll
        for (int h = 0; h < 2; h++) {
            float tm = -1e30f;
#pragma unroll
            for (int nj = 0; nj < 8; nj++) tm = fmaxf(tm, fmaxf(cs[nj][2*h], cs[nj][2*h+1]));
            tm = fmaxf(tm, __shfl_xor_sync(0xffffffffu, tm, 1));
            tm = fmaxf(tm, __shfl_xor_sync(0xffffffffu, tm, 2));
            float mnew = fmaxf(m_i[h], tm);
            float f = __expf(m_i[h] - mnew);
            m_i[h] = mnew;
            float sum = 0.f;
            __half* prow = psw + (gr + 8*h)*72 + 2*tg;
#pragma unroll
            for (int nj = 0; nj < 8; nj++) {
                float p0 = __expf(cs[nj][2*h]   - mnew);
                float p1 = __expf(cs[nj][2*h+1] - mnew);
                sum += p0 + p1;
                *(unsigned*)(prow + nj*8) = f2h2(p0, p1);
            }
            sum += __shfl_xor_sync(0xffffffffu, sum, 1);
            sum += __shfl_xor_sync(0xffffffffu, sum, 2);
            l_i[h] = l_i[h]*f + sum;
#pragma unroll
            for (int nj = 0; nj < 4; nj++) { co[nj][2*h] *= f; co[nj][2*h+1] *= f; }
        }
        __syncwarp();

        // ---- O += P @ V ----
        {
            const unsigned* psu = (const unsigned*)psw;
            unsigned vlbase = cvta_sh(vsh) + (lane & 15)*80;
#pragma unroll
            for (int ks8 = 0; ks8 < 4; ks8++) {
                unsigned pa[4];
                pa[0] = psu[gr*36 + ks8*8 + tg];
                pa[1] = psu[(gr+8)*36 + ks8*8 + tg];
                pa[2] = psu[gr*36 + ks8*8 + tg + 4];
                pa[3] = psu[(gr+8)*36 + ks8*8 + tg + 4];
#pragma unroll
                for (int nj = 0; nj < 4; nj++) {
                    unsigned vb0r, vb1r;
                    unsigned addr = vlbase + ks8*1280 + nj*16;
                    asm volatile("ldmatrix.sync.aligned.m8n8.x2.trans.shared.b16 {%0,%1}, [%2];"
                                 : "=r"(vb0r), "=r"(vb1r) : "r"(addr));
                    mma16h(co[nj], pa, vb0r, vb1r);
                }
            }
        }
        __syncthreads();
    }

    float inv0 = 1.f/l_i[0], inv1 = 1.f/l_i[1];
#pragma unroll
    for (int nj = 0; nj < 4; nj++) {
        int d = nj*8 + 2*tg;
        if (rown0 < NN)
            *(float2*)&g_ao[(b*NN + rown0)*CC + head*HD + d] =
                make_float2(co[nj][0]*inv0, co[nj][1]*inv0);
        if (rown1 < NN)
            *(float2*)&g_ao[(b*NN + rown1)*CC + head*HD + d] =
                make_float2(co[nj][2]*inv1, co[nj][3]*inv1);
    }
}

// ---------------- 6: output projection (fp16 core, prefetch) ---------------
__global__ __launch_bounds__(256) void gemm_proj_kernel(const float* __restrict__ pw,
                                                        const float* __restrict__ pb,
                                                        float* __restrict__ out) {
    __shared__ unsigned Asu[AS_U32];
    __shared__ unsigned Bsu[BS_U32];
    int tid = threadIdx.x, lane = tid & 31, w = tid >> 5;
    int wm = w >> 1, wn = w & 1;
    int gr = lane >> 2, tg = lane & 3;
    ACC_INIT
    unsigned bsb = cvta_sh(Bsu);
    int b = blockIdx.z, n0 = blockIdx.x*128, c0 = blockIdx.y*64;
    int mrow = tid >> 1, kh = (tid & 1)*8;
    int kk = tid >> 4, c4 = (tid & 15)*4;
    int arow = n0 + mrow; if (arow > NN-1) arow = NN-1;
    const float* ap = g_ao + (b*NN + arow)*CC + kh;

    float4 v0, v1, wv;
    v0 = *(const float4*)(ap);
    v1 = *(const float4*)(ap + 4);
    wv = *(const float4*)(pw + kk*CC + c0 + c4);

    for (int kt = 0; kt < 16; kt++) {
        {
            uint4 aw = make_uint4(f2h2(v0.x,v0.y), f2h2(v0.z,v0.w),
                                  f2h2(v1.x,v1.y), f2h2(v1.z,v1.w));
            *(uint4*)(Asu + mrow*12 + (tid&1)*4) = aw;
            *(uint2*)(Bsu + kk*36 + c4/2) = make_uint2(f2h2(wv.x,wv.y), f2h2(wv.z,wv.w));
        }
        __syncthreads();
        if (kt < 15) {
            int k0 = (kt+1)*16;
            v0 = *(const float4*)(ap + k0);
            v1 = *(const float4*)(ap + k0 + 4);
            wv = *(const float4*)(pw + (k0+kk)*CC + c0 + c4);
        }
        mma_ktile_h(Asu, bsb, wm, wn, lane, acc);
        __syncthreads();
    }
#pragma unroll
    for (int nj = 0; nj < 4; nj++) {
        int c = c0 + wn*32 + nj*8 + 2*tg;
        float2 pbv = *(const float2*)(pb + c);
        float* o0 = out + (b*CC + c)*NN;
        float* o1 = o0 + NN;
#pragma unroll
        for (int mi = 0; mi < 2; mi++) {
            int n1 = n0 + wm*32 + mi*16 + gr;
            if (n1 < NN)   { o0[n1]   = acc[mi][nj][0] + pbv.x; o1[n1]   = acc[mi][nj][1] + pbv.y; }
            if (n1+8 < NN) { o0[n1+8] = acc[mi][nj][2] + pbv.x; o1[n1+8] = acc[mi][nj][3] + pbv.y; }
        }
    }
}

// ---------------- launch ----------------
extern "C" void kernel_launch(void* const* d_in, const int* in_sizes, int n_in,
                              void* d_out, int out_size) {
    const float* x    = (const float*)d_in[0];
    const float* Wq   = (const float*)d_in[1];
    const float* Wkv  = (const float*)d_in[2];
    const float* sr_w = (const float*)d_in[3];
    const float* sr_b = (const float*)d_in[4];
    const float* ln_g = (const float*)d_in[5];
    const float* ln_b = (const float*)d_in[6];
    const float* pos  = (const float*)d_in[7];
    const float* pw   = (const float*)d_in[8];
    const float* pb   = (const float*)d_in[9];
    float* out = (float*)d_out;

    wt_kernel        <<<1024, 256>>>(sr_w);
    gemm_qconv_kernel<<<dim3(25, 20, BB), 256>>>(x, Wq);
    ln_kernel        <<<BB*NK, 256>>>(ln_g, ln_b, sr_b);
    gemm_kv_kernel   <<<dim3(7, 16, BB), 256>>>(Wkv);
    kvcomb_kernel    <<<dim3(NK, BB), 512>>>();
    attn_kernel      <<<dim3(25, 8, BB), 256, 49152>>>(pos);
    gemm_proj_kernel <<<dim3(25, 4, BB), 256>>>(pw, pb, out);
}

// round 16
// speedup vs baseline: 3.1145x; 1.2615x over previous
#include <cuda_runtime.h>
#include <cuda_fp16.h>

#define BB 4
#define CC 256
#define HH 56
#define NN 3136
#define NHD 8
#define HD 32
#define NK 784
#define PEW 111

__device__ __forceinline__ void mma16h(float c[4], const unsigned a[4], unsigned b0, unsigned b1) {
    asm("mma.sync.aligned.m16n8k16.row.col.f32.f16.f16.f32 "
        "{%0,%1,%2,%3},{%4,%5,%6,%7},{%8,%9},{%0,%1,%2,%3};"
        : "+f"(c[0]), "+f"(c[1]), "+f"(c[2]), "+f"(c[3])
        : "r"(a[0]), "r"(a[1]), "r"(a[2]), "r"(a[3]), "r"(b0), "r"(b1));
}
__device__ __forceinline__ unsigned f2h2(float a, float b) {
    __half2 h = __floats2half2_rn(a, b);
    return *(unsigned*)&h;
}
__device__ __forceinline__ unsigned cvta_sh(const void* p) {
    return (unsigned)__cvta_generic_to_shared(p);
}

// ---------------- scratch ----------------
__device__ float    g_q   [BB*NHD*NN*HD];
__device__ float    g_k   [BB*NHD*NK*HD];
__device__ float    g_v   [BB*NHD*NK*HD];
__device__ float    g_xkvp[4*BB*NK*CC];
__device__ float    g_xkv [BB*NK*CC];
__device__ float    g_kvp [2*BB*NK*512];
__device__ float    g_ao  [BB*NN*CC];
__device__ __half   g_wth [1024*CC];

// ---------------- prep ----------------
__global__ void wt_kernel(const float* __restrict__ sr_w) {
    g_wth[blockIdx.x*CC + threadIdx.x] = __float2half_rn(sr_w[threadIdx.x*1024 + blockIdx.x]);
}

// ---- fp16 mma core: block 128(M)x64(N), ktile 16 ----
#define AS_U32  (128*12)
#define BS_U32  (16*36)
__device__ __forceinline__ void mma_ktile_h(const unsigned* Asu, const unsigned bs_base,
                                            int wm, int wn, int lane, float acc[2][4][4]) {
    int gr = lane >> 2, tg = lane & 3;
    unsigned a[2][4];
#pragma unroll
    for (int mi = 0; mi < 2; mi++) {
        int r = wm*32 + mi*16 + gr;
        a[mi][0] = Asu[r*12 + tg];
        a[mi][1] = Asu[(r+8)*12 + tg];
        a[mi][2] = Asu[r*12 + tg + 4];
        a[mi][3] = Asu[(r+8)*12 + tg + 4];
    }
    unsigned bb = bs_base + (lane & 15)*144 + wn*64;
#pragma unroll
    for (int nj = 0; nj < 4; nj++) {
        unsigned b0, b1;
        asm volatile("ldmatrix.sync.aligned.m8n8.x2.trans.shared.b16 {%0,%1}, [%2];"
                     : "=r"(b0), "=r"(b1) : "r"(bb + nj*16));
        mma16h(acc[0][nj], a[0], b0, b1);
        mma16h(acc[1][nj], a[1], b0, b1);
    }
}

#define ACC_INIT                                                         \
    float acc[2][4][4];                                                  \
    _Pragma("unroll") for (int zi = 0; zi < 2; zi++)                     \
    _Pragma("unroll") for (int zj = 0; zj < 4; zj++)                     \
    _Pragma("unroll") for (int zk = 0; zk < 4; zk++) acc[zi][zj][zk] = 0.f;

// ---------------- 1+2 fused: Q projection || SR conv (K-split x4) ----------
__global__ __launch_bounds__(256) void gemm_qconv_kernel(const float* __restrict__ x,
                                                         const float* __restrict__ Wq) {
    __shared__ unsigned Asu[AS_U32];
    __shared__ unsigned Bsu[BS_U32];
    int tid = threadIdx.x, lane = tid & 31, w = tid >> 5;
    int wm = w >> 1, wn = w & 1;
    int gr = lane >> 2, tg = lane & 3;
    int b = blockIdx.z;
    unsigned bsb = cvta_sh(Bsu);
    int mrow = tid >> 1, kh = (tid & 1)*8;
    int kk = tid >> 4, c4 = (tid & 15)*4;

    if (blockIdx.y < 4) {
        ACC_INIT
        int n0 = blockIdx.x*128, c0 = blockIdx.y*64;
        int n = n0 + mrow; if (n > NN-1) n = NN-1;
        const float* xb = x + b*CC*NN + n;

        float va[8]; float4 wv;
        {
#pragma unroll
            for (int j = 0; j < 8; j++) va[j] = xb[(kh+j)*NN];
            wv = *(const float4*)(Wq + kk*CC + c0 + c4);
        }
        for (int kt = 0; kt < 16; kt++) {
            {
                uint4 aw = make_uint4(f2h2(va[0],va[1]), f2h2(va[2],va[3]),
                                      f2h2(va[4],va[5]), f2h2(va[6],va[7]));
                *(uint4*)(Asu + mrow*12 + (tid&1)*4) = aw;
                *(uint2*)(Bsu + kk*36 + c4/2) = make_uint2(f2h2(wv.x,wv.y), f2h2(wv.z,wv.w));
            }
            __syncthreads();
            if (kt < 15) {
                int k0 = (kt+1)*16;
#pragma unroll
                for (int j = 0; j < 8; j++) va[j] = xb[(k0+kh+j)*NN];
                wv = *(const float4*)(Wq + (k0+kk)*CC + c0 + c4);
            }
            mma_ktile_h(Asu, bsb, wm, wn, lane, acc);
            __syncthreads();
        }
#pragma unroll
        for (int nj = 0; nj < 4; nj++) {
            int c = c0 + wn*32 + nj*8 + 2*tg;
            int head = c >> 5, d = c & 31;
            float* qb = g_q + (b*NHD + head)*NN*HD + d;
#pragma unroll
            for (int mi = 0; mi < 2; mi++) {
                int n1 = n0 + wm*32 + mi*16 + gr;
                if (n1 < NN)   *(float2*)(qb + n1*HD)     = make_float2(acc[mi][nj][0], acc[mi][nj][1]);
                if (n1+8 < NN) *(float2*)(qb + (n1+8)*HD) = make_float2(acc[mi][nj][2], acc[mi][nj][3]);
            }
        }
    } else {
        if (blockIdx.x >= 7) return;
        ACC_INIT
        int yy = blockIdx.y - 4;
        int part = yy >> 2;
        int o0 = (yy & 3) * 64;
        int m0 = blockIdx.x * 128;
        bool fok = (m0 + mrow) < NK;
        const float* xb = x + b*CC*NN;
        int sbase;
        {
            int m = fok ? (m0 + mrow) : 0;
            int r = m / 28;
            sbase = (2*r)*HH + 2*(m - r*28);
        }
        int kbase = part*256;

        float va[8]; uint2 vb2;
        {
#pragma unroll
            for (int j = 0; j < 8; j++) {
                int kg = kbase + kh + j;
                int ic = kg >> 2, khh = (kg >> 1) & 1, kw = kg & 1;
                va[j] = fok ? xb[ic*NN + sbase + khh*HH + kw] : 0.f;
            }
            vb2 = *(const uint2*)(g_wth + (kbase+kk)*CC + o0 + c4);
        }
        for (int kt = 0; kt < 16; kt++) {
            {
                uint4 aw = make_uint4(f2h2(va[0],va[1]), f2h2(va[2],va[3]),
                                      f2h2(va[4],va[5]), f2h2(va[6],va[7]));
                *(uint4*)(Asu + mrow*12 + (tid&1)*4) = aw;
                *(uint2*)(Bsu + kk*36 + c4/2) = vb2;
            }
            __syncthreads();
            if (kt < 15) {
                int k0 = kbase + (kt+1)*16;
#pragma unroll
                for (int j = 0; j < 8; j++) {
                    int kg = k0 + kh + j;
                    int ic = kg >> 2, khh = (kg >> 1) & 1, kw = kg & 1;
                    va[j] = fok ? xb[ic*NN + sbase + khh*HH + kw] : 0.f;
                }
                vb2 = *(const uint2*)(g_wth + (k0+kk)*CC + o0 + c4);
            }
            mma_ktile_h(Asu, bsb, wm, wn, lane, acc);
            __syncthreads();
        }
        float* dstp = g_xkvp + part*(BB*NK*CC) + (b*NK)*CC;
#pragma unroll
        for (int nj = 0; nj < 4; nj++) {
            int c = o0 + wn*32 + nj*8 + 2*tg;
#pragma unroll
            for (int mi = 0; mi < 2; mi++) {
                int m1 = m0 + wm*32 + mi*16 + gr;
                if (m1 < NK)   *(float2*)(&dstp[m1*CC + c]) =
                    make_float2(acc[mi][nj][0], acc[mi][nj][1]);
                if (m1+8 < NK) *(float2*)(&dstp[(m1+8)*CC + c]) =
                    make_float2(acc[mi][nj][2], acc[mi][nj][3]);
            }
        }
    }
}

// ---------------- 3: LayerNorm ----------------
__global__ void ln_kernel(const float* __restrict__ gamma, const float* __restrict__ beta,
                          const float* __restrict__ sr_b) {
    int row = blockIdx.x, t = threadIdx.x;
    int idx = row*CC + t;
    const int stride = BB*NK*CC;
    float v = ((g_xkvp[idx] + g_xkvp[idx + stride]) +
               (g_xkvp[idx + 2*stride] + g_xkvp[idx + 3*stride])) + sr_b[t];
    float s = v, q = v*v;
#pragma unroll
    for (int m = 16; m >= 1; m >>= 1) {
        s += __shfl_xor_sync(0xffffffffu, s, m);
        q += __shfl_xor_sync(0xffffffffu, q, m);
    }
    __shared__ float r1[8], r2[8];
    if ((t & 31) == 0) { r1[t>>5] = s; r2[t>>5] = q; }
    __syncthreads();
    float tot = 0.f, tq = 0.f;
#pragma unroll
    for (int wv = 0; wv < 8; wv++) { tot += r1[wv]; tq += r2[wv]; }
    float mean = tot * (1.f/256.f);
    float var  = tq * (1.f/256.f) - mean*mean;
    float inv  = rsqrtf(var + 1e-5f);
    g_xkv[row*CC + t] = (v - mean)*inv*gamma[t] + beta[t];
}

// ---------------- 4: KV projection, K-split x2 ----------------
__global__ __launch_bounds__(256) void gemm_kv_kernel(const float* __restrict__ Wkv) {
    __shared__ unsigned Asu[AS_U32];
    __shared__ unsigned Bsu[BS_U32];
    int tid = threadIdx.x, lane = tid & 31, w = tid >> 5;
    int wm = w >> 1, wn = w & 1;
    int gr = lane >> 2, tg = lane & 3;
    ACC_INIT
    unsigned bsb = cvta_sh(Bsu);
    int b = blockIdx.z, m0 = blockIdx.x*128;
    int part = blockIdx.y >> 3;
    int c0 = (blockIdx.y & 7)*64;
    int mrow = tid >> 1, kh = (tid & 1)*8;
    int kk = tid >> 4, c4 = (tid & 15)*4;
    int arow = m0 + mrow; if (arow > NK-1) arow = NK-1;
    const float* ap = g_xkv + (b*NK + arow)*CC + part*128 + kh;
    const float* wp = Wkv + part*128*512;

    float4 v0, v1, wv;
    v0 = *(const float4*)(ap);
    v1 = *(const float4*)(ap + 4);
    wv = *(const float4*)(wp + kk*512 + c0 + c4);

    for (int kt = 0; kt < 8; kt++) {
        {
            uint4 aw = make_uint4(f2h2(v0.x,v0.y), f2h2(v0.z,v0.w),
                                  f2h2(v1.x,v1.y), f2h2(v1.z,v1.w));
            *(uint4*)(Asu + mrow*12 + (tid&1)*4) = aw;
            *(uint2*)(Bsu + kk*36 + c4/2) = make_uint2(f2h2(wv.x,wv.y), f2h2(wv.z,wv.w));
        }
        __syncthreads();
        if (kt < 7) {
            int k0 = (kt+1)*16;
            v0 = *(const float4*)(ap + k0);
            v1 = *(const float4*)(ap + k0 + 4);
            wv = *(const float4*)(wp + (k0+kk)*512 + c0 + c4);
        }
        mma_ktile_h(Asu, bsb, wm, wn, lane, acc);
        __syncthreads();
    }
    float* dstp = g_kvp + ((part*BB + b)*NK)*512;
#pragma unroll
    for (int nj = 0; nj < 4; nj++) {
        int c = c0 + wn*32 + nj*8 + 2*tg;
#pragma unroll
        for (int mi = 0; mi < 2; mi++) {
            int m1 = m0 + wm*32 + mi*16 + gr;
            if (m1 < NK)   *(float2*)(&dstp[m1*512 + c]) =
                make_float2(acc[mi][nj][0], acc[mi][nj][1]);
            if (m1+8 < NK) *(float2*)(&dstp[(m1+8)*512 + c]) =
                make_float2(acc[mi][nj][2], acc[mi][nj][3]);
        }
    }
}

// ---------------- 4b: combine kv partials ----------------
__global__ void kvcomb_kernel() {
    int m = blockIdx.x, b = blockIdx.y, c = threadIdx.x;
    int idx = (b*NK + m)*512 + c;
    float val = g_kvp[idx] + g_kvp[BB*NK*512 + idx];
    int d = c >> 4, head = (c >> 1) & 7, sel = c & 1;
    float* dst = sel ? g_v : g_k;
    dst[((b*NHD + head)*NK + m)*HD + d] = val;
}

// ---------------- 5: fused flash attention ----------------
// smem: qsh 5120h, k0/v0/k1/v1 2560h each, psh 9216h = 24576 halves (49152B)
// + posw 2000 floats (8000B) => 57152 bytes
__global__ __launch_bounds__(256, 3) void attn_kernel(const float* __restrict__ pos_emb) {
    extern __shared__ __half smh[];
    __half* qsh = smh;
    __half* kb0 = smh + 5120;
    __half* vb0 = smh + 7680;
    __half* kb1 = smh + 10240;
    __half* vb1 = smh + 12800;
    __half* psh = smh + 15360;
    float* posw = (float*)(smh + 24576);
    int b = blockIdx.z, head = blockIdx.y, n0 = blockIdx.x*128;
    int tid = threadIdx.x, lane = tid & 31, w = tid >> 5;
    int gr = lane >> 2, tg = lane & 3;
    const float scale = 0.17677669529663687f;
    const float LOG2E = 1.4426950408889634f;
    int bh = b*NHD + head;
    const float* qg = g_q + bh*NN*HD;
    const float* kg = g_k + bh*NK*HD;
    const float* vg = g_v + bh*NK*HD;

    {   // q fill
        int r = tid >> 1, dcq = (tid & 1)*16;
        int n = n0 + r; if (n > NN-1) n = NN-1;
        const float* p = qg + n*HD + dcq;
        float4 u0 = *(const float4*)(p);
        float4 u1 = *(const float4*)(p+4);
        float4 u2 = *(const float4*)(p+8);
        float4 u3 = *(const float4*)(p+12);
        uint4 w0 = make_uint4(f2h2(u0.x*scale,u0.y*scale), f2h2(u0.z*scale,u0.w*scale),
                              f2h2(u1.x*scale,u1.y*scale), f2h2(u1.z*scale,u1.w*scale));
        uint4 w1 = make_uint4(f2h2(u2.x*scale,u2.y*scale), f2h2(u2.z*scale,u2.w*scale),
                              f2h2(u3.x*scale,u3.y*scale), f2h2(u3.z*scale,u3.w*scale));
        *(uint4*)(qsh + r*40 + dcq)     = w0;
        *(uint4*)(qsh + r*40 + dcq + 8) = w1;
    }

    // stage pos_emb window (rows [rowlo, 69-qi_lo], contiguous)
    int qi_lo = n0 / HH;
    int nmax = n0 + 127; if (nmax > NN-1) nmax = NN-1;
    int qi_hi = nmax / HH;
    int rowlo = 55 - qi_hi;
    int cnt = (15 + qi_hi - qi_lo) * PEW;
    {
        const float* psrc = pos_emb + rowlo*PEW;
        for (int i = tid; i < cnt; i += 256) posw[i] = psrc[i];
    }

    int kr = tid >> 2, dck = (tid & 3)*8;
    auto fillKV = [&](int mbase, __half* kd, __half* vd) {
        bool ok = (mbase + kr) < NK;
        int mr = ok ? (mbase + kr) : 0;
        const float* kp = kg + mr*HD + dck;
        float4 a0 = *(const float4*)kp, a1 = *(const float4*)(kp+4);
        const float* vp = vg + mr*HD + dck;
        float4 w0 = *(const float4*)vp, w1 = *(const float4*)(vp+4);
        uint4 kw = make_uint4(f2h2(a0.x,a0.y), f2h2(a0.z,a0.w),
                              f2h2(a1.x,a1.y), f2h2(a1.z,a1.w));
        uint4 vw = make_uint4(f2h2(w0.x,w0.y), f2h2(w0.z,w0.w),
                              f2h2(w1.x,w1.y), f2h2(w1.z,w1.w));
        if (!ok) { kw = make_uint4(0,0,0,0); vw = kw; }
        *(uint4*)(kd + kr*40 + dck) = kw;
        *(uint4*)(vd + kr*40 + dck) = vw;
    };
    fillKV(0, kb0, vb0);
    __syncthreads();

    unsigned qa[2][4];
    {
        const unsigned* qsu = (const unsigned*)qsh;
        int rw = (w*16 + gr)*20;
#pragma unroll
        for (int ks = 0; ks < 2; ks++) {
            qa[ks][0] = qsu[rw + ks*8 + tg];
            qa[ks][1] = qsu[rw + 160 + ks*8 + tg];
            qa[ks][2] = qsu[rw + ks*8 + tg + 4];
            qa[ks][3] = qsu[rw + 160 + ks*8 + tg + 4];
        }
    }

    int rown0 = n0 + w*16 + gr, rown1 = rown0 + 8;
    int nq0 = rown0 > NN-1 ? NN-1 : rown0;
    int nq1 = rown1 > NN-1 ? NN-1 : rown1;
    int qi0 = nq0/HH, qj0 = nq0 - qi0*HH;
    int qi1 = nq1/HH, qj1 = nq1 - qi1*HH;
    // smem-window bias constants: posw[ki*111+kj + C] = bias for this q row
    int C0 = (qi_hi - qi0)*PEW + 55 - qj0;
    int C1 = (qi_hi - qi1)*PEW + 55 - qj1;

    float m_i[2] = {-1e30f, -1e30f}, l_i[2] = {0.f, 0.f};
    float co[4][4];
#pragma unroll
    for (int i = 0; i < 4; i++) { co[i][0]=0.f; co[i][1]=0.f; co[i][2]=0.f; co[i][3]=0.f; }
    __half* psw = psh + w*1152;

    for (int t = 0; t < 13; t++) {
        int mb = t*64;
        int cur = t & 1;
        __half* ksh = cur ? kb1 : kb0;
        __half* vsh = cur ? vb1 : vb0;
        if (t < 12) fillKV(mb + 64, cur ? kb0 : kb1, cur ? vb0 : vb1);

        // ---- QK^T ----
        float cs[8][4];
#pragma unroll
        for (int i = 0; i < 8; i++) { cs[i][0]=0.f; cs[i][1]=0.f; cs[i][2]=0.f; cs[i][3]=0.f; }
        {
            const unsigned* ksu = (const unsigned*)ksh;
#pragma unroll
            for (int nj = 0; nj < 8; nj++) {
                int bw = (nj*8 + gr)*20;
#pragma unroll
                for (int ks = 0; ks < 2; ks++) {
                    unsigned b0 = ksu[bw + ks*8 + tg];
                    unsigned b1 = ksu[bw + ks*8 + tg + 4];
                    mma16h(cs[nj], qa[ks], b0, b1);
                }
            }
        }

        // ---- bias + mask (smem window, incremental index) ----
        {
            int mk = mb + 2*tg;
            int ki = mk / HH;
            int kj = mk - ki*HH;
            int bix = ki*PEW + kj;
#pragma unroll
            for (int nj = 0; nj < 8; nj++) {
                if (mk < NK) {
                    int dlt = (kj == HH-1) ? (PEW - HH + 1) : 1;   // 56 or 1
                    cs[nj][0] += posw[bix + C0];
                    cs[nj][1] += posw[bix + C0 + dlt];
                    cs[nj][2] += posw[bix + C1];
                    cs[nj][3] += posw[bix + C1 + dlt];
                } else {
                    cs[nj][0] = -1e30f; cs[nj][1] = -1e30f;
                    cs[nj][2] = -1e30f; cs[nj][3] = -1e30f;
                }
                mk += 8; kj += 8; bix += 8;
                if (kj >= HH) { kj -= HH; bix += PEW - HH; }
            }
        }

        // ---- online softmax (fp16x2 ex2) ----
#pragma unroll
        for (int h = 0; h < 2; h++) {
            float tm = -1e30f;
#pragma unroll
            for (int nj = 0; nj < 8; nj++) tm = fmaxf(tm, fmaxf(cs[nj][2*h], cs[nj][2*h+1]));
            tm = fmaxf(tm, __shfl_xor_sync(0xffffffffu, tm, 1));
            tm = fmaxf(tm, __shfl_xor_sync(0xffffffffu, tm, 2));
            float mnew = fmaxf(m_i[h], tm);
            float f = __expf(m_i[h] - mnew);
            m_i[h] = mnew;
            float mL = mnew * LOG2E;
            float sum = 0.f;
            __half* prow = psw + (gr + 8*h)*72 + 2*tg;
#pragma unroll
            for (int nj = 0; nj < 8; nj++) {
                float e0 = fmaf(cs[nj][2*h],   LOG2E, -mL);
                float e1 = fmaf(cs[nj][2*h+1], LOG2E, -mL);
                unsigned eh = f2h2(e0, e1);
                unsigned ph;
                asm("ex2.approx.f16x2 %0, %1;" : "=r"(ph) : "r"(eh));
                *(unsigned*)(prow + nj*8) = ph;
                float2 pf = __half22float2(*(__half2*)&ph);
                sum += pf.x + pf.y;
            }
            sum += __shfl_xor_sync(0xffffffffu, sum, 1);
            sum += __shfl_xor_sync(0xffffffffu, sum, 2);
            l_i[h] = l_i[h]*f + sum;
#pragma unroll
            for (int nj = 0; nj < 4; nj++) { co[nj][2*h] *= f; co[nj][2*h+1] *= f; }
        }
        __syncwarp();

        // ---- O += P @ V ----
        {
            const unsigned* psu = (const unsigned*)psw;
            unsigned vlbase = cvta_sh(vsh) + (lane & 15)*80;
#pragma unroll
            for (int ks8 = 0; ks8 < 4; ks8++) {
                unsigned pa[4];
                pa[0] = psu[gr*36 + ks8*8 + tg];
                pa[1] = psu[(gr+8)*36 + ks8*8 + tg];
                pa[2] = psu[gr*36 + ks8*8 + tg + 4];
                pa[3] = psu[(gr+8)*36 + ks8*8 + tg + 4];
#pragma unroll
                for (int nj = 0; nj < 4; nj++) {
                    unsigned vb0r, vb1r;
                    unsigned addr = vlbase + ks8*1280 + nj*16;
                    asm volatile("ldmatrix.sync.aligned.m8n8.x2.trans.shared.b16 {%0,%1}, [%2];"
                                 : "=r"(vb0r), "=r"(vb1r) : "r"(addr));
                    mma16h(co[nj], pa, vb0r, vb1r);
                }
            }
        }
        __syncthreads();
    }

    float inv0 = 1.f/l_i[0], inv1 = 1.f/l_i[1];
#pragma unroll
    for (int nj = 0; nj < 4; nj++) {
        int d = nj*8 + 2*tg;
        if (rown0 < NN)
            *(float2*)&g_ao[(b*NN + rown0)*CC + head*HD + d] =
                make_float2(co[nj][0]*inv0, co[nj][1]*inv0);
        if (rown1 < NN)
            *(float2*)&g_ao[(b*NN + rown1)*CC + head*HD + d] =
                make_float2(co[nj][2]*inv1, co[nj][3]*inv1);
    }
}

// ---------------- 6: output projection ----------------
__global__ __launch_bounds__(256) void gemm_proj_kernel(const float* __restrict__ pw,
                                                        const float* __restrict__ pb,
                                                        float* __restrict__ out) {
    __shared__ unsigned Asu[AS_U32];
    __shared__ unsigned Bsu[BS_U32];
    int tid = threadIdx.x, lane = tid & 31, w = tid >> 5;
    int wm = w >> 1, wn = w & 1;
    int gr = lane >> 2, tg = lane & 3;
    ACC_INIT
    unsigned bsb = cvta_sh(Bsu);
    int b = blockIdx.z, n0 = blockIdx.x*128, c0 = blockIdx.y*64;
    int mrow = tid >> 1, kh = (tid & 1)*8;
    int kk = tid >> 4, c4 = (tid & 15)*4;
    int arow = n0 + mrow; if (arow > NN-1) arow = NN-1;
    const float* ap = g_ao + (b*NN + arow)*CC + kh;

    float4 v0, v1, wv;
    v0 = *(const float4*)(ap);
    v1 = *(const float4*)(ap + 4);
    wv = *(const float4*)(pw + kk*CC + c0 + c4);

    for (int kt = 0; kt < 16; kt++) {
        {
            uint4 aw = make_uint4(f2h2(v0.x,v0.y), f2h2(v0.z,v0.w),
                                  f2h2(v1.x,v1.y), f2h2(v1.z,v1.w));
            *(uint4*)(Asu + mrow*12 + (tid&1)*4) = aw;
            *(uint2*)(Bsu + kk*36 + c4/2) = make_uint2(f2h2(wv.x,wv.y), f2h2(wv.z,wv.w));
        }
        __syncthreads();
        if (kt < 15) {
            int k0 = (kt+1)*16;
            v0 = *(const float4*)(ap + k0);
            v1 = *(const float4*)(ap + k0 + 4);
            wv = *(const float4*)(pw + (k0+kk)*CC + c0 + c4);
        }
        mma_ktile_h(Asu, bsb, wm, wn, lane, acc);
        __syncthreads();
    }
#pragma unroll
    for (int nj = 0; nj < 4; nj++) {
        int c = c0 + wn*32 + nj*8 + 2*tg;
        float2 pbv = *(const float2*)(pb + c);
        float* o0 = out + (b*CC + c)*NN;
        float* o1 = o0 + NN;
#pragma unroll
        for (int mi = 0; mi < 2; mi++) {
            int n1 = n0 + wm*32 + mi*16 + gr;
            if (n1 < NN)   { o0[n1]   = acc[mi][nj][0] + pbv.x; o1[n1]   = acc[mi][nj][1] + pbv.y; }
            if (n1+8 < NN) { o0[n1+8] = acc[mi][nj][2] + pbv.x; o1[n1+8] = acc[mi][nj][3] + pbv.y; }
        }
    }
}

// ---------------- launch ----------------
extern "C" void kernel_launch(void* const* d_in, const int* in_sizes, int n_in,
                              void* d_out, int out_size) {
    const float* x    = (const float*)d_in[0];
    const float* Wq   = (const float*)d_in[1];
    const float* Wkv  = (const float*)d_in[2];
    const float* sr_w = (const float*)d_in[3];
    const float* sr_b = (const float*)d_in[4];
    const float* ln_g = (const float*)d_in[5];
    const float* ln_b = (const float*)d_in[6];
    const float* pos  = (const float*)d_in[7];
    const float* pw   = (const float*)d_in[8];
    const float* pb   = (const float*)d_in[9];
    float* out = (float*)d_out;

    static int smem_set = 0;
    if (!smem_set) {
        cudaFuncSetAttribute(attn_kernel, cudaFuncAttributeMaxDynamicSharedMemorySize, 57152);
        smem_set = 1;
    }

    wt_kernel        <<<1024, 256>>>(sr_w);
    gemm_qconv_kernel<<<dim3(25, 20, BB), 256>>>(x, Wq);
    ln_kernel        <<<BB*NK, 256>>>(ln_g, ln_b, sr_b);
    gemm_kv_kernel   <<<dim3(7, 16, BB), 256>>>(Wkv);
    kvcomb_kernel    <<<dim3(NK, BB), 512>>>();
    attn_kernel      <<<dim3(25, 8, BB), 256, 57152>>>(pos);
    gemm_proj_kernel <<<dim3(25, 4, BB), 256>>>(pw, pb, out);
}

// round 17
// speedup vs baseline: 3.1260x; 1.0037x over previous
#include <cuda_runtime.h>
#include <cuda_fp16.h>

#define BB 4
#define CC 256
#define HH 56
#define NN 3136
#define NHD 8
#define HD 32
#define NK 784
#define PEW 111

__device__ __forceinline__ void mma16h(float c[4], const unsigned a[4], unsigned b0, unsigned b1) {
    asm("mma.sync.aligned.m16n8k16.row.col.f32.f16.f16.f32 "
        "{%0,%1,%2,%3},{%4,%5,%6,%7},{%8,%9},{%0,%1,%2,%3};"
        : "+f"(c[0]), "+f"(c[1]), "+f"(c[2]), "+f"(c[3])
        : "r"(a[0]), "r"(a[1]), "r"(a[2]), "r"(a[3]), "r"(b0), "r"(b1));
}
__device__ __forceinline__ unsigned f2h2(float a, float b) {
    __half2 h = __floats2half2_rn(a, b);
    return *(unsigned*)&h;
}
__device__ __forceinline__ unsigned cvta_sh(const void* p) {
    return (unsigned)__cvta_generic_to_shared(p);
}

// ---------------- scratch ----------------
__device__ float    g_q   [BB*NHD*NN*HD];
__device__ float    g_k   [BB*NHD*NK*HD];
__device__ float    g_v   [BB*NHD*NK*HD];
__device__ float    g_xkvp[4*BB*NK*CC];
__device__ float    g_xkv [BB*NK*CC];
__device__ float    g_kvp [2*BB*NK*512];
__device__ float    g_ao  [BB*NN*CC];
__device__ __half   g_wth [1024*CC];

// ---------------- prep ----------------
__global__ void wt_kernel(const float* __restrict__ sr_w) {
    g_wth[blockIdx.x*CC + threadIdx.x] = __float2half_rn(sr_w[threadIdx.x*1024 + blockIdx.x]);
}

// ---- fp16 mma core: block 128(M)x64(N), ktile 16, ping-pong smem ----
#define AS_U32  (128*12)
#define BS_U32  (16*36)
__device__ __forceinline__ void mma_ktile_h(const unsigned* Asu, const unsigned bs_base,
                                            int wm, int wn, int lane, float acc[2][4][4]) {
    int gr = lane >> 2, tg = lane & 3;
    unsigned a[2][4];
#pragma unroll
    for (int mi = 0; mi < 2; mi++) {
        int r = wm*32 + mi*16 + gr;
        a[mi][0] = Asu[r*12 + tg];
        a[mi][1] = Asu[(r+8)*12 + tg];
        a[mi][2] = Asu[r*12 + tg + 4];
        a[mi][3] = Asu[(r+8)*12 + tg + 4];
    }
    unsigned bb = bs_base + (lane & 15)*144 + wn*64;
#pragma unroll
    for (int nj = 0; nj < 4; nj++) {
        unsigned b0, b1;
        asm volatile("ldmatrix.sync.aligned.m8n8.x2.trans.shared.b16 {%0,%1}, [%2];"
                     : "=r"(b0), "=r"(b1) : "r"(bb + nj*16));
        mma16h(acc[0][nj], a[0], b0, b1);
        mma16h(acc[1][nj], a[1], b0, b1);
    }
}

#define ACC_INIT                                                         \
    float acc[2][4][4];                                                  \
    _Pragma("unroll") for (int zi = 0; zi < 2; zi++)                     \
    _Pragma("unroll") for (int zj = 0; zj < 4; zj++)                     \
    _Pragma("unroll") for (int zk = 0; zk < 4; zk++) acc[zi][zj][zk] = 0.f;

// ---------------- 1+2 fused: Q projection || SR conv (K-split x4) ----------
__global__ __launch_bounds__(256) void gemm_qconv_kernel(const float* __restrict__ x,
                                                         const float* __restrict__ Wq) {
    __shared__ unsigned Asu[2*AS_U32];
    __shared__ unsigned Bsu[2*BS_U32];
    int tid = threadIdx.x, lane = tid & 31, w = tid >> 5;
    int wm = w >> 1, wn = w & 1;
    int gr = lane >> 2, tg = lane & 3;
    int b = blockIdx.z;
    unsigned bsb = cvta_sh(Bsu);
    int mrow = tid >> 1, kh = (tid & 1)*8;
    int kk = tid >> 4, c4 = (tid & 15)*4;

    if (blockIdx.y < 4) {
        ACC_INIT
        int n0 = blockIdx.x*128, c0 = blockIdx.y*64;
        int n = n0 + mrow; if (n > NN-1) n = NN-1;
        const float* xb = x + b*CC*NN + n;

        float va[8]; float4 wv;
        {
#pragma unroll
            for (int j = 0; j < 8; j++) va[j] = xb[(kh+j)*NN];
            wv = *(const float4*)(Wq + kk*CC + c0 + c4);
        }
        for (int kt = 0; kt < 16; kt++) {
            int cur = kt & 1;
            {
                uint4 aw = make_uint4(f2h2(va[0],va[1]), f2h2(va[2],va[3]),
                                      f2h2(va[4],va[5]), f2h2(va[6],va[7]));
                *(uint4*)(Asu + cur*AS_U32 + mrow*12 + (tid&1)*4) = aw;
                *(uint2*)(Bsu + cur*BS_U32 + kk*36 + c4/2) = make_uint2(f2h2(wv.x,wv.y), f2h2(wv.z,wv.w));
            }
            __syncthreads();
            if (kt < 15) {
                int k0 = (kt+1)*16;
#pragma unroll
                for (int j = 0; j < 8; j++) va[j] = xb[(k0+kh+j)*NN];
                wv = *(const float4*)(Wq + (k0+kk)*CC + c0 + c4);
            }
            mma_ktile_h(Asu + cur*AS_U32, bsb + cur*BS_U32*4, wm, wn, lane, acc);
        }
#pragma unroll
        for (int nj = 0; nj < 4; nj++) {
            int c = c0 + wn*32 + nj*8 + 2*tg;
            int head = c >> 5, d = c & 31;
            float* qb = g_q + (b*NHD + head)*NN*HD + d;
#pragma unroll
            for (int mi = 0; mi < 2; mi++) {
                int n1 = n0 + wm*32 + mi*16 + gr;
                if (n1 < NN)   *(float2*)(qb + n1*HD)     = make_float2(acc[mi][nj][0], acc[mi][nj][1]);
                if (n1+8 < NN) *(float2*)(qb + (n1+8)*HD) = make_float2(acc[mi][nj][2], acc[mi][nj][3]);
            }
        }
    } else {
        if (blockIdx.x >= 7) return;
        ACC_INIT
        int yy = blockIdx.y - 4;
        int part = yy >> 2;
        int o0 = (yy & 3) * 64;
        int m0 = blockIdx.x * 128;
        bool fok = (m0 + mrow) < NK;
        const float* xb = x + b*CC*NN;
        int sbase;
        {
            int m = fok ? (m0 + mrow) : 0;
            int r = m / 28;
            sbase = (2*r)*HH + 2*(m - r*28);
        }
        int kbase = part*256;

        float va[8]; uint2 vb2;
        {
#pragma unroll
            for (int j = 0; j < 8; j++) {
                int kg = kbase + kh + j;
                int ic = kg >> 2, khh = (kg >> 1) & 1, kw = kg & 1;
                va[j] = fok ? xb[ic*NN + sbase + khh*HH + kw] : 0.f;
            }
            vb2 = *(const uint2*)(g_wth + (kbase+kk)*CC + o0 + c4);
        }
        for (int kt = 0; kt < 16; kt++) {
            int cur = kt & 1;
            {
                uint4 aw = make_uint4(f2h2(va[0],va[1]), f2h2(va[2],va[3]),
                                      f2h2(va[4],va[5]), f2h2(va[6],va[7]));
                *(uint4*)(Asu + cur*AS_U32 + mrow*12 + (tid&1)*4) = aw;
                *(uint2*)(Bsu + cur*BS_U32 + kk*36 + c4/2) = vb2;
            }
            __syncthreads();
            if (kt < 15) {
                int k0 = kbase + (kt+1)*16;
#pragma unroll
                for (int j = 0; j < 8; j++) {
                    int kg = k0 + kh + j;
                    int ic = kg >> 2, khh = (kg >> 1) & 1, kw = kg & 1;
                    va[j] = fok ? xb[ic*NN + sbase + khh*HH + kw] : 0.f;
                }
                vb2 = *(const uint2*)(g_wth + (k0+kk)*CC + o0 + c4);
            }
            mma_ktile_h(Asu + cur*AS_U32, bsb + cur*BS_U32*4, wm, wn, lane, acc);
        }
        float* dstp = g_xkvp + part*(BB*NK*CC) + (b*NK)*CC;
#pragma unroll
        for (int nj = 0; nj < 4; nj++) {
            int c = o0 + wn*32 + nj*8 + 2*tg;
#pragma unroll
            for (int mi = 0; mi < 2; mi++) {
                int m1 = m0 + wm*32 + mi*16 + gr;
                if (m1 < NK)   *(float2*)(&dstp[m1*CC + c]) =
                    make_float2(acc[mi][nj][0], acc[mi][nj][1]);
                if (m1+8 < NK) *(float2*)(&dstp[(m1+8)*CC + c]) =
                    make_float2(acc[mi][nj][2], acc[mi][nj][3]);
            }
        }
    }
}

// ---------------- 3: LayerNorm ----------------
__global__ void ln_kernel(const float* __restrict__ gamma, const float* __restrict__ beta,
                          const float* __restrict__ sr_b) {
    int row = blockIdx.x, t = threadIdx.x;
    int idx = row*CC + t;
    const int stride = BB*NK*CC;
    float v = ((g_xkvp[idx] + g_xkvp[idx + stride]) +
               (g_xkvp[idx + 2*stride] + g_xkvp[idx + 3*stride])) + sr_b[t];
    float s = v, q = v*v;
#pragma unroll
    for (int m = 16; m >= 1; m >>= 1) {
        s += __shfl_xor_sync(0xffffffffu, s, m);
        q += __shfl_xor_sync(0xffffffffu, q, m);
    }
    __shared__ float r1[8], r2[8];
    if ((t & 31) == 0) { r1[t>>5] = s; r2[t>>5] = q; }
    __syncthreads();
    float tot = 0.f, tq = 0.f;
#pragma unroll
    for (int wv = 0; wv < 8; wv++) { tot += r1[wv]; tq += r2[wv]; }
    float mean = tot * (1.f/256.f);
    float var  = tq * (1.f/256.f) - mean*mean;
    float inv  = rsqrtf(var + 1e-5f);
    g_xkv[row*CC + t] = (v - mean)*inv*gamma[t] + beta[t];
}

// ---------------- 4: KV projection, K-split x2, ping-pong ----------------
__global__ __launch_bounds__(256) void gemm_kv_kernel(const float* __restrict__ Wkv) {
    __shared__ unsigned Asu[2*AS_U32];
    __shared__ unsigned Bsu[2*BS_U32];
    int tid = threadIdx.x, lane = tid & 31, w = tid >> 5;
    int wm = w >> 1, wn = w & 1;
    int gr = lane >> 2, tg = lane & 3;
    ACC_INIT
    unsigned bsb = cvta_sh(Bsu);
    int b = blockIdx.z, m0 = blockIdx.x*128;
    int part = blockIdx.y >> 3;
    int c0 = (blockIdx.y & 7)*64;
    int mrow = tid >> 1, kh = (tid & 1)*8;
    int kk = tid >> 4, c4 = (tid & 15)*4;
    int arow = m0 + mrow; if (arow > NK-1) arow = NK-1;
    const float* ap = g_xkv + (b*NK + arow)*CC + part*128 + kh;
    const float* wp = Wkv + part*128*512;

    float4 v0, v1, wv;
    v0 = *(const float4*)(ap);
    v1 = *(const float4*)(ap + 4);
    wv = *(const float4*)(wp + kk*512 + c0 + c4);

    for (int kt = 0; kt < 8; kt++) {
        int cur = kt & 1;
        {
            uint4 aw = make_uint4(f2h2(v0.x,v0.y), f2h2(v0.z,v0.w),
                                  f2h2(v1.x,v1.y), f2h2(v1.z,v1.w));
            *(uint4*)(Asu + cur*AS_U32 + mrow*12 + (tid&1)*4) = aw;
            *(uint2*)(Bsu + cur*BS_U32 + kk*36 + c4/2) = make_uint2(f2h2(wv.x,wv.y), f2h2(wv.z,wv.w));
        }
        __syncthreads();
        if (kt < 7) {
            int k0 = (kt+1)*16;
            v0 = *(const float4*)(ap + k0);
            v1 = *(const float4*)(ap + k0 + 4);
            wv = *(const float4*)(wp + (k0+kk)*512 + c0 + c4);
        }
        mma_ktile_h(Asu + cur*AS_U32, bsb + cur*BS_U32*4, wm, wn, lane, acc);
    }
    float* dstp = g_kvp + ((part*BB + b)*NK)*512;
#pragma unroll
    for (int nj = 0; nj < 4; nj++) {
        int c = c0 + wn*32 + nj*8 + 2*tg;
#pragma unroll
        for (int mi = 0; mi < 2; mi++) {
            int m1 = m0 + wm*32 + mi*16 + gr;
            if (m1 < NK)   *(float2*)(&dstp[m1*512 + c]) =
                make_float2(acc[mi][nj][0], acc[mi][nj][1]);
            if (m1+8 < NK) *(float2*)(&dstp[(m1+8)*512 + c]) =
                make_float2(acc[mi][nj][2], acc[mi][nj][3]);
        }
    }
}

// ---------------- 4b: combine kv partials ----------------
__global__ void kvcomb_kernel() {
    int m = blockIdx.x, b = blockIdx.y, c = threadIdx.x;
    int idx = (b*NK + m)*512 + c;
    float val = g_kvp[idx] + g_kvp[BB*NK*512 + idx];
    int d = c >> 4, head = (c >> 1) & 7, sel = c & 1;
    float* dst = sel ? g_v : g_k;
    dst[((b*NHD + head)*NK + m)*HD + d] = val;
}

// ---------------- 5: fused flash attention (R16 body, untouched) ----------
__global__ __launch_bounds__(256, 3) void attn_kernel(const float* __restrict__ pos_emb) {
    extern __shared__ __half smh[];
    __half* qsh = smh;
    __half* kb0 = smh + 5120;
    __half* vb0 = smh + 7680;
    __half* kb1 = smh + 10240;
    __half* vb1 = smh + 12800;
    __half* psh = smh + 15360;
    float* posw = (float*)(smh + 24576);
    int b = blockIdx.z, head = blockIdx.y, n0 = blockIdx.x*128;
    int tid = threadIdx.x, lane = tid & 31, w = tid >> 5;
    int gr = lane >> 2, tg = lane & 3;
    const float scale = 0.17677669529663687f;
    const float LOG2E = 1.4426950408889634f;
    int bh = b*NHD + head;
    const float* qg = g_q + bh*NN*HD;
    const float* kg = g_k + bh*NK*HD;
    const float* vg = g_v + bh*NK*HD;

    {
        int r = tid >> 1, dcq = (tid & 1)*16;
        int n = n0 + r; if (n > NN-1) n = NN-1;
        const float* p = qg + n*HD + dcq;
        float4 u0 = *(const float4*)(p);
        float4 u1 = *(const float4*)(p+4);
        float4 u2 = *(const float4*)(p+8);
        float4 u3 = *(const float4*)(p+12);
        uint4 w0 = make_uint4(f2h2(u0.x*scale,u0.y*scale), f2h2(u0.z*scale,u0.w*scale),
                              f2h2(u1.x*scale,u1.y*scale), f2h2(u1.z*scale,u1.w*scale));
        uint4 w1 = make_uint4(f2h2(u2.x*scale,u2.y*scale), f2h2(u2.z*scale,u2.w*scale),
                              f2h2(u3.x*scale,u3.y*scale), f2h2(u3.z*scale,u3.w*scale));
        *(uint4*)(qsh + r*40 + dcq)     = w0;
        *(uint4*)(qsh + r*40 + dcq + 8) = w1;
    }

    int qi_lo = n0 / HH;
    int nmax = n0 + 127; if (nmax > NN-1) nmax = NN-1;
    int qi_hi = nmax / HH;
    int rowlo = 55 - qi_hi;
    int cnt = (15 + qi_hi - qi_lo) * PEW;
    {
        const float* psrc = pos_emb + rowlo*PEW;
        for (int i = tid; i < cnt; i += 256) posw[i] = psrc[i];
    }

    int kr = tid >> 2, dck = (tid & 3)*8;
    auto fillKV = [&](int mbase, __half* kd, __half* vd) {
        bool ok = (mbase + kr) < NK;
        int mr = ok ? (mbase + kr) : 0;
        const float* kp = kg + mr*HD + dck;
        float4 a0 = *(const float4*)kp, a1 = *(const float4*)(kp+4);
        const float* vp = vg + mr*HD + dck;
        float4 w0 = *(const float4*)vp, w1 = *(const float4*)(vp+4);
        uint4 kw = make_uint4(f2h2(a0.x,a0.y), f2h2(a0.z,a0.w),
                              f2h2(a1.x,a1.y), f2h2(a1.z,a1.w));
        uint4 vw = make_uint4(f2h2(w0.x,w0.y), f2h2(w0.z,w0.w),
                              f2h2(w1.x,w1.y), f2h2(w1.z,w1.w));
        if (!ok) { kw = make_uint4(0,0,0,0); vw = kw; }
        *(uint4*)(kd + kr*40 + dck) = kw;
        *(uint4*)(vd + kr*40 + dck) = vw;
    };
    fillKV(0, kb0, vb0);
    __syncthreads();

    unsigned qa[2][4];
    {
        const unsigned* qsu = (const unsigned*)qsh;
        int rw = (w*16 + gr)*20;
#pragma unroll
        for (int ks = 0; ks < 2; ks++) {
            qa[ks][0] = qsu[rw + ks*8 + tg];
            qa[ks][1] = qsu[rw + 160 + ks*8 + tg];
            qa[ks][2] = qsu[rw + ks*8 + tg + 4];
            qa[ks][3] = qsu[rw + 160 + ks*8 + tg + 4];
        }
    }

    int rown0 = n0 + w*16 + gr, rown1 = rown0 + 8;
    int nq0 = rown0 > NN-1 ? NN-1 : rown0;
    int nq1 = rown1 > NN-1 ? NN-1 : rown1;
    int qi0 = nq0/HH, qj0 = nq0 - qi0*HH;
    int qi1 = nq1/HH, qj1 = nq1 - qi1*HH;
    int C0 = (qi_hi - qi0)*PEW + 55 - qj0;
    int C1 = (qi_hi - qi1)*PEW + 55 - qj1;

    float m_i[2] = {-1e30f, -1e30f}, l_i[2] = {0.f, 0.f};
    float co[4][4];
#pragma unroll
    for (int i = 0; i < 4; i++) { co[i][0]=0.f; co[i][1]=0.f; co[i][2]=0.f; co[i][3]=0.f; }
    __half* psw = psh + w*1152;

    for (int t = 0; t < 13; t++) {
        int mb = t*64;
        int cur = t & 1;
        __half* ksh = cur ? kb1 : kb0;
        __half* vsh = cur ? vb1 : vb0;
        if (t < 12) fillKV(mb + 64, cur ? kb0 : kb1, cur ? vb0 : vb1);

        float cs[8][4];
#pragma unroll
        for (int i = 0; i < 8; i++) { cs[i][0]=0.f; cs[i][1]=0.f; cs[i][2]=0.f; cs[i][3]=0.f; }
        {
            const unsigned* ksu = (const unsigned*)ksh;
#pragma unroll
            for (int nj = 0; nj < 8; nj++) {
                int bw = (nj*8 + gr)*20;
#pragma unroll
                for (int ks = 0; ks < 2; ks++) {
                    unsigned b0 = ksu[bw + ks*8 + tg];
                    unsigned b1 = ksu[bw + ks*8 + tg + 4];
                    mma16h(cs[nj], qa[ks], b0, b1);
                }
            }
        }

        {
            int mk = mb + 2*tg;
            int ki = mk / HH;
            int kj = mk - ki*HH;
            int bix = ki*PEW + kj;
#pragma unroll
            for (int nj = 0; nj < 8; nj++) {
                if (mk < NK) {
                    int dlt = (kj == HH-1) ? (PEW - HH + 1) : 1;
                    cs[nj][0] += posw[bix + C0];
                    cs[nj][1] += posw[bix + C0 + dlt];
                    cs[nj][2] += posw[bix + C1];
                    cs[nj][3] += posw[bix + C1 + dlt];
                } else {
                    cs[nj][0] = -1e30f; cs[nj][1] = -1e30f;
                    cs[nj][2] = -1e30f; cs[nj][3] = -1e30f;
                }
                mk += 8; kj += 8; bix += 8;
                if (kj >= HH) { kj -= HH; bix += PEW - HH; }
            }
        }

#pragma unroll
        for (int h = 0; h < 2; h++) {
            float tm = -1e30f;
#pragma unroll
            for (int nj = 0; nj < 8; nj++) tm = fmaxf(tm, fmaxf(cs[nj][2*h], cs[nj][2*h+1]));
            tm = fmaxf(tm, __shfl_xor_sync(0xffffffffu, tm, 1));
            tm = fmaxf(tm, __shfl_xor_sync(0xffffffffu, tm, 2));
            float mnew = fmaxf(m_i[h], tm);
            float f = __expf(m_i[h] - mnew);
            m_i[h] = mnew;
            float mL = mnew * LOG2E;
            float sum = 0.f;
            __half* prow = psw + (gr + 8*h)*72 + 2*tg;
#pragma unroll
            for (int nj = 0; nj < 8; nj++) {
                float e0 = fmaf(cs[nj][2*h],   LOG2E, -mL);
                float e1 = fmaf(cs[nj][2*h+1], LOG2E, -mL);
                unsigned eh = f2h2(e0, e1);
                unsigned ph;
                asm("ex2.approx.f16x2 %0, %1;" : "=r"(ph) : "r"(eh));
                *(unsigned*)(prow + nj*8) = ph;
                float2 pf = __half22float2(*(__half2*)&ph);
                sum += pf.x + pf.y;
            }
            sum += __shfl_xor_sync(0xffffffffu, sum, 1);
            sum += __shfl_xor_sync(0xffffffffu, sum, 2);
            l_i[h] = l_i[h]*f + sum;
#pragma unroll
            for (int nj = 0; nj < 4; nj++) { co[nj][2*h] *= f; co[nj][2*h+1] *= f; }
        }
        __syncwarp();

        {
            const unsigned* psu = (const unsigned*)psw;
            unsigned vlbase = cvta_sh(vsh) + (lane & 15)*80;
#pragma unroll
            for (int ks8 = 0; ks8 < 4; ks8++) {
                unsigned pa[4];
                pa[0] = psu[gr*36 + ks8*8 + tg];
                pa[1] = psu[(gr+8)*36 + ks8*8 + tg];
                pa[2] = psu[gr*36 + ks8*8 + tg + 4];
                pa[3] = psu[(gr+8)*36 + ks8*8 + tg + 4];
#pragma unroll
                for (int nj = 0; nj < 4; nj++) {
                    unsigned vb0r, vb1r;
                    unsigned addr = vlbase + ks8*1280 + nj*16;
                    asm volatile("ldmatrix.sync.aligned.m8n8.x2.trans.shared.b16 {%0,%1}, [%2];"
                                 : "=r"(vb0r), "=r"(vb1r) : "r"(addr));
                    mma16h(co[nj], pa, vb0r, vb1r);
                }
            }
        }
        __syncthreads();
    }

    float inv0 = 1.f/l_i[0], inv1 = 1.f/l_i[1];
#pragma unroll
    for (int nj = 0; nj < 4; nj++) {
        int d = nj*8 + 2*tg;
        if (rown0 < NN)
            *(float2*)&g_ao[(b*NN + rown0)*CC + head*HD + d] =
                make_float2(co[nj][0]*inv0, co[nj][1]*inv0);
        if (rown1 < NN)
            *(float2*)&g_ao[(b*NN + rown1)*CC + head*HD + d] =
                make_float2(co[nj][2]*inv1, co[nj][3]*inv1);
    }
}

// ---------------- 6: output projection (ping-pong) ----------------
__global__ __launch_bounds__(256) void gemm_proj_kernel(const float* __restrict__ pw,
                                                        const float* __restrict__ pb,
                                                        float* __restrict__ out) {
    __shared__ unsigned Asu[2*AS_U32];
    __shared__ unsigned Bsu[2*BS_U32];
    int tid = threadIdx.x, lane = tid & 31, w = tid >> 5;
    int wm = w >> 1, wn = w & 1;
    int gr = lane >> 2, tg = lane & 3;
    ACC_INIT
    unsigned bsb = cvta_sh(Bsu);
    int b = blockIdx.z, n0 = blockIdx.x*128, c0 = blockIdx.y*64;
    int mrow = tid >> 1, kh = (tid & 1)*8;
    int kk = tid >> 4, c4 = (tid & 15)*4;
    int arow = n0 + mrow; if (arow > NN-1) arow = NN-1;
    const float* ap = g_ao + (b*NN + arow)*CC + kh;

    float4 v0, v1, wv;
    v0 = *(const float4*)(ap);
    v1 = *(const float4*)(ap + 4);
    wv = *(const float4*)(pw + kk*CC + c0 + c4);

    for (int kt = 0; kt < 16; kt++) {
        int cur = kt & 1;
        {
            uint4 aw = make_uint4(f2h2(v0.x,v0.y), f2h2(v0.z,v0.w),
                                  f2h2(v1.x,v1.y), f2h2(v1.z,v1.w));
            *(uint4*)(Asu + cur*AS_U32 + mrow*12 + (tid&1)*4) = aw;
            *(uint2*)(Bsu + cur*BS_U32 + kk*36 + c4/2) = make_uint2(f2h2(wv.x,wv.y), f2h2(wv.z,wv.w));
        }
        __syncthreads();
        if (kt < 15) {
            int k0 = (kt+1)*16;
            v0 = *(const float4*)(ap + k0);
            v1 = *(const float4*)(ap + k0 + 4);
            wv = *(const float4*)(pw + (k0+kk)*CC + c0 + c4);
        }
        mma_ktile_h(Asu + cur*AS_U32, bsb + cur*BS_U32*4, wm, wn, lane, acc);
    }
#pragma unroll
    for (int nj = 0; nj < 4; nj++) {
        int c = c0 + wn*32 + nj*8 + 2*tg;
        float2 pbv = *(const float2*)(pb + c);
        float* o0 = out + (b*CC + c)*NN;
        float* o1 = o0 + NN;
#pragma unroll
        for (int mi = 0; mi < 2; mi++) {
            int n1 = n0 + wm*32 + mi*16 + gr;
            if (n1 < NN)   { o0[n1]   = acc[mi][nj][0] + pbv.x; o1[n1]   = acc[mi][nj][1] + pbv.y; }
            if (n1+8 < NN) { o0[n1+8] = acc[mi][nj][2] + pbv.x; o1[n1+8] = acc[mi][nj][3] + pbv.y; }
        }
    }
}

// ---------------- launch ----------------
extern "C" void kernel_launch(void* const* d_in, const int* in_sizes, int n_in,
                              void* d_out, int out_size) {
    const float* x    = (const float*)d_in[0];
    const float* Wq   = (const float*)d_in[1];
    const float* Wkv  = (const float*)d_in[2];
    const float* sr_w = (const float*)d_in[3];
    const float* sr_b = (const float*)d_in[4];
    const float* ln_g = (const float*)d_in[5];
    const float* ln_b = (const float*)d_in[6];
    const float* pos  = (const float*)d_in[7];
    const float* pw   = (const float*)d_in[8];
    const float* pb   = (const float*)d_in[9];
    float* out = (float*)d_out;

    static int smem_set = 0;
    if (!smem_set) {
        cudaFuncSetAttribute(attn_kernel, cudaFuncAttributeMaxDynamicSharedMemorySize, 57152);
        smem_set = 1;
    }

    wt_kernel        <<<1024, 256>>>(sr_w);
    gemm_qconv_kernel<<<dim3(25, 20, BB), 256>>>(x, Wq);
    ln_kernel        <<<BB*NK, 256>>>(ln_g, ln_b, sr_b);
    gemm_kv_kernel   <<<dim3(7, 16, BB), 256>>>(Wkv);
    kvcomb_kernel    <<<dim3(NK, BB), 512>>>();
    attn_kernel      <<<dim3(25, 8, BB), 256, 57152>>>(pos);
    gemm_proj_kernel <<<dim3(25, 4, BB), 256>>>(pw, pb, out);
}